// round 10
// baseline (speedup 1.0000x reference)
#include <cuda_runtime.h>

// ---------------------------------------------------------------------------
// Allegro GNN layer: streaming FFMA2 GEMMs, duplicated-X operand layout.
// GEMM inputs stored DUPLICATED in global ((v,v) pairs) so the packed FFMA2
// broadcast operand is a direct LDS — no pack MOVs; weights via LDS.128.
//   k123  : X0 -> 40->64->128->128*fcut -> g_lat(dup)
//   OpG4  : lat @ Wenv0 -> wedge + env scatter        (dup-X)
//   kp1   : products -> scal0(dup) + P
//   OpG5  : scal0 @ Ws0 -> smix                        (dup-X)
//   OpG6  : P @ Wv0 -> vmx                             (old path)
//   OpG7/8: lat-update MLP + residual                  (dup-X)
//   OpG9  : lat @ Wenv1 -> env1 scatter                (dup-X)
//   kp2   : q0/q1 (dup)
//   OpG10/11: final MLP + residual -> node scatter     (dup-X)
// ---------------------------------------------------------------------------

#define NN 10000
#define NE 320000
#define NE3 960000
typedef unsigned long long ULL;

__device__ float g_X0  [NE * 40];
__device__ float g_H   [(long)NE * 256];   // dup
__device__ float g_lat [(long)NE * 256];   // dup
__device__ float g_wedge[NE * 64];
__device__ float g_scal0[(long)NE * 128];  // dup
__device__ float g_P   [(long)NE3 * 96];
__device__ float g_smix[NE * 32];
__device__ float g_vmx [NE3 * 32];
__device__ float g_q   [(long)NE * 128];   // dup
__device__ float g_Y   [NE * 4];
__device__ float g_fcut[NE];
__device__ float g_env [NN * 128];
__device__ float g_env1[NN * 128];

#define F_RS40      0.15811388300841897f
#define F_RS64      0.125f
#define F_RS96      0.10206207261596575f
#define F_RS128     0.08838834764831845f
#define F_RS192     0.07216878364870323f
#define F_ISN       0.17677669529663689f
#define F_SQRT3     1.7320508075688772f
#define F_INV_SQRT3 0.5773502691896258f
#define F_INV_SQRT2 0.7071067811865476f
#define F_C_OLD     0.8944271909999159f
#define F_C_NEW     0.4472135954999579f
#define F_BESSEL    0.6324555320336759f
#define F_PI        3.14159265358979323846f
#define F_INV_RMAX  0.2f

__device__ __forceinline__ ULL fma2(ULL a, ULL b, ULL c) {
    ULL d;
    asm("fma.rn.f32x2 %0, %1, %2, %3;" : "=l"(d) : "l"(a), "l"(b), "l"(c));
    return d;
}
__device__ __forceinline__ ULL pack2(float x) {
    ULL d; unsigned u = __float_as_uint(x);
    asm("mov.b64 %0, {%1,%1};" : "=l"(d) : "r"(u));
    return d;
}
__device__ __forceinline__ void red4(float* p, float a, float b, float c, float d) {
    asm volatile("red.global.add.v4.f32 [%0], {%1,%2,%3,%4};"
                 :: "l"(p), "f"(a), "f"(b), "f"(c), "f"(d) : "memory");
}
__device__ __forceinline__ float silu_f(float v) {
    return v * __frcp_rn(1.0f + __expf(-v));
}
__device__ __forceinline__ void cpa16(const void* s, const void* g) {
    unsigned sa = (unsigned)__cvta_generic_to_shared(s);
    asm volatile("cp.async.cg.shared.global [%0], [%1], 16;" :: "r"(sa), "l"(g));
}
__device__ __forceinline__ void cp_commit() { asm volatile("cp.async.commit_group;"); }
__device__ __forceinline__ void cp_wait1()  { asm volatile("cp.async.wait_group 1;"); }
__device__ __forceinline__ void cp_wait0()  { asm volatile("cp.async.wait_group 0;"); }

// ---------------------------------------------------------------------------
// Generic streaming GEMM.  BM=128 edge rows/tile, 512 threads.
// DUPX: X rows stored duplicated (2*KTOT floats); packed pairs direct-loaded.
// ---------------------------------------------------------------------------
template <int KTOT, int KC, int OUT, int OPO, bool DUPX, class Op>
__global__ void __launch_bounds__(512, 1) gk(Op op, const float* __restrict__ Wg,
                                             int ntiles)
{
    constexpr int KCrow = DUPX ? 2 * KC : KC;
    constexpr int PC  = KCrow + 4;           // ≡4 mod 8 -> conflict-free
    constexpr int NCH = KTOT / KC;
    constexpr int OG  = OUT / OPO;
    constexpr int OGW = OG / 4;
    constexpr int EGN = 512 / OG;
    constexpr int EPT = 128 / EGN;
    constexpr int NP  = OPO / 2;

    extern __shared__ __align__(16) float sh[];
    float* sW = sh;
    float* sX = sh + KTOT * OUT;

    int tid = threadIdx.x;
    for (int i = tid; i < KTOT * OUT / 4; i += 512)
        ((float4*)sW)[i] = ((const float4*)Wg)[i];

    int lane = tid & 31, w = tid >> 5;
    int og = (w & (OGW - 1)) * 4 + (lane & 3);
    int eg = (w / OGW) * 8 + (lane >> 2);

    auto stage = [&](long t, int c, int b) {
        float* dst = sX + b * (128 * PC);
        constexpr int UN = 128 * (KCrow / 4);
        for (int i = tid; i < UN; i += 512) {
            int e_l = i / (KCrow / 4);
            int ks  = (i % (KCrow / 4)) * 4;
            cpa16(dst + e_l * PC + ks, op.src(t * 128 + e_l, c * KCrow + ks));
        }
        cp_commit();
    };

    long t0 = blockIdx.x;
    if (t0 < ntiles) stage(t0, 0, 0);
    int b = 0;

    for (long t = t0; t < ntiles; t += gridDim.x) {
        ULL acc[EPT][NP];
#pragma unroll
        for (int j = 0; j < EPT; j++)
#pragma unroll
            for (int p = 0; p < NP; p++) acc[j][p] = 0ULL;

        for (int c = 0; c < NCH; c++) {
            long nt = t; int nc = c + 1;
            if (nc == NCH) { nt = t + gridDim.x; nc = 0; }
            bool hn = nt < ntiles;
            __syncthreads();
            if (hn) stage(nt, nc, b ^ 1);
            if (hn) cp_wait1(); else cp_wait0();
            __syncthreads();

            const float* Xb = sX + b * (128 * PC);
            const float* xr[EPT];
#pragma unroll
            for (int j = 0; j < EPT; j++) xr[j] = Xb + (eg + EGN * j) * PC;

            if constexpr (DUPX) {
#pragma unroll 2
                for (int k4 = 0; k4 < KC; k4 += 4) {
#pragma unroll
                    for (int half = 0; half < 2; half++) {
                        ulonglong2 xa[EPT];
#pragma unroll
                        for (int j = 0; j < EPT; j++)
                            xa[j] = *(const ulonglong2*)(xr[j] + 2 * k4 + 4 * half);
#pragma unroll
                        for (int kk = 0; kk < 2; kk++) {
                            int k = c * KC + k4 + 2 * half + kk;
                            const float* wr = sW + k * OUT + og * OPO;
                            ULL wv[NP];
                            if constexpr (NP == 4) {
                                ulonglong2 wa = *(const ulonglong2*)wr;
                                ulonglong2 wb = *(const ulonglong2*)(wr + 4);
                                wv[0] = wa.x; wv[1] = wa.y; wv[2] = wb.x; wv[3] = wb.y;
                            } else {
                                ulonglong2 wa = *(const ulonglong2*)wr;
                                wv[0] = wa.x; wv[1] = wa.y;
                            }
#pragma unroll
                            for (int j = 0; j < EPT; j++) {
                                ULL xd = kk ? xa[j].y : xa[j].x;
#pragma unroll
                                for (int p = 0; p < NP; p++)
                                    acc[j][p] = fma2(xd, wv[p], acc[j][p]);
                            }
                        }
                    }
                }
            } else {
#pragma unroll 2
                for (int k4 = 0; k4 < KC; k4 += 4) {
                    float4 xv[EPT];
#pragma unroll
                    for (int j = 0; j < EPT; j++)
                        xv[j] = *(const float4*)(xr[j] + k4);
#pragma unroll
                    for (int kk = 0; kk < 4; kk++) {
                        const float* wr = sW + (c * KC + k4 + kk) * OUT + og * OPO;
                        ULL wv[NP];
                        if constexpr (NP == 4) {
                            ulonglong2 wa = *(const ulonglong2*)wr;
                            ulonglong2 wb = *(const ulonglong2*)(wr + 4);
                            wv[0] = wa.x; wv[1] = wa.y; wv[2] = wb.x; wv[3] = wb.y;
                        } else {
                            ulonglong2 wa = *(const ulonglong2*)wr;
                            wv[0] = wa.x; wv[1] = wa.y;
                        }
#pragma unroll
                        for (int j = 0; j < EPT; j++) {
                            float xs = (kk == 0) ? xv[j].x : (kk == 1) ? xv[j].y
                                     : (kk == 2) ? xv[j].z : xv[j].w;
                            ULL xd = pack2(xs);
#pragma unroll
                            for (int p = 0; p < NP; p++)
                                acc[j][p] = fma2(xd, wv[p], acc[j][p]);
                        }
                    }
                }
            }
            b ^= 1;
        }

#pragma unroll
        for (int j = 0; j < EPT; j++) {
            long e = t * 128 + eg + EGN * j;
            float r[OPO];
#pragma unroll
            for (int p = 0; p < NP; p++) {
                union { ULL u; float2 f; } cv; cv.u = acc[j][p];
                r[2 * p] = cv.f.x; r[2 * p + 1] = cv.f.y;
            }
            op.epi(e, og, r);
        }
    }
}

// ---------------------------------------------------------------------------
// Dup-store helper: write 8 values duplicated at base (dup row, 16 floats)
__device__ __forceinline__ void store8dup(float* base, const float* r, float s) {
    *(float4*)(base + 0)  = make_float4(r[0] * s, r[0] * s, r[1] * s, r[1] * s);
    *(float4*)(base + 4)  = make_float4(r[2] * s, r[2] * s, r[3] * s, r[3] * s);
    *(float4*)(base + 8)  = make_float4(r[4] * s, r[4] * s, r[5] * s, r[5] * s);
    *(float4*)(base + 12) = make_float4(r[6] * s, r[6] * s, r[7] * s, r[7] * s);
}

// ---------------------------------------------------------------------------
// Epilogue / source policies (f = float offset within possibly-dup row)
// ---------------------------------------------------------------------------
struct OpG4 {   // lat(dup) -> w_all(128): outs 0-63 wedge, 64-127 env scatter
    const int* ctr;
    __device__ const float* src(long e, int f) const { return g_lat + e * 256 + f; }
    __device__ void epi(long e, int og, const float* r) const {
        if (og < 8) {
            *(float4*)(g_wedge + e * 64 + og * 8) =
                make_float4(r[0] * F_RS128, r[1] * F_RS128, r[2] * F_RS128, r[3] * F_RS128);
            *(float4*)(g_wedge + e * 64 + og * 8 + 4) =
                make_float4(r[4] * F_RS128, r[5] * F_RS128, r[6] * F_RS128, r[7] * F_RS128);
        } else {
            long c = ctr[e];
            float4 Y = *(const float4*)(g_Y + e * 4);
#pragma unroll
            for (int p = 0; p < 4; p++) {
                int m = (og - 8) * 4 + p;
                float w0 = r[2 * p] * F_RS128, w1 = r[2 * p + 1] * F_RS128;
                red4(g_env + c * 128 + 4 * m, w0, w1 * Y.y, w1 * Y.z, w1 * Y.w);
            }
        }
    }
};
struct OpG5 {   // scal0(dup,128) -> smix(32)
    __device__ const float* src(long e, int f) const { return g_scal0 + e * 128 + f; }
    __device__ void epi(long e, int og, const float* r) const {
        *(float4*)(g_smix + e * 32 + og * 4) =
            make_float4(r[0] * F_RS64, r[1] * F_RS64, r[2] * F_RS64, r[3] * F_RS64);
    }
};
struct OpG6 {   // P(3E,96) -> vmx(3E,32)   (non-dup path)
    __device__ const float* src(long e, int f) const { return g_P + e * 96 + f; }
    __device__ void epi(long e, int og, const float* r) const {
        *(float4*)(g_vmx + e * 32 + og * 4) =
            make_float4(r[0] * F_RS96, r[1] * F_RS96, r[2] * F_RS96, r[3] * F_RS96);
    }
};
struct OpG7 {   // [lat|scal0] dup (384 row) -> silu -> H(dup)
    __device__ const float* src(long e, int f) const {
        return (f < 256) ? (g_lat + e * 256 + f) : (g_scal0 + e * 128 + (f - 256));
    }
    __device__ void epi(long e, int og, const float* r) const {
        float v[8];
#pragma unroll
        for (int i = 0; i < 8; i++) v[i] = silu_f(r[i] * F_RS192);
        store8dup(g_H + e * 256 + og * 16, v, 1.0f);
    }
};
struct OpG8 {   // H(dup) -> *fcut, residual -> lat(dup)
    __device__ const float* src(long e, int f) const { return g_H + e * 256 + f; }
    __device__ void epi(long e, int og, const float* r) const {
        float s = F_C_NEW * F_RS128 * g_fcut[e];
        float* L = g_lat + e * 256 + og * 16;
        float4 a0 = *(float4*)(L + 0),  a1 = *(float4*)(L + 4);
        float4 a2 = *(float4*)(L + 8),  a3 = *(float4*)(L + 12);
        float n[8] = {
            F_C_OLD * a0.x + s * r[0], F_C_OLD * a0.z + s * r[1],
            F_C_OLD * a1.x + s * r[2], F_C_OLD * a1.z + s * r[3],
            F_C_OLD * a2.x + s * r[4], F_C_OLD * a2.z + s * r[5],
            F_C_OLD * a3.x + s * r[6], F_C_OLD * a3.z + s * r[7]};
        store8dup(L, n, 1.0f);
    }
};
struct OpG9 {   // lat(dup) -> w_env1(64) -> env1 scatter
    const int* ctr;
    __device__ const float* src(long e, int f) const { return g_lat + e * 256 + f; }
    __device__ void epi(long e, int og, const float* r) const {
        long c = ctr[e];
        float4 Y = *(const float4*)(g_Y + e * 4);
        int m0 = og * 2;
        float w0 = r[0] * F_RS128, w1 = r[1] * F_RS128;
        red4(g_env1 + c * 128 + 4 * m0, w0, w1 * Y.y, w1 * Y.z, w1 * Y.w);
        float w2 = r[2] * F_RS128, w3 = r[3] * F_RS128;
        red4(g_env1 + c * 128 + 4 * (m0 + 1), w2, w3 * Y.y, w3 * Y.z, w3 * Y.w);
    }
};
struct OpG10 {  // [lat|q] dup (384 row) -> silu -> H(dup)
    __device__ const float* src(long e, int f) const {
        return (f < 256) ? (g_lat + e * 256 + f) : (g_q + e * 128 + (f - 256));
    }
    __device__ void epi(long e, int og, const float* r) const {
        float v[8];
#pragma unroll
        for (int i = 0; i < 8; i++) v[i] = silu_f(r[i] * F_RS192);
        store8dup(g_H + e * 256 + og * 16, v, 1.0f);
    }
};
struct OpG11 {  // H(dup) -> *fcut, residual, *isn -> node scatter
    const int* ctr;
    float* out;
    __device__ const float* src(long e, int f) const { return g_H + e * 256 + f; }
    __device__ void epi(long e, int og, const float* r) const {
        long c = ctr[e];
        float s = F_C_NEW * F_RS128 * g_fcut[e];
        const float* L = g_lat + e * 256 + og * 16;
        float4 a0 = *(const float4*)(L + 0),  a1 = *(const float4*)(L + 4);
        float4 a2 = *(const float4*)(L + 8),  a3 = *(const float4*)(L + 12);
        red4(out + c * 128 + og * 8,
             (F_C_OLD * a0.x + s * r[0]) * F_ISN, (F_C_OLD * a0.z + s * r[1]) * F_ISN,
             (F_C_OLD * a1.x + s * r[2]) * F_ISN, (F_C_OLD * a1.z + s * r[3]) * F_ISN);
        red4(out + c * 128 + og * 8 + 4,
             (F_C_OLD * a2.x + s * r[4]) * F_ISN, (F_C_OLD * a2.z + s * r[5]) * F_ISN,
             (F_C_OLD * a3.x + s * r[6]) * F_ISN, (F_C_OLD * a3.z + s * r[7]) * F_ISN);
    }
};

// ---------------------------------------------------------------------------
// k123: fused X0(40) -> silu(64) -> silu(128) -> *fcut*rs128 -> g_lat(dup)
// (internal pack2 path unchanged; only the final store is dup)
// ---------------------------------------------------------------------------
__global__ void __launch_bounds__(512, 1) k123(
    const float* __restrict__ W0g, const float* __restrict__ W1g,
    const float* __restrict__ W2g, int ntiles)
{
    extern __shared__ __align__(16) float sh[];
    float* sW0 = sh;                    // 2560
    float* sW1 = sh + 2560;             // 8192
    float* sW2 = sh + 10752;            // 16384
    float* sX  = sh + 27136;            // 2*5632
    float* sHU = sh + 38400;            // 16896 union

    int tid = threadIdx.x;
    for (int i = tid; i < 2560 / 4;  i += 512) ((float4*)sW0)[i] = ((const float4*)W0g)[i];
    for (int i = tid; i < 8192 / 4;  i += 512) ((float4*)sW1)[i] = ((const float4*)W1g)[i];
    for (int i = tid; i < 16384 / 4; i += 512) ((float4*)sW2)[i] = ((const float4*)W2g)[i];

    int lane = tid & 31, w = tid >> 5;
    int og = (w & 3) * 4 + (lane & 3);      // 0..15
    int eg = (w >> 2) * 8 + (lane >> 2);    // 0..31

    auto stage = [&](long t, int b) {
        float* dst = sX + b * 5632;
        for (int i = tid; i < 1280; i += 512) {
            int e_l = i / 10, ks = (i % 10) * 4;
            cpa16(dst + e_l * 44 + ks, g_X0 + (t * 128 + e_l) * 40 + ks);
        }
        cp_commit();
    };

    long t0 = blockIdx.x;
    if (t0 < ntiles) stage(t0, 0);
    int b = 0;

    for (long t = t0; t < ntiles; t += gridDim.x) {
        long nt = t + gridDim.x;
        bool hn = nt < ntiles;
        __syncthreads();
        if (hn) stage(nt, b ^ 1);
        if (hn) cp_wait1(); else cp_wait0();
        __syncthreads();

        // GEMM1: K=40 -> 64 (OPO=4) -> H1 (pitch 68)
        {
            const float* Xb = sX + b * 5632;
            ULL acc[4][2];
#pragma unroll
            for (int j = 0; j < 4; j++) { acc[j][0] = 0ULL; acc[j][1] = 0ULL; }
            const float* xr[4];
#pragma unroll
            for (int j = 0; j < 4; j++) xr[j] = Xb + (eg + 32 * j) * 44;
#pragma unroll 2
            for (int k4 = 0; k4 < 40; k4 += 4) {
                float4 xv[4];
#pragma unroll
                for (int j = 0; j < 4; j++) xv[j] = *(const float4*)(xr[j] + k4);
#pragma unroll
                for (int kk = 0; kk < 4; kk++) {
                    const float* wr = sW0 + (k4 + kk) * 64 + og * 4;
                    ulonglong2 wa = *(const ulonglong2*)wr;
#pragma unroll
                    for (int j = 0; j < 4; j++) {
                        float xs = (kk == 0) ? xv[j].x : (kk == 1) ? xv[j].y
                                 : (kk == 2) ? xv[j].z : xv[j].w;
                        ULL xd = pack2(xs);
                        acc[j][0] = fma2(xd, wa.x, acc[j][0]);
                        acc[j][1] = fma2(xd, wa.y, acc[j][1]);
                    }
                }
            }
#pragma unroll
            for (int j = 0; j < 4; j++) {
                union { ULL u; float2 f; } c0, c1;
                c0.u = acc[j][0]; c1.u = acc[j][1];
                *(float4*)(sHU + (eg + 32 * j) * 68 + og * 4) =
                    make_float4(silu_f(c0.f.x * F_RS40), silu_f(c0.f.y * F_RS40),
                                silu_f(c1.f.x * F_RS40), silu_f(c1.f.y * F_RS40));
            }
        }
        __syncthreads();

        // GEMM2: K=64 read H1 (pitch 68) -> regs; sync; store H2 (pitch 132)
        {
            ULL acc[4][4];
#pragma unroll
            for (int j = 0; j < 4; j++)
#pragma unroll
                for (int p = 0; p < 4; p++) acc[j][p] = 0ULL;
            const float* xr[4];
#pragma unroll
            for (int j = 0; j < 4; j++) xr[j] = sHU + (eg + 32 * j) * 68;
#pragma unroll 2
            for (int k4 = 0; k4 < 64; k4 += 4) {
                float4 xv[4];
#pragma unroll
                for (int j = 0; j < 4; j++) xv[j] = *(const float4*)(xr[j] + k4);
#pragma unroll
                for (int kk = 0; kk < 4; kk++) {
                    const float* wr = sW1 + (k4 + kk) * 128 + og * 8;
                    ulonglong2 wa = *(const ulonglong2*)wr;
                    ulonglong2 wb = *(const ulonglong2*)(wr + 4);
#pragma unroll
                    for (int j = 0; j < 4; j++) {
                        float xs = (kk == 0) ? xv[j].x : (kk == 1) ? xv[j].y
                                 : (kk == 2) ? xv[j].z : xv[j].w;
                        ULL xd = pack2(xs);
                        acc[j][0] = fma2(xd, wa.x, acc[j][0]);
                        acc[j][1] = fma2(xd, wa.y, acc[j][1]);
                        acc[j][2] = fma2(xd, wb.x, acc[j][2]);
                        acc[j][3] = fma2(xd, wb.y, acc[j][3]);
                    }
                }
            }
            __syncthreads();   // ALL H1 reads complete before H2 overwrites
#pragma unroll
            for (int j = 0; j < 4; j++) {
                float* hr = sHU + (eg + 32 * j) * 132 + og * 8;
                union { ULL u; float2 f; } c0, c1, c2, c3;
                c0.u = acc[j][0]; c1.u = acc[j][1]; c2.u = acc[j][2]; c3.u = acc[j][3];
                *(float4*)hr =
                    make_float4(silu_f(c0.f.x * F_RS64), silu_f(c0.f.y * F_RS64),
                                silu_f(c1.f.x * F_RS64), silu_f(c1.f.y * F_RS64));
                *(float4*)(hr + 4) =
                    make_float4(silu_f(c2.f.x * F_RS64), silu_f(c2.f.y * F_RS64),
                                silu_f(c3.f.x * F_RS64), silu_f(c3.f.y * F_RS64));
            }
        }
        __syncthreads();

        // GEMM3: K=128 read H2 (pitch 132) -> *fcut -> g_lat (DUP store)
        {
            ULL acc[4][4];
#pragma unroll
            for (int j = 0; j < 4; j++)
#pragma unroll
                for (int p = 0; p < 4; p++) acc[j][p] = 0ULL;
            const float* xr[4];
#pragma unroll
            for (int j = 0; j < 4; j++) xr[j] = sHU + (eg + 32 * j) * 132;
#pragma unroll 2
            for (int k4 = 0; k4 < 128; k4 += 4) {
                float4 xv[4];
#pragma unroll
                for (int j = 0; j < 4; j++) xv[j] = *(const float4*)(xr[j] + k4);
#pragma unroll
                for (int kk = 0; kk < 4; kk++) {
                    const float* wr = sW2 + (k4 + kk) * 128 + og * 8;
                    ulonglong2 wa = *(const ulonglong2*)wr;
                    ulonglong2 wb = *(const ulonglong2*)(wr + 4);
#pragma unroll
                    for (int j = 0; j < 4; j++) {
                        float xs = (kk == 0) ? xv[j].x : (kk == 1) ? xv[j].y
                                 : (kk == 2) ? xv[j].z : xv[j].w;
                        ULL xd = pack2(xs);
                        acc[j][0] = fma2(xd, wa.x, acc[j][0]);
                        acc[j][1] = fma2(xd, wa.y, acc[j][1]);
                        acc[j][2] = fma2(xd, wb.x, acc[j][2]);
                        acc[j][3] = fma2(xd, wb.y, acc[j][3]);
                    }
                }
            }
#pragma unroll
            for (int j = 0; j < 4; j++) {
                long e = t * 128 + eg + 32 * j;
                float s = F_RS128 * g_fcut[e];
                union { ULL u; float2 f; } c0, c1, c2, c3;
                c0.u = acc[j][0]; c1.u = acc[j][1]; c2.u = acc[j][2]; c3.u = acc[j][3];
                float v[8] = {c0.f.x, c0.f.y, c1.f.x, c1.f.y,
                              c2.f.x, c2.f.y, c3.f.x, c3.f.y};
                store8dup(g_lat + e * 256 + og * 16, v, s);
            }
        }
        b ^= 1;
    }
}

// ---------------------------------------------------------------------------
__global__ void k_zero(float* __restrict__ out)
{
    int i = blockIdx.x * blockDim.x + threadIdx.x;
    int stride = gridDim.x * blockDim.x;
    for (; i < NN * 128; i += stride) {
        g_env[i]  = 0.0f;
        g_env1[i] = 0.0f;
        out[i]    = 0.0f;
    }
}

__global__ void __launch_bounds__(512) kgeo(
    const float* __restrict__ coords, const float* __restrict__ attrs,
    const int* __restrict__ eidx)
{
    int e = blockIdx.x * 512 + threadIdx.x;
    if (e >= NE) return;
    int snd = eidx[e];
    int c   = eidx[NE + e];
    float dx = coords[c * 3 + 0] - coords[snd * 3 + 0];
    float dy = coords[c * 3 + 1] - coords[snd * 3 + 1];
    float dz = coords[c * 3 + 2] - coords[snd * 3 + 2];
    float r2 = dx * dx + dy * dy + dz * dz + 1e-12f;
    float r  = sqrtf(r2);
    float inv_r = 1.0f / r;
    float u  = r * F_INV_RMAX;
    float u2 = u * u, u3 = u2 * u, u6 = u3 * u3, u7 = u6 * u, u8 = u7 * u;
    float f  = 1.0f - 28.0f * u6 + 48.0f * u7 - 21.0f * u8;
    if (u >= 1.0f) f = 0.0f;
    g_fcut[e] = f;
    *(float4*)(g_Y + e * 4) = make_float4(1.0f, F_SQRT3 * dx * inv_r,
                                          F_SQRT3 * dy * inv_r, F_SQRT3 * dz * inv_r);
    float* X = g_X0 + (long)e * 40;
    const float4* ac = (const float4*)(attrs + c * 16);
    const float4* as = (const float4*)(attrs + snd * 16);
#pragma unroll
    for (int i = 0; i < 4; i++) ((float4*)X)[i] = ac[i];
#pragma unroll
    for (int i = 0; i < 4; i++) ((float4*)(X + 16))[i] = as[i];
    float bi = inv_r * f * F_BESSEL;
#pragma unroll
    for (int n = 0; n < 8; n++)
        X[32 + n] = bi * sinf((n + 1) * F_PI * u);
}

// kp1: products -> scal0(dup) + P rows (warp per edge, lane = m)
__global__ void __launch_bounds__(256) kp1(const int* __restrict__ eidx)
{
    int warp = (blockIdx.x * 256 + threadIdx.x) >> 5;
    int lane = threadIdx.x & 31;
    int nw = gridDim.x * 8;
    for (long e = warp; e < NE; e += nw) {
        long c = eidx[NE + e];
        float2 we = *(const float2*)(g_wedge + e * 64 + 2 * lane);
        float4 en = *(const float4*)(g_env + c * 128 + 4 * lane);
        float4 Y  = *(const float4*)(g_Y + e * 4);
        float fs  = we.x;
        float fv0 = we.y * Y.y, fv1 = we.y * Y.z, fv2 = we.y * Y.w;
        float es  = en.x * F_ISN;
        float ev0 = en.y * F_ISN, ev1 = en.z * F_ISN, ev2 = en.w * F_ISN;
        float s0 = fs * es;
        float s1 = (fv0 * ev0 + fv1 * ev1 + fv2 * ev2) * F_INV_SQRT3;
        *(float2*)(g_scal0 + e * 128 + 2 * lane)      = make_float2(s0, s0);
        *(float2*)(g_scal0 + e * 128 + 64 + 2 * lane) = make_float2(s1, s1);
        float* P0 = g_P + (3 * e + 0) * 96;
        float* P1 = g_P + (3 * e + 1) * 96;
        float* P2 = g_P + (3 * e + 2) * 96;
        P0[lane] = fs * ev0;  P1[lane] = fs * ev1;  P2[lane] = fs * ev2;
        P0[32 + lane] = fv0 * es; P1[32 + lane] = fv1 * es; P2[32 + lane] = fv2 * es;
        P0[64 + lane] = (fv1 * ev2 - fv2 * ev1) * F_INV_SQRT2;
        P1[64 + lane] = (fv2 * ev0 - fv0 * ev2) * F_INV_SQRT2;
        P2[64 + lane] = (fv0 * ev1 - fv1 * ev0) * F_INV_SQRT2;
    }
}

// kp2: q0/q1 -> g_q (dup)  (warp per edge, lane = m)
__global__ void __launch_bounds__(256) kp2(const int* __restrict__ eidx)
{
    int warp = (blockIdx.x * 256 + threadIdx.x) >> 5;
    int lane = threadIdx.x & 31;
    int nw = gridDim.x * 8;
    for (long e = warp; e < NE; e += nw) {
        long c = eidx[NE + e];
        float4 e1 = *(const float4*)(g_env1 + c * 128 + 4 * lane);
        float sm = g_smix[e * 32 + lane];
        float v0 = g_vmx[(3 * e + 0) * 32 + lane];
        float v1 = g_vmx[(3 * e + 1) * 32 + lane];
        float v2 = g_vmx[(3 * e + 2) * 32 + lane];
        float q0 = sm * e1.x * F_ISN;
        float q1 = (v0 * e1.y + v1 * e1.z + v2 * e1.w) * F_ISN * F_INV_SQRT3;
        *(float2*)(g_q + e * 128 + 2 * lane)      = make_float2(q0, q0);
        *(float2*)(g_q + e * 128 + 64 + 2 * lane) = make_float2(q1, q1);
    }
}

// ---------------------------------------------------------------------------
extern "C" void kernel_launch(void* const* d_in, const int* in_sizes, int n_in,
                              void* d_out, int out_size)
{
    const float* coords = (const float*)d_in[0];
    const float* attrs  = (const float*)d_in[1];
    const int*   eidx   = (const int*)  d_in[2];
    const float* W2b0   = (const float*)d_in[3];
    const float* W2b1   = (const float*)d_in[4];
    const float* W2b2   = (const float*)d_in[5];
    const float* Wenv0  = (const float*)d_in[6];
    const float* Wlat0  = (const float*)d_in[7];
    const float* Wlat1  = (const float*)d_in[8];
    const float* Ws0    = (const float*)d_in[9];
    const float* Wv0    = (const float*)d_in[10];
    const float* Wenv1  = (const float*)d_in[11];
    const float* Wfin0  = (const float*)d_in[12];
    const float* Wfin1  = (const float*)d_in[13];
    float* out = (float*)d_out;
    const int* ctr = eidx + NE;

    const size_t sm_k123   = (2560 + 8192 + 16384 + 11264 + 16896) * 4;  // 221184
    const size_t sm_d128   = (16384 + 2 * 128 * 132) * 4;                // 200704
    const size_t sm_d64o   = (8192 + 2 * 128 * 132) * 4;                 // 167936
    const size_t sm_d32    = (2048 + 2 * 128 * 132) * 4;                 // 143360
    const size_t sm_d192   = (24576 + 2 * 128 * 100) * 4;                // 200704
    const size_t sm_g6     = (3072 + 2 * 128 * 100) * 4;                 // 114688

    cudaFuncSetAttribute(k123, cudaFuncAttributeMaxDynamicSharedMemorySize, (int)sm_k123);
    cudaFuncSetAttribute(gk<128, 64, 128, 8, true,  OpG4>,  cudaFuncAttributeMaxDynamicSharedMemorySize, (int)sm_d128);
    cudaFuncSetAttribute(gk<64,  64, 32,  4, true,  OpG5>,  cudaFuncAttributeMaxDynamicSharedMemorySize, (int)sm_d32);
    cudaFuncSetAttribute(gk<96,  96, 32,  4, false, OpG6>,  cudaFuncAttributeMaxDynamicSharedMemorySize, (int)sm_g6);
    cudaFuncSetAttribute(gk<192, 48, 128, 8, true,  OpG7>,  cudaFuncAttributeMaxDynamicSharedMemorySize, (int)sm_d192);
    cudaFuncSetAttribute(gk<128, 64, 128, 8, true,  OpG8>,  cudaFuncAttributeMaxDynamicSharedMemorySize, (int)sm_d128);
    cudaFuncSetAttribute(gk<128, 64, 64,  4, true,  OpG9>,  cudaFuncAttributeMaxDynamicSharedMemorySize, (int)sm_d64o);
    cudaFuncSetAttribute(gk<192, 48, 128, 8, true,  OpG10>, cudaFuncAttributeMaxDynamicSharedMemorySize, (int)sm_d192);
    cudaFuncSetAttribute(gk<128, 64, 128, 8, true,  OpG11>, cudaFuncAttributeMaxDynamicSharedMemorySize, (int)sm_d128);

    const int NT  = NE / 128;    // 2500
    const int NT3 = NE3 / 128;   // 7500

    k_zero<<<512, 256>>>(out);
    kgeo<<<(NE + 511) / 512, 512>>>(coords, attrs, eidx);

    k123<<<148, 512, sm_k123>>>(W2b0, W2b1, W2b2, NT);
    gk<128, 64, 128, 8, true,  OpG4><<<148, 512, sm_d128>>>(OpG4{ctr}, Wenv0, NT);
    kp1<<<2560, 256>>>(eidx);
    gk<64,  64, 32,  4, true,  OpG5><<<148, 512, sm_d32>>>(OpG5{}, Ws0, NT);
    gk<96,  96, 32,  4, false, OpG6><<<148, 512, sm_g6>>>(OpG6{}, Wv0, NT3);
    gk<192, 48, 128, 8, true,  OpG7><<<148, 512, sm_d192>>>(OpG7{}, Wlat0, NT);
    gk<128, 64, 128, 8, true,  OpG8><<<148, 512, sm_d128>>>(OpG8{}, Wlat1, NT);
    gk<128, 64, 64,  4, true,  OpG9><<<148, 512, sm_d64o>>>(OpG9{ctr}, Wenv1, NT);
    kp2<<<2560, 256>>>(eidx);
    gk<192, 48, 128, 8, true,  OpG10><<<148, 512, sm_d192>>>(OpG10{}, Wfin0, NT);
    gk<128, 64, 128, 8, true,  OpG11><<<148, 512, sm_d128>>>(OpG11{ctr, out}, Wfin1, NT);
}

// round 11
// speedup vs baseline: 1.2208x; 1.2208x over previous
#include <cuda_runtime.h>

// ---------------------------------------------------------------------------
// Allegro GNN layer: streaming FFMA2 GEMMs (R9 proven core) + fused product
// kernel (kp1 computes scal0, smix, vmix directly; P never hits HBM).
//   k123  : X0 -> 40->64->128->128*fcut -> g_lat
//   OpG4  : lat @ Wenv0 -> wedge + env scatter     (KC=128)
//   kp1   : products -> scal0 + smix + vmix        (fused GEMVs in-warp)
//   OpG7/8: lat-update MLP + residual              (G8 KC=128)
//   OpG9  : lat @ Wenv1 -> env1 scatter            (KC=128)
//   kp2   : q0/q1
//   OpG10/11: final MLP + residual -> node scatter (G11 KC=128)
// ---------------------------------------------------------------------------

#define NN 10000
#define NE 320000
#define NE3 960000
typedef unsigned long long ULL;

__device__ float g_X0  [NE * 40];
__device__ float g_H   [NE * 128];
__device__ float g_lat [NE * 128];
__device__ float g_wedge[NE * 64];
__device__ float g_scal0[NE * 64];
__device__ float g_smix[NE * 32];
__device__ float g_vmx [NE3 * 32];
__device__ float g_q   [NE * 64];
__device__ float g_Y   [NE * 4];
__device__ float g_fcut[NE];
__device__ float g_env [NN * 128];
__device__ float g_env1[NN * 128];

#define F_RS40      0.15811388300841897f
#define F_RS64      0.125f
#define F_RS96      0.10206207261596575f
#define F_RS128     0.08838834764831845f
#define F_RS192     0.07216878364870323f
#define F_ISN       0.17677669529663689f
#define F_SQRT3     1.7320508075688772f
#define F_INV_SQRT3 0.5773502691896258f
#define F_INV_SQRT2 0.7071067811865476f
#define F_C_OLD     0.8944271909999159f
#define F_C_NEW     0.4472135954999579f
#define F_BESSEL    0.6324555320336759f
#define F_PI        3.14159265358979323846f
#define F_INV_RMAX  0.2f

__device__ __forceinline__ ULL fma2(ULL a, ULL b, ULL c) {
    ULL d;
    asm("fma.rn.f32x2 %0, %1, %2, %3;" : "=l"(d) : "l"(a), "l"(b), "l"(c));
    return d;
}
__device__ __forceinline__ ULL pack2(float x) {
    ULL d; unsigned u = __float_as_uint(x);
    asm("mov.b64 %0, {%1,%1};" : "=l"(d) : "r"(u));
    return d;
}
__device__ __forceinline__ void red4(float* p, float a, float b, float c, float d) {
    asm volatile("red.global.add.v4.f32 [%0], {%1,%2,%3,%4};"
                 :: "l"(p), "f"(a), "f"(b), "f"(c), "f"(d) : "memory");
}
__device__ __forceinline__ float silu_f(float v) {
    return v * __frcp_rn(1.0f + __expf(-v));
}
__device__ __forceinline__ void cpa16(const void* s, const void* g) {
    unsigned sa = (unsigned)__cvta_generic_to_shared(s);
    asm volatile("cp.async.cg.shared.global [%0], [%1], 16;" :: "r"(sa), "l"(g));
}
__device__ __forceinline__ void cp_commit() { asm volatile("cp.async.commit_group;"); }
__device__ __forceinline__ void cp_wait1()  { asm volatile("cp.async.wait_group 1;"); }
__device__ __forceinline__ void cp_wait0()  { asm volatile("cp.async.wait_group 0;"); }

// ---------------------------------------------------------------------------
// Generic streaming GEMM (R9 core).  BM=128 edge rows per tile, 512 threads.
// ---------------------------------------------------------------------------
template <int KTOT, int KC, int OUT, int OPO, class Op>
__global__ void __launch_bounds__(512, 1) gk(Op op, const float* __restrict__ Wg,
                                             int ntiles)
{
    constexpr int PC  = KC + 4;
    constexpr int NCH = KTOT / KC;
    constexpr int OG  = OUT / OPO;
    constexpr int OGW = OG / 4;
    constexpr int EGN = 512 / OG;
    constexpr int EPT = 128 / EGN;
    constexpr int NP  = OPO / 2;

    extern __shared__ __align__(16) float sh[];
    float* sW = sh;
    float* sX = sh + KTOT * OUT;

    int tid = threadIdx.x;
    for (int i = tid; i < KTOT * OUT / 4; i += 512)
        ((float4*)sW)[i] = ((const float4*)Wg)[i];

    int lane = tid & 31, w = tid >> 5;
    int og = (w & (OGW - 1)) * 4 + (lane & 3);
    int eg = (w / OGW) * 8 + (lane >> 2);

    auto stage = [&](long t, int c, int b) {
        float* dst = sX + b * (128 * PC);
        constexpr int UN = 128 * (KC / 4);
        for (int i = tid; i < UN; i += 512) {
            int e_l = i / (KC / 4);
            int ks  = (i % (KC / 4)) * 4;
            cpa16(dst + e_l * PC + ks, op.src(t * 128 + e_l, c * KC + ks));
        }
        cp_commit();
    };

    long t0 = blockIdx.x;
    if (t0 < ntiles) stage(t0, 0, 0);
    int b = 0;

    for (long t = t0; t < ntiles; t += gridDim.x) {
        ULL acc[EPT][NP];
#pragma unroll
        for (int j = 0; j < EPT; j++)
#pragma unroll
            for (int p = 0; p < NP; p++) acc[j][p] = 0ULL;

        for (int c = 0; c < NCH; c++) {
            long nt = t; int nc = c + 1;
            if (nc == NCH) { nt = t + gridDim.x; nc = 0; }
            bool hn = nt < ntiles;
            __syncthreads();
            if (hn) stage(nt, nc, b ^ 1);
            if (hn) cp_wait1(); else cp_wait0();
            __syncthreads();

            const float* Xb = sX + b * (128 * PC);
            const float* xr[EPT];
#pragma unroll
            for (int j = 0; j < EPT; j++) xr[j] = Xb + (eg + EGN * j) * PC;

#pragma unroll 2
            for (int k4 = 0; k4 < KC; k4 += 4) {
                float4 xv[EPT];
#pragma unroll
                for (int j = 0; j < EPT; j++)
                    xv[j] = *(const float4*)(xr[j] + k4);
#pragma unroll
                for (int kk = 0; kk < 4; kk++) {
                    const float* wr = sW + (c * KC + k4 + kk) * OUT + og * OPO;
                    ULL wv[NP];
#pragma unroll
                    for (int p = 0; p < NP; p++)
                        wv[p] = *(const ULL*)(wr + 2 * p);
#pragma unroll
                    for (int j = 0; j < EPT; j++) {
                        float xs = (kk == 0) ? xv[j].x : (kk == 1) ? xv[j].y
                                 : (kk == 2) ? xv[j].z : xv[j].w;
                        ULL xd = pack2(xs);
#pragma unroll
                        for (int p = 0; p < NP; p++)
                            acc[j][p] = fma2(xd, wv[p], acc[j][p]);
                    }
                }
            }
            b ^= 1;
        }

#pragma unroll
        for (int j = 0; j < EPT; j++) {
            long e = t * 128 + eg + EGN * j;
            float r[OPO];
#pragma unroll
            for (int p = 0; p < NP; p++) {
                union { ULL u; float2 f; } cv; cv.u = acc[j][p];
                r[2 * p] = cv.f.x; r[2 * p + 1] = cv.f.y;
            }
            op.epi(e, og, r);
        }
    }
}

// ---------------------------------------------------------------------------
// Epilogue / source policies
// ---------------------------------------------------------------------------
struct OpG4 {   // lat -> w_all(128): outs 0-63 wedge, 64-127 env scatter
    const int* ctr;
    __device__ const float* src(long e, int k) const { return g_lat + e * 128 + k; }
    __device__ void epi(long e, int og, const float* r) const {
        if (og < 8) {
            *(float4*)(g_wedge + e * 64 + og * 8) =
                make_float4(r[0] * F_RS128, r[1] * F_RS128, r[2] * F_RS128, r[3] * F_RS128);
            *(float4*)(g_wedge + e * 64 + og * 8 + 4) =
                make_float4(r[4] * F_RS128, r[5] * F_RS128, r[6] * F_RS128, r[7] * F_RS128);
        } else {
            long c = ctr[e];
            float4 Y = *(const float4*)(g_Y + e * 4);
#pragma unroll
            for (int p = 0; p < 4; p++) {
                int m = (og - 8) * 4 + p;
                float w0 = r[2 * p] * F_RS128, w1 = r[2 * p + 1] * F_RS128;
                red4(g_env + c * 128 + 4 * m, w0, w1 * Y.y, w1 * Y.z, w1 * Y.w);
            }
        }
    }
};
struct OpG7 {   // [lat|scal0](192) -> silu -> H(128)
    __device__ const float* src(long e, int k) const {
        return (k < 128) ? (g_lat + e * 128 + k) : (g_scal0 + e * 64 + (k - 128));
    }
    __device__ void epi(long e, int og, const float* r) const {
        *(float4*)(g_H + e * 128 + og * 8) =
            make_float4(silu_f(r[0] * F_RS192), silu_f(r[1] * F_RS192),
                        silu_f(r[2] * F_RS192), silu_f(r[3] * F_RS192));
        *(float4*)(g_H + e * 128 + og * 8 + 4) =
            make_float4(silu_f(r[4] * F_RS192), silu_f(r[5] * F_RS192),
                        silu_f(r[6] * F_RS192), silu_f(r[7] * F_RS192));
    }
};
struct OpG8 {   // H(128) -> *fcut, residual -> lat
    __device__ const float* src(long e, int k) const { return g_H + e * 128 + k; }
    __device__ void epi(long e, int og, const float* r) const {
        float s = F_C_NEW * F_RS128 * g_fcut[e];
        float4 l0 = *(const float4*)(g_lat + e * 128 + og * 8);
        float4 l1 = *(const float4*)(g_lat + e * 128 + og * 8 + 4);
        *(float4*)(g_lat + e * 128 + og * 8) =
            make_float4(F_C_OLD * l0.x + s * r[0], F_C_OLD * l0.y + s * r[1],
                        F_C_OLD * l0.z + s * r[2], F_C_OLD * l0.w + s * r[3]);
        *(float4*)(g_lat + e * 128 + og * 8 + 4) =
            make_float4(F_C_OLD * l1.x + s * r[4], F_C_OLD * l1.y + s * r[5],
                        F_C_OLD * l1.z + s * r[6], F_C_OLD * l1.w + s * r[7]);
    }
};
struct OpG9 {   // lat -> w_env1(64) -> env1 scatter
    const int* ctr;
    __device__ const float* src(long e, int k) const { return g_lat + e * 128 + k; }
    __device__ void epi(long e, int og, const float* r) const {
        long c = ctr[e];
        float4 Y = *(const float4*)(g_Y + e * 4);
        int m0 = og * 2;
        float w0 = r[0] * F_RS128, w1 = r[1] * F_RS128;
        red4(g_env1 + c * 128 + 4 * m0, w0, w1 * Y.y, w1 * Y.z, w1 * Y.w);
        float w2 = r[2] * F_RS128, w3 = r[3] * F_RS128;
        red4(g_env1 + c * 128 + 4 * (m0 + 1), w2, w3 * Y.y, w3 * Y.z, w3 * Y.w);
    }
};
struct OpG10 {  // [lat|q](192) -> silu -> H(128)
    __device__ const float* src(long e, int k) const {
        return (k < 128) ? (g_lat + e * 128 + k) : (g_q + e * 64 + (k - 128));
    }
    __device__ void epi(long e, int og, const float* r) const {
        *(float4*)(g_H + e * 128 + og * 8) =
            make_float4(silu_f(r[0] * F_RS192), silu_f(r[1] * F_RS192),
                        silu_f(r[2] * F_RS192), silu_f(r[3] * F_RS192));
        *(float4*)(g_H + e * 128 + og * 8 + 4) =
            make_float4(silu_f(r[4] * F_RS192), silu_f(r[5] * F_RS192),
                        silu_f(r[6] * F_RS192), silu_f(r[7] * F_RS192));
    }
};
struct OpG11 {  // H(128) -> *fcut, residual, *isn -> node scatter
    const int* ctr;
    float* out;
    __device__ const float* src(long e, int k) const { return g_H + e * 128 + k; }
    __device__ void epi(long e, int og, const float* r) const {
        long c = ctr[e];
        float s = F_C_NEW * F_RS128 * g_fcut[e];
        float4 l0 = *(const float4*)(g_lat + e * 128 + og * 8);
        float4 l1 = *(const float4*)(g_lat + e * 128 + og * 8 + 4);
        red4(out + c * 128 + og * 8,
             (F_C_OLD * l0.x + s * r[0]) * F_ISN, (F_C_OLD * l0.y + s * r[1]) * F_ISN,
             (F_C_OLD * l0.z + s * r[2]) * F_ISN, (F_C_OLD * l0.w + s * r[3]) * F_ISN);
        red4(out + c * 128 + og * 8 + 4,
             (F_C_OLD * l1.x + s * r[4]) * F_ISN, (F_C_OLD * l1.y + s * r[5]) * F_ISN,
             (F_C_OLD * l1.z + s * r[6]) * F_ISN, (F_C_OLD * l1.w + s * r[7]) * F_ISN);
    }
};

// ---------------------------------------------------------------------------
// k123: fused X0(40) -> silu(64) -> silu(128) -> *fcut*rs128 -> g_lat
// (identical to R9)
// ---------------------------------------------------------------------------
__global__ void __launch_bounds__(512, 1) k123(
    const float* __restrict__ W0g, const float* __restrict__ W1g,
    const float* __restrict__ W2g, int ntiles)
{
    extern __shared__ __align__(16) float sh[];
    float* sW0 = sh;                    // 2560
    float* sW1 = sh + 2560;             // 8192
    float* sW2 = sh + 10752;            // 16384
    float* sX  = sh + 27136;            // 2*5632
    float* sHU = sh + 38400;            // 16896 union

    int tid = threadIdx.x;
    for (int i = tid; i < 2560 / 4;  i += 512) ((float4*)sW0)[i] = ((const float4*)W0g)[i];
    for (int i = tid; i < 8192 / 4;  i += 512) ((float4*)sW1)[i] = ((const float4*)W1g)[i];
    for (int i = tid; i < 16384 / 4; i += 512) ((float4*)sW2)[i] = ((const float4*)W2g)[i];

    int lane = tid & 31, w = tid >> 5;
    int og = (w & 3) * 4 + (lane & 3);      // 0..15
    int eg = (w >> 2) * 8 + (lane >> 2);    // 0..31

    auto stage = [&](long t, int b) {
        float* dst = sX + b * 5632;
        for (int i = tid; i < 1280; i += 512) {
            int e_l = i / 10, ks = (i % 10) * 4;
            cpa16(dst + e_l * 44 + ks, g_X0 + (t * 128 + e_l) * 40 + ks);
        }
        cp_commit();
    };

    long t0 = blockIdx.x;
    if (t0 < ntiles) stage(t0, 0);
    int b = 0;

    for (long t = t0; t < ntiles; t += gridDim.x) {
        long nt = t + gridDim.x;
        bool hn = nt < ntiles;
        __syncthreads();
        if (hn) stage(nt, b ^ 1);
        if (hn) cp_wait1(); else cp_wait0();
        __syncthreads();

        // GEMM1: K=40 -> 64 (OPO=4) -> H1 (pitch 68)
        {
            const float* Xb = sX + b * 5632;
            ULL acc[4][2];
#pragma unroll
            for (int j = 0; j < 4; j++) { acc[j][0] = 0ULL; acc[j][1] = 0ULL; }
            const float* xr[4];
#pragma unroll
            for (int j = 0; j < 4; j++) xr[j] = Xb + (eg + 32 * j) * 44;
#pragma unroll 2
            for (int k4 = 0; k4 < 40; k4 += 4) {
                float4 xv[4];
#pragma unroll
                for (int j = 0; j < 4; j++) xv[j] = *(const float4*)(xr[j] + k4);
#pragma unroll
                for (int kk = 0; kk < 4; kk++) {
                    const float* wr = sW0 + (k4 + kk) * 64 + og * 4;
                    ULL w0 = *(const ULL*)wr, w1 = *(const ULL*)(wr + 2);
#pragma unroll
                    for (int j = 0; j < 4; j++) {
                        float xs = (kk == 0) ? xv[j].x : (kk == 1) ? xv[j].y
                                 : (kk == 2) ? xv[j].z : xv[j].w;
                        ULL xd = pack2(xs);
                        acc[j][0] = fma2(xd, w0, acc[j][0]);
                        acc[j][1] = fma2(xd, w1, acc[j][1]);
                    }
                }
            }
#pragma unroll
            for (int j = 0; j < 4; j++) {
                union { ULL u; float2 f; } c0, c1;
                c0.u = acc[j][0]; c1.u = acc[j][1];
                *(float4*)(sHU + (eg + 32 * j) * 68 + og * 4) =
                    make_float4(silu_f(c0.f.x * F_RS40), silu_f(c0.f.y * F_RS40),
                                silu_f(c1.f.x * F_RS40), silu_f(c1.f.y * F_RS40));
            }
        }
        __syncthreads();

        // GEMM2: K=64 read H1 (pitch 68) -> regs; sync; store H2 (pitch 132)
        {
            ULL acc[4][4];
#pragma unroll
            for (int j = 0; j < 4; j++)
#pragma unroll
                for (int p = 0; p < 4; p++) acc[j][p] = 0ULL;
            const float* xr[4];
#pragma unroll
            for (int j = 0; j < 4; j++) xr[j] = sHU + (eg + 32 * j) * 68;
#pragma unroll 2
            for (int k4 = 0; k4 < 64; k4 += 4) {
                float4 xv[4];
#pragma unroll
                for (int j = 0; j < 4; j++) xv[j] = *(const float4*)(xr[j] + k4);
#pragma unroll
                for (int kk = 0; kk < 4; kk++) {
                    const float* wr = sW1 + (k4 + kk) * 128 + og * 8;
                    ulonglong2 wa = *(const ulonglong2*)wr;
                    ulonglong2 wb = *(const ulonglong2*)(wr + 4);
#pragma unroll
                    for (int j = 0; j < 4; j++) {
                        float xs = (kk == 0) ? xv[j].x : (kk == 1) ? xv[j].y
                                 : (kk == 2) ? xv[j].z : xv[j].w;
                        ULL xd = pack2(xs);
                        acc[j][0] = fma2(xd, wa.x, acc[j][0]);
                        acc[j][1] = fma2(xd, wa.y, acc[j][1]);
                        acc[j][2] = fma2(xd, wb.x, acc[j][2]);
                        acc[j][3] = fma2(xd, wb.y, acc[j][3]);
                    }
                }
            }
            __syncthreads();   // ALL H1 reads complete before H2 overwrites
#pragma unroll
            for (int j = 0; j < 4; j++) {
                float* hr = sHU + (eg + 32 * j) * 132 + og * 8;
                union { ULL u; float2 f; } c0, c1, c2, c3;
                c0.u = acc[j][0]; c1.u = acc[j][1]; c2.u = acc[j][2]; c3.u = acc[j][3];
                *(float4*)hr =
                    make_float4(silu_f(c0.f.x * F_RS64), silu_f(c0.f.y * F_RS64),
                                silu_f(c1.f.x * F_RS64), silu_f(c1.f.y * F_RS64));
                *(float4*)(hr + 4) =
                    make_float4(silu_f(c2.f.x * F_RS64), silu_f(c2.f.y * F_RS64),
                                silu_f(c3.f.x * F_RS64), silu_f(c3.f.y * F_RS64));
            }
        }
        __syncthreads();

        // GEMM3: K=128 read H2 (pitch 132) -> *fcut -> g_lat
        {
            ULL acc[4][4];
#pragma unroll
            for (int j = 0; j < 4; j++)
#pragma unroll
                for (int p = 0; p < 4; p++) acc[j][p] = 0ULL;
            const float* xr[4];
#pragma unroll
            for (int j = 0; j < 4; j++) xr[j] = sHU + (eg + 32 * j) * 132;
#pragma unroll 2
            for (int k4 = 0; k4 < 128; k4 += 4) {
                float4 xv[4];
#pragma unroll
                for (int j = 0; j < 4; j++) xv[j] = *(const float4*)(xr[j] + k4);
#pragma unroll
                for (int kk = 0; kk < 4; kk++) {
                    const float* wr = sW2 + (k4 + kk) * 128 + og * 8;
                    ulonglong2 wa = *(const ulonglong2*)wr;
                    ulonglong2 wb = *(const ulonglong2*)(wr + 4);
#pragma unroll
                    for (int j = 0; j < 4; j++) {
                        float xs = (kk == 0) ? xv[j].x : (kk == 1) ? xv[j].y
                                 : (kk == 2) ? xv[j].z : xv[j].w;
                        ULL xd = pack2(xs);
                        acc[j][0] = fma2(xd, wa.x, acc[j][0]);
                        acc[j][1] = fma2(xd, wa.y, acc[j][1]);
                        acc[j][2] = fma2(xd, wb.x, acc[j][2]);
                        acc[j][3] = fma2(xd, wb.y, acc[j][3]);
                    }
                }
            }
#pragma unroll
            for (int j = 0; j < 4; j++) {
                long e = t * 128 + eg + 32 * j;
                float s = F_RS128 * g_fcut[e];
                union { ULL u; float2 f; } c0, c1, c2, c3;
                c0.u = acc[j][0]; c1.u = acc[j][1]; c2.u = acc[j][2]; c3.u = acc[j][3];
                *(float4*)(g_lat + e * 128 + og * 8) =
                    make_float4(c0.f.x * s, c0.f.y * s, c1.f.x * s, c1.f.y * s);
                *(float4*)(g_lat + e * 128 + og * 8 + 4) =
                    make_float4(c2.f.x * s, c2.f.y * s, c3.f.x * s, c3.f.y * s);
            }
        }
        b ^= 1;
    }
}

// ---------------------------------------------------------------------------
__global__ void k_zero(float* __restrict__ out)
{
    int i = blockIdx.x * blockDim.x + threadIdx.x;
    int stride = gridDim.x * blockDim.x;
    for (; i < NN * 128; i += stride) {
        g_env[i]  = 0.0f;
        g_env1[i] = 0.0f;
        out[i]    = 0.0f;
    }
}

__global__ void __launch_bounds__(512) kgeo(
    const float* __restrict__ coords, const float* __restrict__ attrs,
    const int* __restrict__ eidx)
{
    int e = blockIdx.x * 512 + threadIdx.x;
    if (e >= NE) return;
    int snd = eidx[e];
    int c   = eidx[NE + e];
    float dx = coords[c * 3 + 0] - coords[snd * 3 + 0];
    float dy = coords[c * 3 + 1] - coords[snd * 3 + 1];
    float dz = coords[c * 3 + 2] - coords[snd * 3 + 2];
    float r2 = dx * dx + dy * dy + dz * dz + 1e-12f;
    float r  = sqrtf(r2);
    float inv_r = 1.0f / r;
    float u  = r * F_INV_RMAX;
    float u2 = u * u, u3 = u2 * u, u6 = u3 * u3, u7 = u6 * u, u8 = u7 * u;
    float f  = 1.0f - 28.0f * u6 + 48.0f * u7 - 21.0f * u8;
    if (u >= 1.0f) f = 0.0f;
    g_fcut[e] = f;
    *(float4*)(g_Y + e * 4) = make_float4(1.0f, F_SQRT3 * dx * inv_r,
                                          F_SQRT3 * dy * inv_r, F_SQRT3 * dz * inv_r);
    float* X = g_X0 + (long)e * 40;
    const float4* ac = (const float4*)(attrs + c * 16);
    const float4* as = (const float4*)(attrs + snd * 16);
#pragma unroll
    for (int i = 0; i < 4; i++) ((float4*)X)[i] = ac[i];
#pragma unroll
    for (int i = 0; i < 4; i++) ((float4*)(X + 16))[i] = as[i];
    float bi = inv_r * f * F_BESSEL;
#pragma unroll
    for (int n = 0; n < 8; n++)
        X[32 + n] = bi * sinf((n + 1) * F_PI * u);
}

// ---------------------------------------------------------------------------
// kp1 (fused): products -> scal0 + smix + vmix.  Warp per edge, lane = i.
// Per-warp P tile in smem [32 i][36] (triplets per c at 4c..4c+2), weights
// Ws0/Wv0 smem-resident.  P never touches global.
// smem layout: sWs 2048 | sWv 3072 | sS 8*64 | sP 8*1152
// ---------------------------------------------------------------------------
__global__ void __launch_bounds__(256) kp1(
    const int* __restrict__ eidx,
    const float* __restrict__ Ws0, const float* __restrict__ Wv0)
{
    extern __shared__ __align__(16) float shp[];
    float* sWs = shp;                 // 64*32 = 2048
    float* sWv = shp + 2048;          // 96*32 = 3072
    float* sS  = shp + 5120;          // 8*64  = 512
    float* sP  = shp + 5632;          // 8*1152 = 9216

    int tid = threadIdx.x;
    for (int i = tid; i < 2048; i += 256) sWs[i] = Ws0[i];
    for (int i = tid; i < 3072; i += 256) sWv[i] = Wv0[i];
    __syncthreads();

    int warp = tid >> 5, lane = tid & 31;
    float* Sw = sS + warp * 64;
    float* Pw = sP + warp * 1152;
    long gw = (long)blockIdx.x * 8 + warp;
    long nw = (long)gridDim.x * 8;

    for (long e = gw; e < NE; e += nw) {
        long c = eidx[NE + e];
        float2 we = *(const float2*)(g_wedge + e * 64 + 2 * lane);
        float4 en = *(const float4*)(g_env + c * 128 + 4 * lane);
        float4 Y  = *(const float4*)(g_Y + e * 4);
        float fs  = we.x;
        float fv0 = we.y * Y.y, fv1 = we.y * Y.z, fv2 = we.y * Y.w;
        float es  = en.x * F_ISN;
        float ev0 = en.y * F_ISN, ev1 = en.z * F_ISN, ev2 = en.w * F_ISN;
        float s0 = fs * es;
        float s1 = (fv0 * ev0 + fv1 * ev1 + fv2 * ev2) * F_INV_SQRT3;
        g_scal0[e * 64 + lane]      = s0;
        g_scal0[e * 64 + 32 + lane] = s1;
        Sw[lane]      = s0;
        Sw[32 + lane] = s1;
        float* P = Pw + lane * 36;
        *(float4*)(P + 0) = make_float4(
            fs * ev0, fv0 * es, (fv1 * ev2 - fv2 * ev1) * F_INV_SQRT2, 0.0f);
        *(float4*)(P + 4) = make_float4(
            fs * ev1, fv1 * es, (fv2 * ev0 - fv0 * ev2) * F_INV_SQRT2, 0.0f);
        *(float4*)(P + 8) = make_float4(
            fs * ev2, fv2 * es, (fv0 * ev1 - fv1 * ev0) * F_INV_SQRT2, 0.0f);
        __syncwarp();

        // vmix: out o = lane; 3 c-components; W loads shared across c
        float a0 = 0.0f, a1 = 0.0f, a2 = 0.0f;
#pragma unroll 4
        for (int i = 0; i < 32; i++) {
            float w0 = sWv[i * 32 + lane];
            float w1 = sWv[(32 + i) * 32 + lane];
            float w2 = sWv[(64 + i) * 32 + lane];
            float4 p0 = *(const float4*)(Pw + i * 36 + 0);
            float4 p1 = *(const float4*)(Pw + i * 36 + 4);
            float4 p2 = *(const float4*)(Pw + i * 36 + 8);
            a0 = fmaf(p0.x, w0, fmaf(p0.y, w1, fmaf(p0.z, w2, a0)));
            a1 = fmaf(p1.x, w0, fmaf(p1.y, w1, fmaf(p1.z, w2, a1)));
            a2 = fmaf(p2.x, w0, fmaf(p2.y, w1, fmaf(p2.z, w2, a2)));
        }
        g_vmx[(3 * e + 0) * 32 + lane] = a0 * F_RS96;
        g_vmx[(3 * e + 1) * 32 + lane] = a1 * F_RS96;
        g_vmx[(3 * e + 2) * 32 + lane] = a2 * F_RS96;

        // smix: out o = lane
        float sm = 0.0f;
#pragma unroll 4
        for (int j = 0; j < 64; j++)
            sm = fmaf(Sw[j], sWs[j * 32 + lane], sm);
        g_smix[e * 32 + lane] = sm * F_RS64;
        __syncwarp();
    }
}

// kp2: q0/q1 (warp per edge, lane = m)
__global__ void __launch_bounds__(256) kp2(const int* __restrict__ eidx)
{
    int warp = (blockIdx.x * 256 + threadIdx.x) >> 5;
    int lane = threadIdx.x & 31;
    int nw = gridDim.x * 8;
    for (long e = warp; e < NE; e += nw) {
        long c = eidx[NE + e];
        float4 e1 = *(const float4*)(g_env1 + c * 128 + 4 * lane);
        float sm = g_smix[e * 32 + lane];
        float v0 = g_vmx[(3 * e + 0) * 32 + lane];
        float v1 = g_vmx[(3 * e + 1) * 32 + lane];
        float v2 = g_vmx[(3 * e + 2) * 32 + lane];
        g_q[e * 64 + lane] = sm * e1.x * F_ISN;
        g_q[e * 64 + 32 + lane] =
            (v0 * e1.y + v1 * e1.z + v2 * e1.w) * F_ISN * F_INV_SQRT3;
    }
}

// ---------------------------------------------------------------------------
extern "C" void kernel_launch(void* const* d_in, const int* in_sizes, int n_in,
                              void* d_out, int out_size)
{
    const float* coords = (const float*)d_in[0];
    const float* attrs  = (const float*)d_in[1];
    const int*   eidx   = (const int*)  d_in[2];
    const float* W2b0   = (const float*)d_in[3];
    const float* W2b1   = (const float*)d_in[4];
    const float* W2b2   = (const float*)d_in[5];
    const float* Wenv0  = (const float*)d_in[6];
    const float* Wlat0  = (const float*)d_in[7];
    const float* Wlat1  = (const float*)d_in[8];
    const float* Ws0    = (const float*)d_in[9];
    const float* Wv0    = (const float*)d_in[10];
    const float* Wenv1  = (const float*)d_in[11];
    const float* Wfin0  = (const float*)d_in[12];
    const float* Wfin1  = (const float*)d_in[13];
    float* out = (float*)d_out;
    const int* ctr = eidx + NE;

    const size_t sm_k123    = (2560 + 8192 + 16384 + 11264 + 16896) * 4;  // 221184
    const size_t sm128_128c = (16384 + 2 * 128 * 132) * 4;                // 200704
    const size_t sm128_64c  = (8192 + 2 * 128 * 132) * 4;                 // 167936
    const size_t sm192_128  = (24576 + 2 * 128 * 100) * 4;                // 200704
    const size_t sm_kp1     = (2048 + 3072 + 512 + 9216) * 4;             //  59392

    cudaFuncSetAttribute(k123, cudaFuncAttributeMaxDynamicSharedMemorySize, (int)sm_k123);
    cudaFuncSetAttribute(kp1,  cudaFuncAttributeMaxDynamicSharedMemorySize, (int)sm_kp1);
    cudaFuncSetAttribute(gk<128, 128, 128, 8, OpG4>,  cudaFuncAttributeMaxDynamicSharedMemorySize, (int)sm128_128c);
    cudaFuncSetAttribute(gk<192, 96, 128, 8, OpG7>,   cudaFuncAttributeMaxDynamicSharedMemorySize, (int)sm192_128);
    cudaFuncSetAttribute(gk<128, 128, 128, 8, OpG8>,  cudaFuncAttributeMaxDynamicSharedMemorySize, (int)sm128_128c);
    cudaFuncSetAttribute(gk<128, 128, 64, 4, OpG9>,   cudaFuncAttributeMaxDynamicSharedMemorySize, (int)sm128_64c);
    cudaFuncSetAttribute(gk<192, 96, 128, 8, OpG10>,  cudaFuncAttributeMaxDynamicSharedMemorySize, (int)sm192_128);
    cudaFuncSetAttribute(gk<128, 128, 128, 8, OpG11>, cudaFuncAttributeMaxDynamicSharedMemorySize, (int)sm128_128c);

    const int NT = NE / 128;    // 2500

    k_zero<<<512, 256>>>(out);
    kgeo<<<(NE + 511) / 512, 512>>>(coords, attrs, eidx);

    k123<<<148, 512, sm_k123>>>(W2b0, W2b1, W2b2, NT);
    gk<128, 128, 128, 8, OpG4><<<148, 512, sm128_128c>>>(OpG4{ctr}, Wenv0, NT);
    kp1<<<1184, 256, sm_kp1>>>(eidx, Ws0, Wv0);
    gk<192, 96, 128, 8, OpG7><<<148, 512, sm192_128>>>(OpG7{}, Wlat0, NT);
    gk<128, 128, 128, 8, OpG8><<<148, 512, sm128_128c>>>(OpG8{}, Wlat1, NT);
    gk<128, 128, 64, 4, OpG9><<<148, 512, sm128_64c>>>(OpG9{ctr}, Wenv1, NT);
    kp2<<<2560, 256>>>(eidx);
    gk<192, 96, 128, 8, OpG10><<<148, 512, sm192_128>>>(OpG10{}, Wfin0, NT);
    gk<128, 128, 128, 8, OpG11><<<148, 512, sm128_128c>>>(OpG11{ctr, out}, Wfin1, NT);
}

// round 12
// speedup vs baseline: 1.2722x; 1.0421x over previous
#include <cuda_runtime.h>

// ---------------------------------------------------------------------------
// Allegro GNN layer: streaming FFMA2 GEMMs.
//   k123  : X0 -> 40->64->128->128*fcut -> g_lat   (512 thr, 1 CTA/SM)
//   OpG4  : lat @ Wenv0 -> wedge + env scatter      (gk2: 256 thr, 2 CTA/SM)
//   kp1   : products -> scal0 + P
//   OpG5  : scal0 @ Ws0 -> smix
//   OpG6  : P @ Wv0 -> vmx
//   OpG7/8: lat-update MLP + residual               (G7 512thr, G8 gk2)
//   OpG9  : lat @ Wenv1 -> env1 scatter             (gk2)
//   kp2   : q0/q1
//   OpG10/11: final MLP + residual -> node scatter  (G10 512thr, G11 gk2)
// ---------------------------------------------------------------------------

#define NN 10000
#define NE 320000
#define NE3 960000
typedef unsigned long long ULL;

__device__ float g_X0  [NE * 40];
__device__ float g_H   [NE * 128];
__device__ float g_lat [NE * 128];
__device__ float g_wedge[NE * 64];
__device__ float g_scal0[NE * 64];
__device__ float g_P   [(long)NE3 * 96];
__device__ float g_smix[NE * 32];
__device__ float g_vmx [NE3 * 32];
__device__ float g_q   [NE * 64];
__device__ float g_Y   [NE * 4];
__device__ float g_fcut[NE];
__device__ float g_env [NN * 128];
__device__ float g_env1[NN * 128];

#define F_RS40      0.15811388300841897f
#define F_RS64      0.125f
#define F_RS96      0.10206207261596575f
#define F_RS128     0.08838834764831845f
#define F_RS192     0.07216878364870323f
#define F_ISN       0.17677669529663689f
#define F_SQRT3     1.7320508075688772f
#define F_INV_SQRT3 0.5773502691896258f
#define F_INV_SQRT2 0.7071067811865476f
#define F_C_OLD     0.8944271909999159f
#define F_C_NEW     0.4472135954999579f
#define F_BESSEL    0.6324555320336759f
#define F_PI        3.14159265358979323846f
#define F_INV_RMAX  0.2f

__device__ __forceinline__ ULL fma2(ULL a, ULL b, ULL c) {
    ULL d;
    asm("fma.rn.f32x2 %0, %1, %2, %3;" : "=l"(d) : "l"(a), "l"(b), "l"(c));
    return d;
}
__device__ __forceinline__ ULL pack2(float x) {
    ULL d; unsigned u = __float_as_uint(x);
    asm("mov.b64 %0, {%1,%1};" : "=l"(d) : "r"(u));
    return d;
}
__device__ __forceinline__ void red4(float* p, float a, float b, float c, float d) {
    asm volatile("red.global.add.v4.f32 [%0], {%1,%2,%3,%4};"
                 :: "l"(p), "f"(a), "f"(b), "f"(c), "f"(d) : "memory");
}
__device__ __forceinline__ float silu_f(float v) {
    return v * __frcp_rn(1.0f + __expf(-v));
}
__device__ __forceinline__ void cpa16(const void* s, const void* g) {
    unsigned sa = (unsigned)__cvta_generic_to_shared(s);
    asm volatile("cp.async.cg.shared.global [%0], [%1], 16;" :: "r"(sa), "l"(g));
}
__device__ __forceinline__ void cp_commit() { asm volatile("cp.async.commit_group;"); }
__device__ __forceinline__ void cp_wait1()  { asm volatile("cp.async.wait_group 1;"); }
__device__ __forceinline__ void cp_wait0()  { asm volatile("cp.async.wait_group 0;"); }

// ---------------------------------------------------------------------------
// Streaming GEMM, 512 threads, BM=128, 1 CTA/SM  (used for 192-K and G6/G5)
// ---------------------------------------------------------------------------
template <int KTOT, int KC, int OUT, int OPO, class Op>
__global__ void __launch_bounds__(512, 1) gk(Op op, const float* __restrict__ Wg,
                                             int ntiles)
{
    constexpr int PC  = KC + 4;
    constexpr int NCH = KTOT / KC;
    constexpr int OG  = OUT / OPO;
    constexpr int OGW = OG / 4;
    constexpr int EGN = 512 / OG;
    constexpr int EPT = 128 / EGN;
    constexpr int NP  = OPO / 2;

    extern __shared__ __align__(16) float sh[];
    float* sW = sh;
    float* sX = sh + KTOT * OUT;

    int tid = threadIdx.x;
    for (int i = tid; i < KTOT * OUT / 4; i += 512)
        ((float4*)sW)[i] = ((const float4*)Wg)[i];

    int lane = tid & 31, w = tid >> 5;
    int og = (w & (OGW - 1)) * 4 + (lane & 3);
    int eg = (w / OGW) * 8 + (lane >> 2);

    auto stage = [&](long t, int c, int b) {
        float* dst = sX + b * (128 * PC);
        constexpr int UN = 128 * (KC / 4);
        for (int i = tid; i < UN; i += 512) {
            int e_l = i / (KC / 4);
            int ks  = (i % (KC / 4)) * 4;
            cpa16(dst + e_l * PC + ks, op.src(t * 128 + e_l, c * KC + ks));
        }
        cp_commit();
    };

    long t0 = blockIdx.x;
    if (t0 < ntiles) stage(t0, 0, 0);
    int b = 0;

    for (long t = t0; t < ntiles; t += gridDim.x) {
        ULL acc[EPT][NP];
#pragma unroll
        for (int j = 0; j < EPT; j++)
#pragma unroll
            for (int p = 0; p < NP; p++) acc[j][p] = 0ULL;

        for (int c = 0; c < NCH; c++) {
            long nt = t; int nc = c + 1;
            if (nc == NCH) { nt = t + gridDim.x; nc = 0; }
            bool hn = nt < ntiles;
            __syncthreads();
            if (hn) stage(nt, nc, b ^ 1);
            if (hn) cp_wait1(); else cp_wait0();
            __syncthreads();

            const float* Xb = sX + b * (128 * PC);
            const float* xr[EPT];
#pragma unroll
            for (int j = 0; j < EPT; j++) xr[j] = Xb + (eg + EGN * j) * PC;

#pragma unroll 2
            for (int k4 = 0; k4 < KC; k4 += 4) {
                float4 xv[EPT];
#pragma unroll
                for (int j = 0; j < EPT; j++)
                    xv[j] = *(const float4*)(xr[j] + k4);
#pragma unroll
                for (int kk = 0; kk < 4; kk++) {
                    const float* wr = sW + (c * KC + k4 + kk) * OUT + og * OPO;
                    ULL wv[NP];
#pragma unroll
                    for (int p = 0; p < NP; p++)
                        wv[p] = *(const ULL*)(wr + 2 * p);
#pragma unroll
                    for (int j = 0; j < EPT; j++) {
                        float xs = (kk == 0) ? xv[j].x : (kk == 1) ? xv[j].y
                                 : (kk == 2) ? xv[j].z : xv[j].w;
                        ULL xd = pack2(xs);
#pragma unroll
                        for (int p = 0; p < NP; p++)
                            acc[j][p] = fma2(xd, wv[p], acc[j][p]);
                    }
                }
            }
            b ^= 1;
        }

#pragma unroll
        for (int j = 0; j < EPT; j++) {
            long e = t * 128 + eg + EGN * j;
            float r[OPO];
#pragma unroll
            for (int p = 0; p < NP; p++) {
                union { ULL u; float2 f; } cv; cv.u = acc[j][p];
                r[2 * p] = cv.f.x; r[2 * p + 1] = cv.f.y;
            }
            op.epi(e, og, r);
        }
    }
}

// ---------------------------------------------------------------------------
// Streaming GEMM, 256 threads, BM=64, 2 CTAs/SM  (128-K kernels)
// CTA phases interleave: one CTA computes while the other stages/syncs.
// ---------------------------------------------------------------------------
template <int KTOT, int KC, int OUT, int OPO, class Op>
__global__ void __launch_bounds__(256, 2) gk2(Op op, const float* __restrict__ Wg,
                                              int ntiles)
{
    constexpr int PC  = KC + 4;
    constexpr int NCH = KTOT / KC;
    constexpr int OG  = OUT / OPO;
    constexpr int OGW = OG / 4;
    constexpr int EGN = 256 / OG;          // 16
    constexpr int EPT = 64 / EGN;          // 4
    constexpr int NP  = OPO / 2;

    extern __shared__ __align__(16) float sh[];
    float* sW = sh;
    float* sX = sh + KTOT * OUT;

    int tid = threadIdx.x;
    for (int i = tid; i < KTOT * OUT / 4; i += 256)
        ((float4*)sW)[i] = ((const float4*)Wg)[i];

    int lane = tid & 31, w = tid >> 5;
    int og = (w & (OGW - 1)) * 4 + (lane & 3);
    int eg = (w / OGW) * 8 + (lane >> 2);

    auto stage = [&](long t, int c, int b) {
        float* dst = sX + b * (64 * PC);
        constexpr int UN = 64 * (KC / 4);
        for (int i = tid; i < UN; i += 256) {
            int e_l = i / (KC / 4);
            int ks  = (i % (KC / 4)) * 4;
            cpa16(dst + e_l * PC + ks, op.src(t * 64 + e_l, c * KC + ks));
        }
        cp_commit();
    };

    long t0 = blockIdx.x;
    if (t0 < ntiles) stage(t0, 0, 0);
    int b = 0;

    for (long t = t0; t < ntiles; t += gridDim.x) {
        ULL acc[EPT][NP];
#pragma unroll
        for (int j = 0; j < EPT; j++)
#pragma unroll
            for (int p = 0; p < NP; p++) acc[j][p] = 0ULL;

        for (int c = 0; c < NCH; c++) {
            long nt = t; int nc = c + 1;
            if (nc == NCH) { nt = t + gridDim.x; nc = 0; }
            bool hn = nt < ntiles;
            __syncthreads();
            if (hn) stage(nt, nc, b ^ 1);
            if (hn) cp_wait1(); else cp_wait0();
            __syncthreads();

            const float* Xb = sX + b * (64 * PC);
            const float* xr[EPT];
#pragma unroll
            for (int j = 0; j < EPT; j++) xr[j] = Xb + (eg + EGN * j) * PC;

#pragma unroll 2
            for (int k4 = 0; k4 < KC; k4 += 4) {
                float4 xv[EPT];
#pragma unroll
                for (int j = 0; j < EPT; j++)
                    xv[j] = *(const float4*)(xr[j] + k4);
#pragma unroll
                for (int kk = 0; kk < 4; kk++) {
                    const float* wr = sW + (c * KC + k4 + kk) * OUT + og * OPO;
                    ULL wv[NP];
#pragma unroll
                    for (int p = 0; p < NP; p++)
                        wv[p] = *(const ULL*)(wr + 2 * p);
#pragma unroll
                    for (int j = 0; j < EPT; j++) {
                        float xs = (kk == 0) ? xv[j].x : (kk == 1) ? xv[j].y
                                 : (kk == 2) ? xv[j].z : xv[j].w;
                        ULL xd = pack2(xs);
#pragma unroll
                        for (int p = 0; p < NP; p++)
                            acc[j][p] = fma2(xd, wv[p], acc[j][p]);
                    }
                }
            }
            b ^= 1;
        }

#pragma unroll
        for (int j = 0; j < EPT; j++) {
            long e = t * 64 + eg + EGN * j;
            float r[OPO];
#pragma unroll
            for (int p = 0; p < NP; p++) {
                union { ULL u; float2 f; } cv; cv.u = acc[j][p];
                r[2 * p] = cv.f.x; r[2 * p + 1] = cv.f.y;
            }
            op.epi(e, og, r);
        }
    }
}

// ---------------------------------------------------------------------------
// Epilogue / source policies
// ---------------------------------------------------------------------------
struct OpG4 {   // lat -> w_all(128): outs 0-63 wedge, 64-127 env scatter
    const int* ctr;
    __device__ const float* src(long e, int k) const { return g_lat + e * 128 + k; }
    __device__ void epi(long e, int og, const float* r) const {
        if (og < 8) {
            *(float4*)(g_wedge + e * 64 + og * 8) =
                make_float4(r[0] * F_RS128, r[1] * F_RS128, r[2] * F_RS128, r[3] * F_RS128);
            *(float4*)(g_wedge + e * 64 + og * 8 + 4) =
                make_float4(r[4] * F_RS128, r[5] * F_RS128, r[6] * F_RS128, r[7] * F_RS128);
        } else {
            long c = ctr[e];
            float4 Y = *(const float4*)(g_Y + e * 4);
#pragma unroll
            for (int p = 0; p < 4; p++) {
                int m = (og - 8) * 4 + p;
                float w0 = r[2 * p] * F_RS128, w1 = r[2 * p + 1] * F_RS128;
                red4(g_env + c * 128 + 4 * m, w0, w1 * Y.y, w1 * Y.z, w1 * Y.w);
            }
        }
    }
};
struct OpG5 {   // scal0(64) -> smix(32)
    __device__ const float* src(long e, int k) const { return g_scal0 + e * 64 + k; }
    __device__ void epi(long e, int og, const float* r) const {
        *(float4*)(g_smix + e * 32 + og * 4) =
            make_float4(r[0] * F_RS64, r[1] * F_RS64, r[2] * F_RS64, r[3] * F_RS64);
    }
};
struct OpG6 {   // P(3E,96) -> vmx(3E,32)
    __device__ const float* src(long e, int k) const { return g_P + e * 96 + k; }
    __device__ void epi(long e, int og, const float* r) const {
        *(float4*)(g_vmx + e * 32 + og * 4) =
            make_float4(r[0] * F_RS96, r[1] * F_RS96, r[2] * F_RS96, r[3] * F_RS96);
    }
};
struct OpG7 {   // [lat|scal0](192) -> silu -> H(128)
    __device__ const float* src(long e, int k) const {
        return (k < 128) ? (g_lat + e * 128 + k) : (g_scal0 + e * 64 + (k - 128));
    }
    __device__ void epi(long e, int og, const float* r) const {
        *(float4*)(g_H + e * 128 + og * 8) =
            make_float4(silu_f(r[0] * F_RS192), silu_f(r[1] * F_RS192),
                        silu_f(r[2] * F_RS192), silu_f(r[3] * F_RS192));
        *(float4*)(g_H + e * 128 + og * 8 + 4) =
            make_float4(silu_f(r[4] * F_RS192), silu_f(r[5] * F_RS192),
                        silu_f(r[6] * F_RS192), silu_f(r[7] * F_RS192));
    }
};
struct OpG8 {   // H(128) -> *fcut, residual -> lat
    __device__ const float* src(long e, int k) const { return g_H + e * 128 + k; }
    __device__ void epi(long e, int og, const float* r) const {
        float s = F_C_NEW * F_RS128 * g_fcut[e];
        float4 l0 = *(const float4*)(g_lat + e * 128 + og * 8);
        float4 l1 = *(const float4*)(g_lat + e * 128 + og * 8 + 4);
        *(float4*)(g_lat + e * 128 + og * 8) =
            make_float4(F_C_OLD * l0.x + s * r[0], F_C_OLD * l0.y + s * r[1],
                        F_C_OLD * l0.z + s * r[2], F_C_OLD * l0.w + s * r[3]);
        *(float4*)(g_lat + e * 128 + og * 8 + 4) =
            make_float4(F_C_OLD * l1.x + s * r[4], F_C_OLD * l1.y + s * r[5],
                        F_C_OLD * l1.z + s * r[6], F_C_OLD * l1.w + s * r[7]);
    }
};
struct OpG9 {   // lat -> w_env1(64) -> env1 scatter
    const int* ctr;
    __device__ const float* src(long e, int k) const { return g_lat + e * 128 + k; }
    __device__ void epi(long e, int og, const float* r) const {
        long c = ctr[e];
        float4 Y = *(const float4*)(g_Y + e * 4);
        int m0 = og * 2;
        float w0 = r[0] * F_RS128, w1 = r[1] * F_RS128;
        red4(g_env1 + c * 128 + 4 * m0, w0, w1 * Y.y, w1 * Y.z, w1 * Y.w);
        float w2 = r[2] * F_RS128, w3 = r[3] * F_RS128;
        red4(g_env1 + c * 128 + 4 * (m0 + 1), w2, w3 * Y.y, w3 * Y.z, w3 * Y.w);
    }
};
struct OpG10 {  // [lat|q](192) -> silu -> H(128)
    __device__ const float* src(long e, int k) const {
        return (k < 128) ? (g_lat + e * 128 + k) : (g_q + e * 64 + (k - 128));
    }
    __device__ void epi(long e, int og, const float* r) const {
        *(float4*)(g_H + e * 128 + og * 8) =
            make_float4(silu_f(r[0] * F_RS192), silu_f(r[1] * F_RS192),
                        silu_f(r[2] * F_RS192), silu_f(r[3] * F_RS192));
        *(float4*)(g_H + e * 128 + og * 8 + 4) =
            make_float4(silu_f(r[4] * F_RS192), silu_f(r[5] * F_RS192),
                        silu_f(r[6] * F_RS192), silu_f(r[7] * F_RS192));
    }
};
struct OpG11 {  // H(128) -> *fcut, residual, *isn -> node scatter
    const int* ctr;
    float* out;
    __device__ const float* src(long e, int k) const { return g_H + e * 128 + k; }
    __device__ void epi(long e, int og, const float* r) const {
        long c = ctr[e];
        float s = F_C_NEW * F_RS128 * g_fcut[e];
        float4 l0 = *(const float4*)(g_lat + e * 128 + og * 8);
        float4 l1 = *(const float4*)(g_lat + e * 128 + og * 8 + 4);
        red4(out + c * 128 + og * 8,
             (F_C_OLD * l0.x + s * r[0]) * F_ISN, (F_C_OLD * l0.y + s * r[1]) * F_ISN,
             (F_C_OLD * l0.z + s * r[2]) * F_ISN, (F_C_OLD * l0.w + s * r[3]) * F_ISN);
        red4(out + c * 128 + og * 8 + 4,
             (F_C_OLD * l1.x + s * r[4]) * F_ISN, (F_C_OLD * l1.y + s * r[5]) * F_ISN,
             (F_C_OLD * l1.z + s * r[6]) * F_ISN, (F_C_OLD * l1.w + s * r[7]) * F_ISN);
    }
};

// ---------------------------------------------------------------------------
// k123: fused X0(40) -> silu(64) -> silu(128) -> *fcut*rs128 -> g_lat
// (identical to R9)
// ---------------------------------------------------------------------------
__global__ void __launch_bounds__(512, 1) k123(
    const float* __restrict__ W0g, const float* __restrict__ W1g,
    const float* __restrict__ W2g, int ntiles)
{
    extern __shared__ __align__(16) float sh[];
    float* sW0 = sh;                    // 2560
    float* sW1 = sh + 2560;             // 8192
    float* sW2 = sh + 10752;            // 16384
    float* sX  = sh + 27136;            // 2*5632
    float* sHU = sh + 38400;            // 16896 union

    int tid = threadIdx.x;
    for (int i = tid; i < 2560 / 4;  i += 512) ((float4*)sW0)[i] = ((const float4*)W0g)[i];
    for (int i = tid; i < 8192 / 4;  i += 512) ((float4*)sW1)[i] = ((const float4*)W1g)[i];
    for (int i = tid; i < 16384 / 4; i += 512) ((float4*)sW2)[i] = ((const float4*)W2g)[i];

    int lane = tid & 31, w = tid >> 5;
    int og = (w & 3) * 4 + (lane & 3);      // 0..15
    int eg = (w >> 2) * 8 + (lane >> 2);    // 0..31

    auto stage = [&](long t, int b) {
        float* dst = sX + b * 5632;
        for (int i = tid; i < 1280; i += 512) {
            int e_l = i / 10, ks = (i % 10) * 4;
            cpa16(dst + e_l * 44 + ks, g_X0 + (t * 128 + e_l) * 40 + ks);
        }
        cp_commit();
    };

    long t0 = blockIdx.x;
    if (t0 < ntiles) stage(t0, 0);
    int b = 0;

    for (long t = t0; t < ntiles; t += gridDim.x) {
        long nt = t + gridDim.x;
        bool hn = nt < ntiles;
        __syncthreads();
        if (hn) stage(nt, b ^ 1);
        if (hn) cp_wait1(); else cp_wait0();
        __syncthreads();

        // GEMM1: K=40 -> 64 (OPO=4) -> H1 (pitch 68)
        {
            const float* Xb = sX + b * 5632;
            ULL acc[4][2];
#pragma unroll
            for (int j = 0; j < 4; j++) { acc[j][0] = 0ULL; acc[j][1] = 0ULL; }
            const float* xr[4];
#pragma unroll
            for (int j = 0; j < 4; j++) xr[j] = Xb + (eg + 32 * j) * 44;
#pragma unroll 2
            for (int k4 = 0; k4 < 40; k4 += 4) {
                float4 xv[4];
#pragma unroll
                for (int j = 0; j < 4; j++) xv[j] = *(const float4*)(xr[j] + k4);
#pragma unroll
                for (int kk = 0; kk < 4; kk++) {
                    const float* wr = sW0 + (k4 + kk) * 64 + og * 4;
                    ULL w0 = *(const ULL*)wr, w1 = *(const ULL*)(wr + 2);
#pragma unroll
                    for (int j = 0; j < 4; j++) {
                        float xs = (kk == 0) ? xv[j].x : (kk == 1) ? xv[j].y
                                 : (kk == 2) ? xv[j].z : xv[j].w;
                        ULL xd = pack2(xs);
                        acc[j][0] = fma2(xd, w0, acc[j][0]);
                        acc[j][1] = fma2(xd, w1, acc[j][1]);
                    }
                }
            }
#pragma unroll
            for (int j = 0; j < 4; j++) {
                union { ULL u; float2 f; } c0, c1;
                c0.u = acc[j][0]; c1.u = acc[j][1];
                *(float4*)(sHU + (eg + 32 * j) * 68 + og * 4) =
                    make_float4(silu_f(c0.f.x * F_RS40), silu_f(c0.f.y * F_RS40),
                                silu_f(c1.f.x * F_RS40), silu_f(c1.f.y * F_RS40));
            }
        }
        __syncthreads();

        // GEMM2: K=64 read H1 (pitch 68) -> regs; sync; store H2 (pitch 132)
        {
            ULL acc[4][4];
#pragma unroll
            for (int j = 0; j < 4; j++)
#pragma unroll
                for (int p = 0; p < 4; p++) acc[j][p] = 0ULL;
            const float* xr[4];
#pragma unroll
            for (int j = 0; j < 4; j++) xr[j] = sHU + (eg + 32 * j) * 68;
#pragma unroll 2
            for (int k4 = 0; k4 < 64; k4 += 4) {
                float4 xv[4];
#pragma unroll
                for (int j = 0; j < 4; j++) xv[j] = *(const float4*)(xr[j] + k4);
#pragma unroll
                for (int kk = 0; kk < 4; kk++) {
                    const float* wr = sW1 + (k4 + kk) * 128 + og * 8;
                    ulonglong2 wa = *(const ulonglong2*)wr;
                    ulonglong2 wb = *(const ulonglong2*)(wr + 4);
#pragma unroll
                    for (int j = 0; j < 4; j++) {
                        float xs = (kk == 0) ? xv[j].x : (kk == 1) ? xv[j].y
                                 : (kk == 2) ? xv[j].z : xv[j].w;
                        ULL xd = pack2(xs);
                        acc[j][0] = fma2(xd, wa.x, acc[j][0]);
                        acc[j][1] = fma2(xd, wa.y, acc[j][1]);
                        acc[j][2] = fma2(xd, wb.x, acc[j][2]);
                        acc[j][3] = fma2(xd, wb.y, acc[j][3]);
                    }
                }
            }
            __syncthreads();   // ALL H1 reads complete before H2 overwrites
#pragma unroll
            for (int j = 0; j < 4; j++) {
                float* hr = sHU + (eg + 32 * j) * 132 + og * 8;
                union { ULL u; float2 f; } c0, c1, c2, c3;
                c0.u = acc[j][0]; c1.u = acc[j][1]; c2.u = acc[j][2]; c3.u = acc[j][3];
                *(float4*)hr =
                    make_float4(silu_f(c0.f.x * F_RS64), silu_f(c0.f.y * F_RS64),
                                silu_f(c1.f.x * F_RS64), silu_f(c1.f.y * F_RS64));
                *(float4*)(hr + 4) =
                    make_float4(silu_f(c2.f.x * F_RS64), silu_f(c2.f.y * F_RS64),
                                silu_f(c3.f.x * F_RS64), silu_f(c3.f.y * F_RS64));
            }
        }
        __syncthreads();

        // GEMM3: K=128 read H2 (pitch 132) -> *fcut -> g_lat
        {
            ULL acc[4][4];
#pragma unroll
            for (int j = 0; j < 4; j++)
#pragma unroll
                for (int p = 0; p < 4; p++) acc[j][p] = 0ULL;
            const float* xr[4];
#pragma unroll
            for (int j = 0; j < 4; j++) xr[j] = sHU + (eg + 32 * j) * 132;
#pragma unroll 2
            for (int k4 = 0; k4 < 128; k4 += 4) {
                float4 xv[4];
#pragma unroll
                for (int j = 0; j < 4; j++) xv[j] = *(const float4*)(xr[j] + k4);
#pragma unroll
                for (int kk = 0; kk < 4; kk++) {
                    const float* wr = sW2 + (k4 + kk) * 128 + og * 8;
                    ulonglong2 wa = *(const ulonglong2*)wr;
                    ulonglong2 wb = *(const ulonglong2*)(wr + 4);
#pragma unroll
                    for (int j = 0; j < 4; j++) {
                        float xs = (kk == 0) ? xv[j].x : (kk == 1) ? xv[j].y
                                 : (kk == 2) ? xv[j].z : xv[j].w;
                        ULL xd = pack2(xs);
                        acc[j][0] = fma2(xd, wa.x, acc[j][0]);
                        acc[j][1] = fma2(xd, wa.y, acc[j][1]);
                        acc[j][2] = fma2(xd, wb.x, acc[j][2]);
                        acc[j][3] = fma2(xd, wb.y, acc[j][3]);
                    }
                }
            }
#pragma unroll
            for (int j = 0; j < 4; j++) {
                long e = t * 128 + eg + 32 * j;
                float s = F_RS128 * g_fcut[e];
                union { ULL u; float2 f; } c0, c1, c2, c3;
                c0.u = acc[j][0]; c1.u = acc[j][1]; c2.u = acc[j][2]; c3.u = acc[j][3];
                *(float4*)(g_lat + e * 128 + og * 8) =
                    make_float4(c0.f.x * s, c0.f.y * s, c1.f.x * s, c1.f.y * s);
                *(float4*)(g_lat + e * 128 + og * 8 + 4) =
                    make_float4(c2.f.x * s, c2.f.y * s, c3.f.x * s, c3.f.y * s);
            }
        }
        b ^= 1;
    }
}

// ---------------------------------------------------------------------------
__global__ void k_zero(float* __restrict__ out)
{
    int i = blockIdx.x * blockDim.x + threadIdx.x;
    int stride = gridDim.x * blockDim.x;
    for (; i < NN * 128; i += stride) {
        g_env[i]  = 0.0f;
        g_env1[i] = 0.0f;
        out[i]    = 0.0f;
    }
}

__global__ void __launch_bounds__(512) kgeo(
    const float* __restrict__ coords, const float* __restrict__ attrs,
    const int* __restrict__ eidx)
{
    int e = blockIdx.x * 512 + threadIdx.x;
    if (e >= NE) return;
    int snd = eidx[e];
    int c   = eidx[NE + e];
    float dx = coords[c * 3 + 0] - coords[snd * 3 + 0];
    float dy = coords[c * 3 + 1] - coords[snd * 3 + 1];
    float dz = coords[c * 3 + 2] - coords[snd * 3 + 2];
    float r2 = dx * dx + dy * dy + dz * dz + 1e-12f;
    float r  = sqrtf(r2);
    float inv_r = 1.0f / r;
    float u  = r * F_INV_RMAX;
    float u2 = u * u, u3 = u2 * u, u6 = u3 * u3, u7 = u6 * u, u8 = u7 * u;
    float f  = 1.0f - 28.0f * u6 + 48.0f * u7 - 21.0f * u8;
    if (u >= 1.0f) f = 0.0f;
    g_fcut[e] = f;
    *(float4*)(g_Y + e * 4) = make_float4(1.0f, F_SQRT3 * dx * inv_r,
                                          F_SQRT3 * dy * inv_r, F_SQRT3 * dz * inv_r);
    float* X = g_X0 + (long)e * 40;
    const float4* ac = (const float4*)(attrs + c * 16);
    const float4* as = (const float4*)(attrs + snd * 16);
#pragma unroll
    for (int i = 0; i < 4; i++) ((float4*)X)[i] = ac[i];
#pragma unroll
    for (int i = 0; i < 4; i++) ((float4*)(X + 16))[i] = as[i];
    float bi = inv_r * f * F_BESSEL;
#pragma unroll
    for (int n = 0; n < 8; n++)
        X[32 + n] = bi * sinf((n + 1) * F_PI * u);
}

// kp1: products -> scal0 + P rows (warp per edge, lane = m)
__global__ void __launch_bounds__(256) kp1(const int* __restrict__ eidx)
{
    int warp = (blockIdx.x * 256 + threadIdx.x) >> 5;
    int lane = threadIdx.x & 31;
    int nw = gridDim.x * 8;
    for (long e = warp; e < NE; e += nw) {
        long c = eidx[NE + e];
        float2 we = *(const float2*)(g_wedge + e * 64 + 2 * lane);
        float4 en = *(const float4*)(g_env + c * 128 + 4 * lane);
        float4 Y  = *(const float4*)(g_Y + e * 4);
        float fs  = we.x;
        float fv0 = we.y * Y.y, fv1 = we.y * Y.z, fv2 = we.y * Y.w;
        float es  = en.x * F_ISN;
        float ev0 = en.y * F_ISN, ev1 = en.z * F_ISN, ev2 = en.w * F_ISN;
        g_scal0[e * 64 + lane]      = fs * es;
        g_scal0[e * 64 + 32 + lane] = (fv0 * ev0 + fv1 * ev1 + fv2 * ev2) * F_INV_SQRT3;
        float* P0 = g_P + (3 * e + 0) * 96;
        float* P1 = g_P + (3 * e + 1) * 96;
        float* P2 = g_P + (3 * e + 2) * 96;
        P0[lane] = fs * ev0;  P1[lane] = fs * ev1;  P2[lane] = fs * ev2;
        P0[32 + lane] = fv0 * es; P1[32 + lane] = fv1 * es; P2[32 + lane] = fv2 * es;
        P0[64 + lane] = (fv1 * ev2 - fv2 * ev1) * F_INV_SQRT2;
        P1[64 + lane] = (fv2 * ev0 - fv0 * ev2) * F_INV_SQRT2;
        P2[64 + lane] = (fv0 * ev1 - fv1 * ev0) * F_INV_SQRT2;
    }
}

// kp2: q0/q1 (warp per edge, lane = m)
__global__ void __launch_bounds__(256) kp2(const int* __restrict__ eidx)
{
    int warp = (blockIdx.x * 256 + threadIdx.x) >> 5;
    int lane = threadIdx.x & 31;
    int nw = gridDim.x * 8;
    for (long e = warp; e < NE; e += nw) {
        long c = eidx[NE + e];
        float4 e1 = *(const float4*)(g_env1 + c * 128 + 4 * lane);
        float sm = g_smix[e * 32 + lane];
        float v0 = g_vmx[(3 * e + 0) * 32 + lane];
        float v1 = g_vmx[(3 * e + 1) * 32 + lane];
        float v2 = g_vmx[(3 * e + 2) * 32 + lane];
        g_q[e * 64 + lane] = sm * e1.x * F_ISN;
        g_q[e * 64 + 32 + lane] =
            (v0 * e1.y + v1 * e1.z + v2 * e1.w) * F_ISN * F_INV_SQRT3;
    }
}

// ---------------------------------------------------------------------------
extern "C" void kernel_launch(void* const* d_in, const int* in_sizes, int n_in,
                              void* d_out, int out_size)
{
    const float* coords = (const float*)d_in[0];
    const float* attrs  = (const float*)d_in[1];
    const int*   eidx   = (const int*)  d_in[2];
    const float* W2b0   = (const float*)d_in[3];
    const float* W2b1   = (const float*)d_in[4];
    const float* W2b2   = (const float*)d_in[5];
    const float* Wenv0  = (const float*)d_in[6];
    const float* Wlat0  = (const float*)d_in[7];
    const float* Wlat1  = (const float*)d_in[8];
    const float* Ws0    = (const float*)d_in[9];
    const float* Wv0    = (const float*)d_in[10];
    const float* Wenv1  = (const float*)d_in[11];
    const float* Wfin0  = (const float*)d_in[12];
    const float* Wfin1  = (const float*)d_in[13];
    float* out = (float*)d_out;
    const int* ctr = eidx + NE;

    const size_t sm_k123   = (2560 + 8192 + 16384 + 11264 + 16896) * 4;  // 221184
    const size_t sm2_128   = (16384 + 2 * 64 * 68) * 4;                  // 100352 /CTA
    const size_t sm2_64    = (8192  + 2 * 64 * 68) * 4;                  //  67584 /CTA
    const size_t sm64_32   = (2048 + 2 * 128 * 68) * 4;                  //  77824
    const size_t sm96_32   = (3072 + 2 * 128 * 100) * 4;                 // 114688
    const size_t sm192_128 = (24576 + 2 * 128 * 100) * 4;                // 200704

    cudaFuncSetAttribute(k123, cudaFuncAttributeMaxDynamicSharedMemorySize, (int)sm_k123);
    cudaFuncSetAttribute(gk2<128, 64, 128, 8, OpG4>,  cudaFuncAttributeMaxDynamicSharedMemorySize, (int)sm2_128);
    cudaFuncSetAttribute(gk<64, 64, 32, 4, OpG5>,     cudaFuncAttributeMaxDynamicSharedMemorySize, (int)sm64_32);
    cudaFuncSetAttribute(gk<96, 96, 32, 4, OpG6>,     cudaFuncAttributeMaxDynamicSharedMemorySize, (int)sm96_32);
    cudaFuncSetAttribute(gk<192, 96, 128, 8, OpG7>,   cudaFuncAttributeMaxDynamicSharedMemorySize, (int)sm192_128);
    cudaFuncSetAttribute(gk2<128, 64, 128, 8, OpG8>,  cudaFuncAttributeMaxDynamicSharedMemorySize, (int)sm2_128);
    cudaFuncSetAttribute(gk2<128, 64, 64, 4, OpG9>,   cudaFuncAttributeMaxDynamicSharedMemorySize, (int)sm2_64);
    cudaFuncSetAttribute(gk<192, 96, 128, 8, OpG10>,  cudaFuncAttributeMaxDynamicSharedMemorySize, (int)sm192_128);
    cudaFuncSetAttribute(gk2<128, 64, 128, 8, OpG11>, cudaFuncAttributeMaxDynamicSharedMemorySize, (int)sm2_128);

    const int NT   = NE / 128;   // 2500
    const int NT64 = NE / 64;    // 5000
    const int NT3  = NE3 / 128;  // 7500

    k_zero<<<512, 256>>>(out);
    kgeo<<<(NE + 511) / 512, 512>>>(coords, attrs, eidx);

    k123<<<148, 512, sm_k123>>>(W2b0, W2b1, W2b2, NT);
    gk2<128, 64, 128, 8, OpG4><<<296, 256, sm2_128>>>(OpG4{ctr}, Wenv0, NT64);
    kp1<<<2560, 256>>>(eidx);
    gk<64, 64, 32, 4, OpG5><<<148, 512, sm64_32>>>(OpG5{}, Ws0, NT);
    gk<96, 96, 32, 4, OpG6><<<148, 512, sm96_32>>>(OpG6{}, Wv0, NT3);
    gk<192, 96, 128, 8, OpG7><<<148, 512, sm192_128>>>(OpG7{}, Wlat0, NT);
    gk2<128, 64, 128, 8, OpG8><<<296, 256, sm2_128>>>(OpG8{}, Wlat1, NT64);
    gk2<128, 64, 64, 4, OpG9><<<296, 256, sm2_64>>>(OpG9{ctr}, Wenv1, NT64);
    kp2<<<2560, 256>>>(eidx);
    gk<192, 96, 128, 8, OpG10><<<148, 512, sm192_128>>>(OpG10{}, Wfin0, NT);
    gk2<128, 64, 128, 8, OpG11><<<296, 256, sm2_128>>>(OpG11{ctr, out}, Wfin1, NT64);
}

// round 14
// speedup vs baseline: 1.5332x; 1.2052x over previous
#include <cuda_runtime.h>
#include <cuda_bf16.h>

// ---------------------------------------------------------------------------
// Allegro GNN layer.  tkm = warp-level mma.sync bf16-split (hi/lo, 3-pass)
// GEMM for the five big GEMMs (G4/G8/G11 K=128, G7/G10 K=192).
// Rest = proven R12 pipeline (gk/gk2 FFMA2, k123, kp1/kp2).
// ---------------------------------------------------------------------------

#define NN 10000
#define NE 320000
#define NE3 960000
typedef unsigned long long ULL;
typedef unsigned int U32;

__device__ float g_X0  [NE * 40];
__device__ float g_H   [NE * 128];
__device__ float g_lat [NE * 128];
__device__ float g_wedge[NE * 64];
__device__ float g_scal0[NE * 64];
__device__ float g_P   [(long)NE3 * 96];
__device__ float g_smix[NE * 32];
__device__ float g_vmx [NE3 * 32];
__device__ float g_q   [NE * 64];
__device__ float g_Y   [NE * 4];
__device__ float g_fcut[NE];
__device__ float g_env [NN * 128];
__device__ float g_env1[NN * 128];

#define F_RS40      0.15811388300841897f
#define F_RS64      0.125f
#define F_RS96      0.10206207261596575f
#define F_RS128     0.08838834764831845f
#define F_RS192     0.07216878364870323f
#define F_ISN       0.17677669529663689f
#define F_SQRT3     1.7320508075688772f
#define F_INV_SQRT3 0.5773502691896258f
#define F_INV_SQRT2 0.7071067811865476f
#define F_C_OLD     0.8944271909999159f
#define F_C_NEW     0.4472135954999579f
#define F_BESSEL    0.6324555320336759f
#define F_PI        3.14159265358979323846f
#define F_INV_RMAX  0.2f

__device__ __forceinline__ ULL fma2(ULL a, ULL b, ULL c) {
    ULL d;
    asm("fma.rn.f32x2 %0, %1, %2, %3;" : "=l"(d) : "l"(a), "l"(b), "l"(c));
    return d;
}
__device__ __forceinline__ ULL pack2(float x) {
    ULL d; unsigned u = __float_as_uint(x);
    asm("mov.b64 %0, {%1,%1};" : "=l"(d) : "r"(u));
    return d;
}
__device__ __forceinline__ void red4(float* p, float a, float b, float c, float d) {
    asm volatile("red.global.add.v4.f32 [%0], {%1,%2,%3,%4};"
                 :: "l"(p), "f"(a), "f"(b), "f"(c), "f"(d) : "memory");
}
__device__ __forceinline__ void red2(float* p, float a, float b) {
    asm volatile("red.global.add.v2.f32 [%0], {%1,%2};"
                 :: "l"(p), "f"(a), "f"(b) : "memory");
}
__device__ __forceinline__ float silu_f(float v) {
    return v * __frcp_rn(1.0f + __expf(-v));
}
__device__ __forceinline__ void cpa16(const void* s, const void* g) {
    unsigned sa = (unsigned)__cvta_generic_to_shared(s);
    asm volatile("cp.async.cg.shared.global [%0], [%1], 16;" :: "r"(sa), "l"(g));
}
__device__ __forceinline__ void cp_commit() { asm volatile("cp.async.commit_group;"); }
__device__ __forceinline__ void cp_wait1()  { asm volatile("cp.async.wait_group 1;"); }
__device__ __forceinline__ void cp_wait0()  { asm volatile("cp.async.wait_group 0;"); }

__device__ __forceinline__ void mma16816(float* d, const U32* a, const U32* b) {
    asm volatile(
        "mma.sync.aligned.m16n8k16.row.col.f32.bf16.bf16.f32 "
        "{%0,%1,%2,%3}, {%4,%5,%6,%7}, {%8,%9}, {%0,%1,%2,%3};"
        : "+f"(d[0]), "+f"(d[1]), "+f"(d[2]), "+f"(d[3])
        : "r"(a[0]), "r"(a[1]), "r"(a[2]), "r"(a[3]), "r"(b[0]), "r"(b[1]));
}
__device__ __forceinline__ void bsplit8(const float* xs, uint4& hi, uint4& lo) {
    unsigned h[4], l[4];
#pragma unroll
    for (int p = 0; p < 4; p++) {
        __nv_bfloat16 h0 = __float2bfloat16(xs[2 * p]);
        __nv_bfloat16 h1 = __float2bfloat16(xs[2 * p + 1]);
        __nv_bfloat16 l0 = __float2bfloat16(xs[2 * p] - __bfloat162float(h0));
        __nv_bfloat16 l1 = __float2bfloat16(xs[2 * p + 1] - __bfloat162float(h1));
        h[p] = (unsigned)__bfloat16_as_ushort(h0) |
               ((unsigned)__bfloat16_as_ushort(h1) << 16);
        l[p] = (unsigned)__bfloat16_as_ushort(l0) |
               ((unsigned)__bfloat16_as_ushort(l1) << 16);
    }
    hi = make_uint4(h[0], h[1], h[2], h[3]);
    lo = make_uint4(l[0], l[1], l[2], l[3]);
}
// swizzled pair index: row-major [row][K/2 pairs], pair p XOR ((row&7)<<2)
__device__ __forceinline__ int pidx(int row, int p, int KH) {
    return row * KH + (p ^ ((row & 7) << 2));
}

// ---------------------------------------------------------------------------
// tkm: warp-level mma bf16-split GEMM.  BM=128, OUT=128, 512 thr, 16 warps.
// Warp (wm = w&3, wn = w>>2) owns rows [wm*32,+32) x cols [wn*32,+32).
// A/B in smem as bf16 hi/lo, swizzled pairs.  D = Ah*Bh + Ah*Bl + Al*Bh.
// ---------------------------------------------------------------------------
template <int K, class Op>
__global__ void __launch_bounds__(512, 1) tkm(Op op, const float* __restrict__ Wg,
                                              int ntiles)
{
    constexpr int KH = K / 2;    // pairs per row
    constexpr int KB = K / 8;    // 8-elem groups per row
    extern __shared__ __align__(16) U32 su[];
    U32* AH = su;                 // 128*KH
    U32* AL = AH + 128 * KH;
    U32* BH = AL + 128 * KH;
    U32* BL = BH + 128 * KH;

    int tid = threadIdx.x, lane = tid & 31, w = tid >> 5;
    int g = lane >> 2, tg = lane & 3;
    int wm = w & 3, wn = w >> 2;

    // B = W^T : Bs[n][k] = W[k][n], bf16 hi/lo
    for (int i = tid; i < 128 * KB; i += 512) {
        int n = i / KB, kb = (i % KB) * 8;
        float xs[8];
#pragma unroll
        for (int j = 0; j < 8; j++) xs[j] = Wg[(kb + j) * 128 + n];
        uint4 hi, lo; bsplit8(xs, hi, lo);
        int p4 = ((kb >> 1) ^ ((n & 7) << 2));
        *(uint4*)&BH[n * KH + p4] = hi;
        *(uint4*)&BL[n * KH + p4] = lo;
    }
    __syncthreads();

    for (long t = blockIdx.x; t < ntiles; t += gridDim.x) {
        // stage A: rows = edges, bf16 hi/lo
        for (int i = tid; i < 128 * KB; i += 512) {
            int m = i / KB, kb = (i % KB) * 8;
            const float* s = op.src(t * 128 + m, kb);
            float4 x0 = *(const float4*)s, x1 = *(const float4*)(s + 4);
            float xs[8] = {x0.x, x0.y, x0.z, x0.w, x1.x, x1.y, x1.z, x1.w};
            uint4 hi, lo; bsplit8(xs, hi, lo);
            int p4 = ((kb >> 1) ^ ((m & 7) << 2));
            *(uint4*)&AH[m * KH + p4] = hi;
            *(uint4*)&AL[m * KH + p4] = lo;
        }
        __syncthreads();

        float acc[2][4][4];
#pragma unroll
        for (int mt = 0; mt < 2; mt++)
#pragma unroll
            for (int nt = 0; nt < 4; nt++)
#pragma unroll
                for (int q = 0; q < 4; q++) acc[mt][nt][q] = 0.0f;

#pragma unroll 2
        for (int ks = 0; ks < K / 16; ks++) {
            int pb = ks * 8;
            U32 ah[2][4], al[2][4];
#pragma unroll
            for (int mt = 0; mt < 2; mt++) {
                int r0 = wm * 32 + mt * 16 + g;
                ah[mt][0] = AH[pidx(r0,     pb + tg,     KH)];
                ah[mt][1] = AH[pidx(r0 + 8, pb + tg,     KH)];
                ah[mt][2] = AH[pidx(r0,     pb + tg + 4, KH)];
                ah[mt][3] = AH[pidx(r0 + 8, pb + tg + 4, KH)];
                al[mt][0] = AL[pidx(r0,     pb + tg,     KH)];
                al[mt][1] = AL[pidx(r0 + 8, pb + tg,     KH)];
                al[mt][2] = AL[pidx(r0,     pb + tg + 4, KH)];
                al[mt][3] = AL[pidx(r0 + 8, pb + tg + 4, KH)];
            }
            U32 bh[4][2], bl[4][2];
#pragma unroll
            for (int nt = 0; nt < 4; nt++) {
                int n = wn * 32 + nt * 8 + g;
                bh[nt][0] = BH[pidx(n, pb + tg,     KH)];
                bh[nt][1] = BH[pidx(n, pb + tg + 4, KH)];
                bl[nt][0] = BL[pidx(n, pb + tg,     KH)];
                bl[nt][1] = BL[pidx(n, pb + tg + 4, KH)];
            }
#pragma unroll
            for (int mt = 0; mt < 2; mt++)
#pragma unroll
                for (int nt = 0; nt < 4; nt++) {
                    mma16816(acc[mt][nt], ah[mt], bh[nt]);
                    mma16816(acc[mt][nt], ah[mt], bl[nt]);
                    mma16816(acc[mt][nt], al[mt], bh[nt]);
                }
        }

#pragma unroll
        for (int mt = 0; mt < 2; mt++) {
            int r0 = wm * 32 + mt * 16 + g;
#pragma unroll
            for (int nt = 0; nt < 4; nt++) {
                int col = wn * 32 + nt * 8 + tg * 2;
                op.epi2(t * 128 + r0,     col, acc[mt][nt][0], acc[mt][nt][1]);
                op.epi2(t * 128 + r0 + 8, col, acc[mt][nt][2], acc[mt][nt][3]);
            }
        }
        __syncthreads();
    }
}

// ---------------------------------------------------------------------------
// Streaming FFMA2 GEMM, 512 threads (G5, G6)
// ---------------------------------------------------------------------------
template <int KTOT, int KC, int OUT, int OPO, class Op>
__global__ void __launch_bounds__(512, 1) gk(Op op, const float* __restrict__ Wg,
                                             int ntiles)
{
    constexpr int PC  = KC + 4;
    constexpr int NCH = KTOT / KC;
    constexpr int OG  = OUT / OPO;
    constexpr int OGW = OG / 4;
    constexpr int EGN = 512 / OG;
    constexpr int EPT = 128 / EGN;
    constexpr int NP  = OPO / 2;

    extern __shared__ __align__(16) float sh[];
    float* sW = sh;
    float* sX = sh + KTOT * OUT;

    int tid = threadIdx.x;
    for (int i = tid; i < KTOT * OUT / 4; i += 512)
        ((float4*)sW)[i] = ((const float4*)Wg)[i];

    int lane = tid & 31, w = tid >> 5;
    int og = (w & (OGW - 1)) * 4 + (lane & 3);
    int eg = (w / OGW) * 8 + (lane >> 2);

    auto stage = [&](long t, int c, int b) {
        float* dst = sX + b * (128 * PC);
        constexpr int UN = 128 * (KC / 4);
        for (int i = tid; i < UN; i += 512) {
            int e_l = i / (KC / 4);
            int ks  = (i % (KC / 4)) * 4;
            cpa16(dst + e_l * PC + ks, op.src(t * 128 + e_l, c * KC + ks));
        }
        cp_commit();
    };

    long t0 = blockIdx.x;
    if (t0 < ntiles) stage(t0, 0, 0);
    int b = 0;

    for (long t = t0; t < ntiles; t += gridDim.x) {
        ULL acc[EPT][NP];
#pragma unroll
        for (int j = 0; j < EPT; j++)
#pragma unroll
            for (int p = 0; p < NP; p++) acc[j][p] = 0ULL;

        for (int c = 0; c < NCH; c++) {
            long nt = t; int nc = c + 1;
            if (nc == NCH) { nt = t + gridDim.x; nc = 0; }
            bool hn = nt < ntiles;
            __syncthreads();
            if (hn) stage(nt, nc, b ^ 1);
            if (hn) cp_wait1(); else cp_wait0();
            __syncthreads();

            const float* Xb = sX + b * (128 * PC);
            const float* xr[EPT];
#pragma unroll
            for (int j = 0; j < EPT; j++) xr[j] = Xb + (eg + EGN * j) * PC;

#pragma unroll 2
            for (int k4 = 0; k4 < KC; k4 += 4) {
                float4 xv[EPT];
#pragma unroll
                for (int j = 0; j < EPT; j++)
                    xv[j] = *(const float4*)(xr[j] + k4);
#pragma unroll
                for (int kk = 0; kk < 4; kk++) {
                    const float* wr = sW + (c * KC + k4 + kk) * OUT + og * OPO;
                    ULL wv[NP];
#pragma unroll
                    for (int p = 0; p < NP; p++)
                        wv[p] = *(const ULL*)(wr + 2 * p);
#pragma unroll
                    for (int j = 0; j < EPT; j++) {
                        float xs = (kk == 0) ? xv[j].x : (kk == 1) ? xv[j].y
                                 : (kk == 2) ? xv[j].z : xv[j].w;
                        ULL xd = pack2(xs);
#pragma unroll
                        for (int p = 0; p < NP; p++)
                            acc[j][p] = fma2(xd, wv[p], acc[j][p]);
                    }
                }
            }
            b ^= 1;
        }

#pragma unroll
        for (int j = 0; j < EPT; j++) {
            long e = t * 128 + eg + EGN * j;
            float r[OPO];
#pragma unroll
            for (int p = 0; p < NP; p++) {
                union { ULL u; float2 f; } cv; cv.u = acc[j][p];
                r[2 * p] = cv.f.x; r[2 * p + 1] = cv.f.y;
            }
            op.epi(e, og, r);
        }
    }
}

// ---------------------------------------------------------------------------
// Streaming FFMA2 GEMM, 256 threads, 2 CTAs/SM (G9)
// ---------------------------------------------------------------------------
template <int KTOT, int KC, int OUT, int OPO, class Op>
__global__ void __launch_bounds__(256, 2) gk2(Op op, const float* __restrict__ Wg,
                                              int ntiles)
{
    constexpr int PC  = KC + 4;
    constexpr int NCH = KTOT / KC;
    constexpr int OG  = OUT / OPO;
    constexpr int OGW = OG / 4;
    constexpr int EGN = 256 / OG;
    constexpr int EPT = 64 / EGN;
    constexpr int NP  = OPO / 2;

    extern __shared__ __align__(16) float sh[];
    float* sW = sh;
    float* sX = sh + KTOT * OUT;

    int tid = threadIdx.x;
    for (int i = tid; i < KTOT * OUT / 4; i += 256)
        ((float4*)sW)[i] = ((const float4*)Wg)[i];

    int lane = tid & 31, w = tid >> 5;
    int og = (w & (OGW - 1)) * 4 + (lane & 3);
    int eg = (w / OGW) * 8 + (lane >> 2);

    auto stage = [&](long t, int c, int b) {
        float* dst = sX + b * (64 * PC);
        constexpr int UN = 64 * (KC / 4);
        for (int i = tid; i < UN; i += 256) {
            int e_l = i / (KC / 4);
            int ks  = (i % (KC / 4)) * 4;
            cpa16(dst + e_l * PC + ks, op.src(t * 64 + e_l, c * KC + ks));
        }
        cp_commit();
    };

    long t0 = blockIdx.x;
    if (t0 < ntiles) stage(t0, 0, 0);
    int b = 0;

    for (long t = t0; t < ntiles; t += gridDim.x) {
        ULL acc[EPT][NP];
#pragma unroll
        for (int j = 0; j < EPT; j++)
#pragma unroll
            for (int p = 0; p < NP; p++) acc[j][p] = 0ULL;

        for (int c = 0; c < NCH; c++) {
            long nt = t; int nc = c + 1;
            if (nc == NCH) { nt = t + gridDim.x; nc = 0; }
            bool hn = nt < ntiles;
            __syncthreads();
            if (hn) stage(nt, nc, b ^ 1);
            if (hn) cp_wait1(); else cp_wait0();
            __syncthreads();

            const float* Xb = sX + b * (64 * PC);
            const float* xr[EPT];
#pragma unroll
            for (int j = 0; j < EPT; j++) xr[j] = Xb + (eg + EGN * j) * PC;

#pragma unroll 2
            for (int k4 = 0; k4 < KC; k4 += 4) {
                float4 xv[EPT];
#pragma unroll
                for (int j = 0; j < EPT; j++)
                    xv[j] = *(const float4*)(xr[j] + k4);
#pragma unroll
                for (int kk = 0; kk < 4; kk++) {
                    const float* wr = sW + (c * KC + k4 + kk) * OUT + og * OPO;
                    ULL wv[NP];
#pragma unroll
                    for (int p = 0; p < NP; p++)
                        wv[p] = *(const ULL*)(wr + 2 * p);
#pragma unroll
                    for (int j = 0; j < EPT; j++) {
                        float xs = (kk == 0) ? xv[j].x : (kk == 1) ? xv[j].y
                                 : (kk == 2) ? xv[j].z : xv[j].w;
                        ULL xd = pack2(xs);
#pragma unroll
                        for (int p = 0; p < NP; p++)
                            acc[j][p] = fma2(xd, wv[p], acc[j][p]);
                    }
                }
            }
            b ^= 1;
        }

#pragma unroll
        for (int j = 0; j < EPT; j++) {
            long e = t * 64 + eg + EGN * j;
            float r[OPO];
#pragma unroll
            for (int p = 0; p < NP; p++) {
                union { ULL u; float2 f; } cv; cv.u = acc[j][p];
                r[2 * p] = cv.f.x; r[2 * p + 1] = cv.f.y;
            }
            op.epi(e, og, r);
        }
    }
}

// ---------------------------------------------------------------------------
// Epilogue / source policies.  tkm ops use src + epi2(e, col, v0, v1).
// ---------------------------------------------------------------------------
struct OpG4T {  // lat -> w_all: cols 0-63 wedge, 64-127 env scatter
    const int* ctr;
    __device__ const float* src(long e, int k) const { return g_lat + e * 128 + k; }
    __device__ void epi2(long e, int col, float v0, float v1) const {
        if (col < 64) {
            *(float2*)(g_wedge + e * 64 + col) =
                make_float2(v0 * F_RS128, v1 * F_RS128);
        } else {
            long c = ctr[e];
            float4 Y = *(const float4*)(g_Y + e * 4);
            int m = (col - 64) >> 1;
            float w0 = v0 * F_RS128, w1 = v1 * F_RS128;
            red4(g_env + c * 128 + 4 * m, w0, w1 * Y.y, w1 * Y.z, w1 * Y.w);
        }
    }
};
struct OpG7T {  // [lat|scal0](192) -> silu -> H
    __device__ const float* src(long e, int k) const {
        return (k < 128) ? (g_lat + e * 128 + k) : (g_scal0 + e * 64 + (k - 128));
    }
    __device__ void epi2(long e, int col, float v0, float v1) const {
        *(float2*)(g_H + e * 128 + col) =
            make_float2(silu_f(v0 * F_RS192), silu_f(v1 * F_RS192));
    }
};
struct OpG8T {  // H -> *fcut, residual -> lat
    __device__ const float* src(long e, int k) const { return g_H + e * 128 + k; }
    __device__ void epi2(long e, int col, float v0, float v1) const {
        float s = F_C_NEW * F_RS128 * g_fcut[e];
        float2 l = *(float2*)(g_lat + e * 128 + col);
        *(float2*)(g_lat + e * 128 + col) =
            make_float2(F_C_OLD * l.x + s * v0, F_C_OLD * l.y + s * v1);
    }
};
struct OpG10T { // [lat|q](192) -> silu -> H
    __device__ const float* src(long e, int k) const {
        return (k < 128) ? (g_lat + e * 128 + k) : (g_q + e * 64 + (k - 128));
    }
    __device__ void epi2(long e, int col, float v0, float v1) const {
        *(float2*)(g_H + e * 128 + col) =
            make_float2(silu_f(v0 * F_RS192), silu_f(v1 * F_RS192));
    }
};
struct OpG11T { // H -> *fcut, residual, *isn -> node scatter
    const int* ctr;
    float* out;
    __device__ const float* src(long e, int k) const { return g_H + e * 128 + k; }
    __device__ void epi2(long e, int col, float v0, float v1) const {
        long c = ctr[e];
        float s = F_C_NEW * F_RS128 * g_fcut[e];
        float2 l = *(const float2*)(g_lat + e * 128 + col);
        red2(out + c * 128 + col,
             (F_C_OLD * l.x + s * v0) * F_ISN,
             (F_C_OLD * l.y + s * v1) * F_ISN);
    }
};
struct OpG5 {
    __device__ const float* src(long e, int k) const { return g_scal0 + e * 64 + k; }
    __device__ void epi(long e, int og, const float* r) const {
        *(float4*)(g_smix + e * 32 + og * 4) =
            make_float4(r[0] * F_RS64, r[1] * F_RS64, r[2] * F_RS64, r[3] * F_RS64);
    }
};
struct OpG6 {
    __device__ const float* src(long e, int k) const { return g_P + e * 96 + k; }
    __device__ void epi(long e, int og, const float* r) const {
        *(float4*)(g_vmx + e * 32 + og * 4) =
            make_float4(r[0] * F_RS96, r[1] * F_RS96, r[2] * F_RS96, r[3] * F_RS96);
    }
};
struct OpG9 {
    const int* ctr;
    __device__ const float* src(long e, int k) const { return g_lat + e * 128 + k; }
    __device__ void epi(long e, int og, const float* r) const {
        long c = ctr[e];
        float4 Y = *(const float4*)(g_Y + e * 4);
        int m0 = og * 2;
        float w0 = r[0] * F_RS128, w1 = r[1] * F_RS128;
        red4(g_env1 + c * 128 + 4 * m0, w0, w1 * Y.y, w1 * Y.z, w1 * Y.w);
        float w2 = r[2] * F_RS128, w3 = r[3] * F_RS128;
        red4(g_env1 + c * 128 + 4 * (m0 + 1), w2, w3 * Y.y, w3 * Y.z, w3 * Y.w);
    }
};

// ---------------------------------------------------------------------------
// k123: fused X0(40) -> silu(64) -> silu(128) -> *fcut*rs128 -> g_lat
// ---------------------------------------------------------------------------
__global__ void __launch_bounds__(512, 1) k123(
    const float* __restrict__ W0g, const float* __restrict__ W1g,
    const float* __restrict__ W2g, int ntiles)
{
    extern __shared__ __align__(16) float sh[];
    float* sW0 = sh;
    float* sW1 = sh + 2560;
    float* sW2 = sh + 10752;
    float* sX  = sh + 27136;
    float* sHU = sh + 38400;

    int tid = threadIdx.x;
    for (int i = tid; i < 2560 / 4;  i += 512) ((float4*)sW0)[i] = ((const float4*)W0g)[i];
    for (int i = tid; i < 8192 / 4;  i += 512) ((float4*)sW1)[i] = ((const float4*)W1g)[i];
    for (int i = tid; i < 16384 / 4; i += 512) ((float4*)sW2)[i] = ((const float4*)W2g)[i];

    int lane = tid & 31, w = tid >> 5;
    int og = (w & 3) * 4 + (lane & 3);
    int eg = (w >> 2) * 8 + (lane >> 2);

    auto stage = [&](long t, int b) {
        float* dst = sX + b * 5632;
        for (int i = tid; i < 1280; i += 512) {
            int e_l = i / 10, ks = (i % 10) * 4;
            cpa16(dst + e_l * 44 + ks, g_X0 + (t * 128 + e_l) * 40 + ks);
        }
        cp_commit();
    };

    long t0 = blockIdx.x;
    if (t0 < ntiles) stage(t0, 0);
    int b = 0;

    for (long t = t0; t < ntiles; t += gridDim.x) {
        long nt = t + gridDim.x;
        bool hn = nt < ntiles;
        __syncthreads();
        if (hn) stage(nt, b ^ 1);
        if (hn) cp_wait1(); else cp_wait0();
        __syncthreads();

        {
            const float* Xb = sX + b * 5632;
            ULL acc[4][2];
#pragma unroll
            for (int j = 0; j < 4; j++) { acc[j][0] = 0ULL; acc[j][1] = 0ULL; }
            const float* xr[4];
#pragma unroll
            for (int j = 0; j < 4; j++) xr[j] = Xb + (eg + 32 * j) * 44;
#pragma unroll 2
            for (int k4 = 0; k4 < 40; k4 += 4) {
                float4 xv[4];
#pragma unroll
                for (int j = 0; j < 4; j++) xv[j] = *(const float4*)(xr[j] + k4);
#pragma unroll
                for (int kk = 0; kk < 4; kk++) {
                    const float* wr = sW0 + (k4 + kk) * 64 + og * 4;
                    ULL w0 = *(const ULL*)wr, w1 = *(const ULL*)(wr + 2);
#pragma unroll
                    for (int j = 0; j < 4; j++) {
                        float xs = (kk == 0) ? xv[j].x : (kk == 1) ? xv[j].y
                                 : (kk == 2) ? xv[j].z : xv[j].w;
                        ULL xd = pack2(xs);
                        acc[j][0] = fma2(xd, w0, acc[j][0]);
                        acc[j][1] = fma2(xd, w1, acc[j][1]);
                    }
                }
            }
#pragma unroll
            for (int j = 0; j < 4; j++) {
                union { ULL u; float2 f; } c0, c1;
                c0.u = acc[j][0]; c1.u = acc[j][1];
                *(float4*)(sHU + (eg + 32 * j) * 68 + og * 4) =
                    make_float4(silu_f(c0.f.x * F_RS40), silu_f(c0.f.y * F_RS40),
                                silu_f(c1.f.x * F_RS40), silu_f(c1.f.y * F_RS40));
            }
        }
        __syncthreads();

        {
            ULL acc[4][4];
#pragma unroll
            for (int j = 0; j < 4; j++)
#pragma unroll
                for (int p = 0; p < 4; p++) acc[j][p] = 0ULL;
            const float* xr[4];
#pragma unroll
            for (int j = 0; j < 4; j++) xr[j] = sHU + (eg + 32 * j) * 68;
#pragma unroll 2
            for (int k4 = 0; k4 < 64; k4 += 4) {
                float4 xv[4];
#pragma unroll
                for (int j = 0; j < 4; j++) xv[j] = *(const float4*)(xr[j] + k4);
#pragma unroll
                for (int kk = 0; kk < 4; kk++) {
                    const float* wr = sW1 + (k4 + kk) * 128 + og * 8;
                    ulonglong2 wa = *(const ulonglong2*)wr;
                    ulonglong2 wb = *(const ulonglong2*)(wr + 4);
#pragma unroll
                    for (int j = 0; j < 4; j++) {
                        float xs = (kk == 0) ? xv[j].x : (kk == 1) ? xv[j].y
                                 : (kk == 2) ? xv[j].z : xv[j].w;
                        ULL xd = pack2(xs);
                        acc[j][0] = fma2(xd, wa.x, acc[j][0]);
                        acc[j][1] = fma2(xd, wa.y, acc[j][1]);
                        acc[j][2] = fma2(xd, wb.x, acc[j][2]);
                        acc[j][3] = fma2(xd, wb.y, acc[j][3]);
                    }
                }
            }
            __syncthreads();
#pragma unroll
            for (int j = 0; j < 4; j++) {
                float* hr = sHU + (eg + 32 * j) * 132 + og * 8;
                union { ULL u; float2 f; } c0, c1, c2, c3;
                c0.u = acc[j][0]; c1.u = acc[j][1]; c2.u = acc[j][2]; c3.u = acc[j][3];
                *(float4*)hr =
                    make_float4(silu_f(c0.f.x * F_RS64), silu_f(c0.f.y * F_RS64),
                                silu_f(c1.f.x * F_RS64), silu_f(c1.f.y * F_RS64));
                *(float4*)(hr + 4) =
                    make_float4(silu_f(c2.f.x * F_RS64), silu_f(c2.f.y * F_RS64),
                                silu_f(c3.f.x * F_RS64), silu_f(c3.f.y * F_RS64));
            }
        }
        __syncthreads();

        {
            ULL acc[4][4];
#pragma unroll
            for (int j = 0; j < 4; j++)
#pragma unroll
                for (int p = 0; p < 4; p++) acc[j][p] = 0ULL;
            const float* xr[4];
#pragma unroll
            for (int j = 0; j < 4; j++) xr[j] = sHU + (eg + 32 * j) * 132;
#pragma unroll 2
            for (int k4 = 0; k4 < 128; k4 += 4) {
                float4 xv[4];
#pragma unroll
                for (int j = 0; j < 4; j++) xv[j] = *(const float4*)(xr[j] + k4);
#pragma unroll
                for (int kk = 0; kk < 4; kk++) {
                    const float* wr = sW2 + (k4 + kk) * 128 + og * 8;
                    ulonglong2 wa = *(const ulonglong2*)wr;
                    ulonglong2 wb = *(const ulonglong2*)(wr + 4);
#pragma unroll
                    for (int j = 0; j < 4; j++) {
                        float xs = (kk == 0) ? xv[j].x : (kk == 1) ? xv[j].y
                                 : (kk == 2) ? xv[j].z : xv[j].w;
                        ULL xd = pack2(xs);
                        acc[j][0] = fma2(xd, wa.x, acc[j][0]);
                        acc[j][1] = fma2(xd, wa.y, acc[j][1]);
                        acc[j][2] = fma2(xd, wb.x, acc[j][2]);
                        acc[j][3] = fma2(xd, wb.y, acc[j][3]);
                    }
                }
            }
#pragma unroll
            for (int j = 0; j < 4; j++) {
                long e = t * 128 + eg + 32 * j;
                float s = F_RS128 * g_fcut[e];
                union { ULL u; float2 f; } c0, c1, c2, c3;
                c0.u = acc[j][0]; c1.u = acc[j][1]; c2.u = acc[j][2]; c3.u = acc[j][3];
                *(float4*)(g_lat + e * 128 + og * 8) =
                    make_float4(c0.f.x * s, c0.f.y * s, c1.f.x * s, c1.f.y * s);
                *(float4*)(g_lat + e * 128 + og * 8 + 4) =
                    make_float4(c2.f.x * s, c2.f.y * s, c3.f.x * s, c3.f.y * s);
            }
        }
        b ^= 1;
    }
}

// ---------------------------------------------------------------------------
__global__ void k_zero(float* __restrict__ out)
{
    int i = blockIdx.x * blockDim.x + threadIdx.x;
    int stride = gridDim.x * blockDim.x;
    for (; i < NN * 128; i += stride) {
        g_env[i]  = 0.0f;
        g_env1[i] = 0.0f;
        out[i]    = 0.0f;
    }
}

__global__ void __launch_bounds__(512) kgeo(
    const float* __restrict__ coords, const float* __restrict__ attrs,
    const int* __restrict__ eidx)
{
    int e = blockIdx.x * 512 + threadIdx.x;
    if (e >= NE) return;
    int snd = eidx[e];
    int c   = eidx[NE + e];
    float dx = coords[c * 3 + 0] - coords[snd * 3 + 0];
    float dy = coords[c * 3 + 1] - coords[snd * 3 + 1];
    float dz = coords[c * 3 + 2] - coords[snd * 3 + 2];
    float r2 = dx * dx + dy * dy + dz * dz + 1e-12f;
    float r  = sqrtf(r2);
    float inv_r = 1.0f / r;
    float u  = r * F_INV_RMAX;
    float u2 = u * u, u3 = u2 * u, u6 = u3 * u3, u7 = u6 * u, u8 = u7 * u;
    float f  = 1.0f - 28.0f * u6 + 48.0f * u7 - 21.0f * u8;
    if (u >= 1.0f) f = 0.0f;
    g_fcut[e] = f;
    *(float4*)(g_Y + e * 4) = make_float4(1.0f, F_SQRT3 * dx * inv_r,
                                          F_SQRT3 * dy * inv_r, F_SQRT3 * dz * inv_r);
    float* X = g_X0 + (long)e * 40;
    const float4* ac = (const float4*)(attrs + c * 16);
    const float4* as = (const float4*)(attrs + snd * 16);
#pragma unroll
    for (int i = 0; i < 4; i++) ((float4*)X)[i] = ac[i];
#pragma unroll
    for (int i = 0; i < 4; i++) ((float4*)(X + 16))[i] = as[i];
    float bi = inv_r * f * F_BESSEL;
#pragma unroll
    for (int n = 0; n < 8; n++)
        X[32 + n] = bi * sinf((n + 1) * F_PI * u);
}

__global__ void __launch_bounds__(256) kp1(const int* __restrict__ eidx)
{
    int warp = (blockIdx.x * 256 + threadIdx.x) >> 5;
    int lane = threadIdx.x & 31;
    int nw = gridDim.x * 8;
    for (long e = warp; e < NE; e += nw) {
        long c = eidx[NE + e];
        float2 we = *(const float2*)(g_wedge + e * 64 + 2 * lane);
        float4 en = *(const float4*)(g_env + c * 128 + 4 * lane);
        float4 Y  = *(const float4*)(g_Y + e * 4);
        float fs  = we.x;
        float fv0 = we.y * Y.y, fv1 = we.y * Y.z, fv2 = we.y * Y.w;
        float es  = en.x * F_ISN;
        float ev0 = en.y * F_ISN, ev1 = en.z * F_ISN, ev2 = en.w * F_ISN;
        g_scal0[e * 64 + lane]      = fs * es;
        g_scal0[e * 64 + 32 + lane] = (fv0 * ev0 + fv1 * ev1 + fv2 * ev2) * F_INV_SQRT3;
        float* P0 = g_P + (3 * e + 0) * 96;
        float* P1 = g_P + (3 * e + 1) * 96;
        float* P2 = g_P + (3 * e + 2) * 96;
        P0[lane] = fs * ev0;  P1[lane] = fs * ev1;  P2[lane] = fs * ev2;
        P0[32 + lane] = fv0 * es; P1[32 + lane] = fv1 * es; P2[32 + lane] = fv2 * es;
        P0[64 + lane] = (fv1 * ev2 - fv2 * ev1) * F_INV_SQRT2;
        P1[64 + lane] = (fv2 * ev0 - fv0 * ev2) * F_INV_SQRT2;
        P2[64 + lane] = (fv0 * ev1 - fv1 * ev0) * F_INV_SQRT2;
    }
}

__global__ void __launch_bounds__(256) kp2(const int* __restrict__ eidx)
{
    int warp = (blockIdx.x * 256 + threadIdx.x) >> 5;
    int lane = threadIdx.x & 31;
    int nw = gridDim.x * 8;
    for (long e = warp; e < NE; e += nw) {
        long c = eidx[NE + e];
        float4 e1 = *(const float4*)(g_env1 + c * 128 + 4 * lane);
        float sm = g_smix[e * 32 + lane];
        float v0 = g_vmx[(3 * e + 0) * 32 + lane];
        float v1 = g_vmx[(3 * e + 1) * 32 + lane];
        float v2 = g_vmx[(3 * e + 2) * 32 + lane];
        g_q[e * 64 + lane] = sm * e1.x * F_ISN;
        g_q[e * 64 + 32 + lane] =
            (v0 * e1.y + v1 * e1.z + v2 * e1.w) * F_ISN * F_INV_SQRT3;
    }
}

// ---------------------------------------------------------------------------
extern "C" void kernel_launch(void* const* d_in, const int* in_sizes, int n_in,
                              void* d_out, int out_size)
{
    const float* coords = (const float*)d_in[0];
    const float* attrs  = (const float*)d_in[1];
    const int*   eidx   = (const int*)  d_in[2];
    const float* W2b0   = (const float*)d_in[3];
    const float* W2b1   = (const float*)d_in[4];
    const float* W2b2   = (const float*)d_in[5];
    const float* Wenv0  = (const float*)d_in[6];
    const float* Wlat0  = (const float*)d_in[7];
    const float* Wlat1  = (const float*)d_in[8];
    const float* Ws0    = (const float*)d_in[9];
    const float* Wv0    = (const float*)d_in[10];
    const float* Wenv1  = (const float*)d_in[11];
    const float* Wfin0  = (const float*)d_in[12];
    const float* Wfin1  = (const float*)d_in[13];
    float* out = (float*)d_out;
    const int* ctr = eidx + NE;

    const size_t sm_k123   = (2560 + 8192 + 16384 + 11264 + 16896) * 4;
    const size_t sm2_64    = (8192  + 2 * 64 * 68) * 4;
    const size_t sm64_32   = (2048 + 2 * 128 * 68) * 4;
    const size_t sm96_32   = (3072 + 2 * 128 * 100) * 4;
    const size_t sm_t128   = (size_t)4 * 128 * 64 * 4;   // 131072
    const size_t sm_t192   = (size_t)4 * 128 * 96 * 4;   // 196608

    cudaFuncSetAttribute(k123, cudaFuncAttributeMaxDynamicSharedMemorySize, (int)sm_k123);
    cudaFuncSetAttribute(tkm<128, OpG4T>,  cudaFuncAttributeMaxDynamicSharedMemorySize, (int)sm_t128);
    cudaFuncSetAttribute(tkm<192, OpG7T>,  cudaFuncAttributeMaxDynamicSharedMemorySize, (int)sm_t192);
    cudaFuncSetAttribute(tkm<128, OpG8T>,  cudaFuncAttributeMaxDynamicSharedMemorySize, (int)sm_t128);
    cudaFuncSetAttribute(tkm<192, OpG10T>, cudaFuncAttributeMaxDynamicSharedMemorySize, (int)sm_t192);
    cudaFuncSetAttribute(tkm<128, OpG11T>, cudaFuncAttributeMaxDynamicSharedMemorySize, (int)sm_t128);
    cudaFuncSetAttribute(gk<64, 64, 32, 4, OpG5>, cudaFuncAttributeMaxDynamicSharedMemorySize, (int)sm64_32);
    cudaFuncSetAttribute(gk<96, 96, 32, 4, OpG6>, cudaFuncAttributeMaxDynamicSharedMemorySize, (int)sm96_32);
    cudaFuncSetAttribute(gk2<128, 64, 64, 4, OpG9>, cudaFuncAttributeMaxDynamicSharedMemorySize, (int)sm2_64);

    const int NT   = NE / 128;   // 2500
    const int NT64 = NE / 64;    // 5000
    const int NT3  = NE3 / 128;  // 7500

    k_zero<<<512, 256>>>(out);
    kgeo<<<(NE + 511) / 512, 512>>>(coords, attrs, eidx);

    k123<<<148, 512, sm_k123>>>(W2b0, W2b1, W2b2, NT);
    tkm<128, OpG4T><<<148, 512, sm_t128>>>(OpG4T{ctr}, Wenv0, NT);
    kp1<<<2560, 256>>>(eidx);
    gk<64, 64, 32, 4, OpG5><<<148, 512, sm64_32>>>(OpG5{}, Ws0, NT);
    gk<96, 96, 32, 4, OpG6><<<148, 512, sm96_32>>>(OpG6{}, Wv0, NT3);
    tkm<192, OpG7T><<<148, 512, sm_t192>>>(OpG7T{}, Wlat0, NT);
    tkm<128, OpG8T><<<148, 512, sm_t128>>>(OpG8T{}, Wlat1, NT);
    gk2<128, 64, 64, 4, OpG9><<<296, 256, sm2_64>>>(OpG9{ctr}, Wenv1, NT64);
    kp2<<<2560, 256>>>(eidx);
    tkm<192, OpG10T><<<148, 512, sm_t192>>>(OpG10T{}, Wfin0, NT);
    tkm<128, OpG11T><<<148, 512, sm_t128>>>(OpG11T{ctr, out}, Wfin1, NT);
}

// round 15
// speedup vs baseline: 1.5775x; 1.0289x over previous
#include <cuda_runtime.h>
#include <cuda_bf16.h>

// ---------------------------------------------------------------------------
// Allegro GNN layer.  tkm  = warp-level mma.sync bf16-split GEMM (K=192,
// 512 thr, BM=128);  tkm2 = same algorithm at BM=64, 256 thr, 2 CTAs/SM
// (K=128: G4/G8/G11) so stage and MMA phases of the two CTAs interleave.
// Rest = proven R12 pipeline (gk/gk2 FFMA2, k123, kp1/kp2).
// ---------------------------------------------------------------------------

#define NN 10000
#define NE 320000
#define NE3 960000
typedef unsigned long long ULL;
typedef unsigned int U32;

__device__ float g_X0  [NE * 40];
__device__ float g_H   [NE * 128];
__device__ float g_lat [NE * 128];
__device__ float g_wedge[NE * 64];
__device__ float g_scal0[NE * 64];
__device__ float g_P   [(long)NE3 * 96];
__device__ float g_smix[NE * 32];
__device__ float g_vmx [NE3 * 32];
__device__ float g_q   [NE * 64];
__device__ float g_Y   [NE * 4];
__device__ float g_fcut[NE];
__device__ float g_env [NN * 128];
__device__ float g_env1[NN * 128];

#define F_RS40      0.15811388300841897f
#define F_RS64      0.125f
#define F_RS96      0.10206207261596575f
#define F_RS128     0.08838834764831845f
#define F_RS192     0.07216878364870323f
#define F_ISN       0.17677669529663689f
#define F_SQRT3     1.7320508075688772f
#define F_INV_SQRT3 0.5773502691896258f
#define F_INV_SQRT2 0.7071067811865476f
#define F_C_OLD     0.8944271909999159f
#define F_C_NEW     0.4472135954999579f
#define F_BESSEL    0.6324555320336759f
#define F_PI        3.14159265358979323846f
#define F_INV_RMAX  0.2f

__device__ __forceinline__ ULL fma2(ULL a, ULL b, ULL c) {
    ULL d;
    asm("fma.rn.f32x2 %0, %1, %2, %3;" : "=l"(d) : "l"(a), "l"(b), "l"(c));
    return d;
}
__device__ __forceinline__ ULL pack2(float x) {
    ULL d; unsigned u = __float_as_uint(x);
    asm("mov.b64 %0, {%1,%1};" : "=l"(d) : "r"(u));
    return d;
}
__device__ __forceinline__ void red4(float* p, float a, float b, float c, float d) {
    asm volatile("red.global.add.v4.f32 [%0], {%1,%2,%3,%4};"
                 :: "l"(p), "f"(a), "f"(b), "f"(c), "f"(d) : "memory");
}
__device__ __forceinline__ void red2(float* p, float a, float b) {
    asm volatile("red.global.add.v2.f32 [%0], {%1,%2};"
                 :: "l"(p), "f"(a), "f"(b) : "memory");
}
__device__ __forceinline__ float silu_f(float v) {
    return v * __frcp_rn(1.0f + __expf(-v));
}
__device__ __forceinline__ void cpa16(const void* s, const void* g) {
    unsigned sa = (unsigned)__cvta_generic_to_shared(s);
    asm volatile("cp.async.cg.shared.global [%0], [%1], 16;" :: "r"(sa), "l"(g));
}
__device__ __forceinline__ void cp_commit() { asm volatile("cp.async.commit_group;"); }
__device__ __forceinline__ void cp_wait1()  { asm volatile("cp.async.wait_group 1;"); }
__device__ __forceinline__ void cp_wait0()  { asm volatile("cp.async.wait_group 0;"); }

__device__ __forceinline__ void mma16816(float* d, const U32* a, const U32* b) {
    asm volatile(
        "mma.sync.aligned.m16n8k16.row.col.f32.bf16.bf16.f32 "
        "{%0,%1,%2,%3}, {%4,%5,%6,%7}, {%8,%9}, {%0,%1,%2,%3};"
        : "+f"(d[0]), "+f"(d[1]), "+f"(d[2]), "+f"(d[3])
        : "r"(a[0]), "r"(a[1]), "r"(a[2]), "r"(a[3]), "r"(b[0]), "r"(b[1]));
}
__device__ __forceinline__ void bsplit8(const float* xs, uint4& hi, uint4& lo) {
    unsigned h[4], l[4];
#pragma unroll
    for (int p = 0; p < 4; p++) {
        __nv_bfloat16 h0 = __float2bfloat16(xs[2 * p]);
        __nv_bfloat16 h1 = __float2bfloat16(xs[2 * p + 1]);
        __nv_bfloat16 l0 = __float2bfloat16(xs[2 * p] - __bfloat162float(h0));
        __nv_bfloat16 l1 = __float2bfloat16(xs[2 * p + 1] - __bfloat162float(h1));
        h[p] = (unsigned)__bfloat16_as_ushort(h0) |
               ((unsigned)__bfloat16_as_ushort(h1) << 16);
        l[p] = (unsigned)__bfloat16_as_ushort(l0) |
               ((unsigned)__bfloat16_as_ushort(l1) << 16);
    }
    hi = make_uint4(h[0], h[1], h[2], h[3]);
    lo = make_uint4(l[0], l[1], l[2], l[3]);
}
// swizzled pair index: row-major [row][K/2 pairs], pair p XOR ((row&7)<<2)
__device__ __forceinline__ int pidx(int row, int p, int KH) {
    return row * KH + (p ^ ((row & 7) << 2));
}

// ---------------------------------------------------------------------------
// tkm: warp mma bf16-split GEMM.  BM=128, OUT=128, 512 thr (K=192 kernels).
// ---------------------------------------------------------------------------
template <int K, class Op>
__global__ void __launch_bounds__(512, 1) tkm(Op op, const float* __restrict__ Wg,
                                              int ntiles)
{
    constexpr int KH = K / 2;
    constexpr int KB = K / 8;
    extern __shared__ __align__(16) U32 su[];
    U32* AH = su;
    U32* AL = AH + 128 * KH;
    U32* BH = AL + 128 * KH;
    U32* BL = BH + 128 * KH;

    int tid = threadIdx.x, lane = tid & 31, w = tid >> 5;
    int g = lane >> 2, tg = lane & 3;
    int wm = w & 3, wn = w >> 2;

    for (int i = tid; i < 128 * KB; i += 512) {
        int n = i / KB, kb = (i % KB) * 8;
        float xs[8];
#pragma unroll
        for (int j = 0; j < 8; j++) xs[j] = Wg[(kb + j) * 128 + n];
        uint4 hi, lo; bsplit8(xs, hi, lo);
        int p4 = ((kb >> 1) ^ ((n & 7) << 2));
        *(uint4*)&BH[n * KH + p4] = hi;
        *(uint4*)&BL[n * KH + p4] = lo;
    }
    __syncthreads();

    for (long t = blockIdx.x; t < ntiles; t += gridDim.x) {
        for (int i = tid; i < 128 * KB; i += 512) {
            int m = i / KB, kb = (i % KB) * 8;
            const float* s = op.src(t * 128 + m, kb);
            float4 x0 = *(const float4*)s, x1 = *(const float4*)(s + 4);
            float xs[8] = {x0.x, x0.y, x0.z, x0.w, x1.x, x1.y, x1.z, x1.w};
            uint4 hi, lo; bsplit8(xs, hi, lo);
            int p4 = ((kb >> 1) ^ ((m & 7) << 2));
            *(uint4*)&AH[m * KH + p4] = hi;
            *(uint4*)&AL[m * KH + p4] = lo;
        }
        __syncthreads();

        float acc[2][4][4];
#pragma unroll
        for (int mt = 0; mt < 2; mt++)
#pragma unroll
            for (int nt = 0; nt < 4; nt++)
#pragma unroll
                for (int q = 0; q < 4; q++) acc[mt][nt][q] = 0.0f;

#pragma unroll 2
        for (int ks = 0; ks < K / 16; ks++) {
            int pb = ks * 8;
            U32 ah[2][4], al[2][4];
#pragma unroll
            for (int mt = 0; mt < 2; mt++) {
                int r0 = wm * 32 + mt * 16 + g;
                ah[mt][0] = AH[pidx(r0,     pb + tg,     KH)];
                ah[mt][1] = AH[pidx(r0 + 8, pb + tg,     KH)];
                ah[mt][2] = AH[pidx(r0,     pb + tg + 4, KH)];
                ah[mt][3] = AH[pidx(r0 + 8, pb + tg + 4, KH)];
                al[mt][0] = AL[pidx(r0,     pb + tg,     KH)];
                al[mt][1] = AL[pidx(r0 + 8, pb + tg,     KH)];
                al[mt][2] = AL[pidx(r0,     pb + tg + 4, KH)];
                al[mt][3] = AL[pidx(r0 + 8, pb + tg + 4, KH)];
            }
            U32 bh[4][2], bl[4][2];
#pragma unroll
            for (int nt = 0; nt < 4; nt++) {
                int n = wn * 32 + nt * 8 + g;
                bh[nt][0] = BH[pidx(n, pb + tg,     KH)];
                bh[nt][1] = BH[pidx(n, pb + tg + 4, KH)];
                bl[nt][0] = BL[pidx(n, pb + tg,     KH)];
                bl[nt][1] = BL[pidx(n, pb + tg + 4, KH)];
            }
#pragma unroll
            for (int mt = 0; mt < 2; mt++)
#pragma unroll
                for (int nt = 0; nt < 4; nt++) {
                    mma16816(acc[mt][nt], ah[mt], bh[nt]);
                    mma16816(acc[mt][nt], ah[mt], bl[nt]);
                    mma16816(acc[mt][nt], al[mt], bh[nt]);
                }
        }

#pragma unroll
        for (int mt = 0; mt < 2; mt++) {
            int r0 = wm * 32 + mt * 16 + g;
#pragma unroll
            for (int nt = 0; nt < 4; nt++) {
                int col = wn * 32 + nt * 8 + tg * 2;
                op.epi2(t * 128 + r0,     col, acc[mt][nt][0], acc[mt][nt][1]);
                op.epi2(t * 128 + r0 + 8, col, acc[mt][nt][2], acc[mt][nt][3]);
            }
        }
        __syncthreads();
    }
}

// ---------------------------------------------------------------------------
// tkm2: same algorithm, BM=64, 256 thr, 2 CTAs/SM  (K=128: G4/G8/G11).
// Two CTAs per SM interleave stage (LSU/FMA) with MMA (tensor pipe).
// ---------------------------------------------------------------------------
template <int K, class Op>
__global__ void __launch_bounds__(256, 2) tkm2(Op op, const float* __restrict__ Wg,
                                               int ntiles)
{
    constexpr int KH = K / 2;
    constexpr int KB = K / 8;
    extern __shared__ __align__(16) U32 su[];
    U32* AH = su;                  // 64*KH
    U32* AL = AH + 64 * KH;
    U32* BH = AL + 64 * KH;        // 128*KH
    U32* BL = BH + 128 * KH;

    int tid = threadIdx.x, lane = tid & 31, w = tid >> 5;
    int g = lane >> 2, tg = lane & 3;
    int wm = w & 1, wn = w >> 1;

    for (int i = tid; i < 128 * KB; i += 256) {
        int n = i / KB, kb = (i % KB) * 8;
        float xs[8];
#pragma unroll
        for (int j = 0; j < 8; j++) xs[j] = Wg[(kb + j) * 128 + n];
        uint4 hi, lo; bsplit8(xs, hi, lo);
        int p4 = ((kb >> 1) ^ ((n & 7) << 2));
        *(uint4*)&BH[n * KH + p4] = hi;
        *(uint4*)&BL[n * KH + p4] = lo;
    }
    __syncthreads();

    for (long t = blockIdx.x; t < ntiles; t += gridDim.x) {
        for (int i = tid; i < 64 * KB; i += 256) {
            int m = i / KB, kb = (i % KB) * 8;
            const float* s = op.src(t * 64 + m, kb);
            float4 x0 = *(const float4*)s, x1 = *(const float4*)(s + 4);
            float xs[8] = {x0.x, x0.y, x0.z, x0.w, x1.x, x1.y, x1.z, x1.w};
            uint4 hi, lo; bsplit8(xs, hi, lo);
            int p4 = ((kb >> 1) ^ ((m & 7) << 2));
            *(uint4*)&AH[m * KH + p4] = hi;
            *(uint4*)&AL[m * KH + p4] = lo;
        }
        __syncthreads();

        float acc[2][4][4];
#pragma unroll
        for (int mt = 0; mt < 2; mt++)
#pragma unroll
            for (int nt = 0; nt < 4; nt++)
#pragma unroll
                for (int q = 0; q < 4; q++) acc[mt][nt][q] = 0.0f;

#pragma unroll 2
        for (int ks = 0; ks < K / 16; ks++) {
            int pb = ks * 8;
            U32 ah[2][4], al[2][4];
#pragma unroll
            for (int mt = 0; mt < 2; mt++) {
                int r0 = wm * 32 + mt * 16 + g;
                ah[mt][0] = AH[pidx(r0,     pb + tg,     KH)];
                ah[mt][1] = AH[pidx(r0 + 8, pb + tg,     KH)];
                ah[mt][2] = AH[pidx(r0,     pb + tg + 4, KH)];
                ah[mt][3] = AH[pidx(r0 + 8, pb + tg + 4, KH)];
                al[mt][0] = AL[pidx(r0,     pb + tg,     KH)];
                al[mt][1] = AL[pidx(r0 + 8, pb + tg,     KH)];
                al[mt][2] = AL[pidx(r0,     pb + tg + 4, KH)];
                al[mt][3] = AL[pidx(r0 + 8, pb + tg + 4, KH)];
            }
            U32 bh[4][2], bl[4][2];
#pragma unroll
            for (int nt = 0; nt < 4; nt++) {
                int n = wn * 32 + nt * 8 + g;
                bh[nt][0] = BH[pidx(n, pb + tg,     KH)];
                bh[nt][1] = BH[pidx(n, pb + tg + 4, KH)];
                bl[nt][0] = BL[pidx(n, pb + tg,     KH)];
                bl[nt][1] = BL[pidx(n, pb + tg + 4, KH)];
            }
#pragma unroll
            for (int mt = 0; mt < 2; mt++)
#pragma unroll
                for (int nt = 0; nt < 4; nt++) {
                    mma16816(acc[mt][nt], ah[mt], bh[nt]);
                    mma16816(acc[mt][nt], ah[mt], bl[nt]);
                    mma16816(acc[mt][nt], al[mt], bh[nt]);
                }
        }

#pragma unroll
        for (int mt = 0; mt < 2; mt++) {
            int r0 = wm * 32 + mt * 16 + g;
#pragma unroll
            for (int nt = 0; nt < 4; nt++) {
                int col = wn * 32 + nt * 8 + tg * 2;
                op.epi2(t * 64 + r0,     col, acc[mt][nt][0], acc[mt][nt][1]);
                op.epi2(t * 64 + r0 + 8, col, acc[mt][nt][2], acc[mt][nt][3]);
            }
        }
        __syncthreads();
    }
}

// ---------------------------------------------------------------------------
// Streaming FFMA2 GEMM, 512 threads (G5, G6)
// ---------------------------------------------------------------------------
template <int KTOT, int KC, int OUT, int OPO, class Op>
__global__ void __launch_bounds__(512, 1) gk(Op op, const float* __restrict__ Wg,
                                             int ntiles)
{
    constexpr int PC  = KC + 4;
    constexpr int NCH = KTOT / KC;
    constexpr int OG  = OUT / OPO;
    constexpr int OGW = OG / 4;
    constexpr int EGN = 512 / OG;
    constexpr int EPT = 128 / EGN;
    constexpr int NP  = OPO / 2;

    extern __shared__ __align__(16) float sh[];
    float* sW = sh;
    float* sX = sh + KTOT * OUT;

    int tid = threadIdx.x;
    for (int i = tid; i < KTOT * OUT / 4; i += 512)
        ((float4*)sW)[i] = ((const float4*)Wg)[i];

    int lane = tid & 31, w = tid >> 5;
    int og = (w & (OGW - 1)) * 4 + (lane & 3);
    int eg = (w / OGW) * 8 + (lane >> 2);

    auto stage = [&](long t, int c, int b) {
        float* dst = sX + b * (128 * PC);
        constexpr int UN = 128 * (KC / 4);
        for (int i = tid; i < UN; i += 512) {
            int e_l = i / (KC / 4);
            int ks  = (i % (KC / 4)) * 4;
            cpa16(dst + e_l * PC + ks, op.src(t * 128 + e_l, c * KC + ks));
        }
        cp_commit();
    };

    long t0 = blockIdx.x;
    if (t0 < ntiles) stage(t0, 0, 0);
    int b = 0;

    for (long t = t0; t < ntiles; t += gridDim.x) {
        ULL acc[EPT][NP];
#pragma unroll
        for (int j = 0; j < EPT; j++)
#pragma unroll
            for (int p = 0; p < NP; p++) acc[j][p] = 0ULL;

        for (int c = 0; c < NCH; c++) {
            long nt = t; int nc = c + 1;
            if (nc == NCH) { nt = t + gridDim.x; nc = 0; }
            bool hn = nt < ntiles;
            __syncthreads();
            if (hn) stage(nt, nc, b ^ 1);
            if (hn) cp_wait1(); else cp_wait0();
            __syncthreads();

            const float* Xb = sX + b * (128 * PC);
            const float* xr[EPT];
#pragma unroll
            for (int j = 0; j < EPT; j++) xr[j] = Xb + (eg + EGN * j) * PC;

#pragma unroll 2
            for (int k4 = 0; k4 < KC; k4 += 4) {
                float4 xv[EPT];
#pragma unroll
                for (int j = 0; j < EPT; j++)
                    xv[j] = *(const float4*)(xr[j] + k4);
#pragma unroll
                for (int kk = 0; kk < 4; kk++) {
                    const float* wr = sW + (c * KC + k4 + kk) * OUT + og * OPO;
                    ULL wv[NP];
#pragma unroll
                    for (int p = 0; p < NP; p++)
                        wv[p] = *(const ULL*)(wr + 2 * p);
#pragma unroll
                    for (int j = 0; j < EPT; j++) {
                        float xs = (kk == 0) ? xv[j].x : (kk == 1) ? xv[j].y
                                 : (kk == 2) ? xv[j].z : xv[j].w;
                        ULL xd = pack2(xs);
#pragma unroll
                        for (int p = 0; p < NP; p++)
                            acc[j][p] = fma2(xd, wv[p], acc[j][p]);
                    }
                }
            }
            b ^= 1;
        }

#pragma unroll
        for (int j = 0; j < EPT; j++) {
            long e = t * 128 + eg + EGN * j;
            float r[OPO];
#pragma unroll
            for (int p = 0; p < NP; p++) {
                union { ULL u; float2 f; } cv; cv.u = acc[j][p];
                r[2 * p] = cv.f.x; r[2 * p + 1] = cv.f.y;
            }
            op.epi(e, og, r);
        }
    }
}

// ---------------------------------------------------------------------------
// Streaming FFMA2 GEMM, 256 threads, 2 CTAs/SM (G9)
// ---------------------------------------------------------------------------
template <int KTOT, int KC, int OUT, int OPO, class Op>
__global__ void __launch_bounds__(256, 2) gk2(Op op, const float* __restrict__ Wg,
                                              int ntiles)
{
    constexpr int PC  = KC + 4;
    constexpr int NCH = KTOT / KC;
    constexpr int OG  = OUT / OPO;
    constexpr int OGW = OG / 4;
    constexpr int EGN = 256 / OG;
    constexpr int EPT = 64 / EGN;
    constexpr int NP  = OPO / 2;

    extern __shared__ __align__(16) float sh[];
    float* sW = sh;
    float* sX = sh + KTOT * OUT;

    int tid = threadIdx.x;
    for (int i = tid; i < KTOT * OUT / 4; i += 256)
        ((float4*)sW)[i] = ((const float4*)Wg)[i];

    int lane = tid & 31, w = tid >> 5;
    int og = (w & (OGW - 1)) * 4 + (lane & 3);
    int eg = (w / OGW) * 8 + (lane >> 2);

    auto stage = [&](long t, int c, int b) {
        float* dst = sX + b * (64 * PC);
        constexpr int UN = 64 * (KC / 4);
        for (int i = tid; i < UN; i += 256) {
            int e_l = i / (KC / 4);
            int ks  = (i % (KC / 4)) * 4;
            cpa16(dst + e_l * PC + ks, op.src(t * 64 + e_l, c * KC + ks));
        }
        cp_commit();
    };

    long t0 = blockIdx.x;
    if (t0 < ntiles) stage(t0, 0, 0);
    int b = 0;

    for (long t = t0; t < ntiles; t += gridDim.x) {
        ULL acc[EPT][NP];
#pragma unroll
        for (int j = 0; j < EPT; j++)
#pragma unroll
            for (int p = 0; p < NP; p++) acc[j][p] = 0ULL;

        for (int c = 0; c < NCH; c++) {
            long nt = t; int nc = c + 1;
            if (nc == NCH) { nt = t + gridDim.x; nc = 0; }
            bool hn = nt < ntiles;
            __syncthreads();
            if (hn) stage(nt, nc, b ^ 1);
            if (hn) cp_wait1(); else cp_wait0();
            __syncthreads();

            const float* Xb = sX + b * (64 * PC);
            const float* xr[EPT];
#pragma unroll
            for (int j = 0; j < EPT; j++) xr[j] = Xb + (eg + EGN * j) * PC;

#pragma unroll 2
            for (int k4 = 0; k4 < KC; k4 += 4) {
                float4 xv[EPT];
#pragma unroll
                for (int j = 0; j < EPT; j++)
                    xv[j] = *(const float4*)(xr[j] + k4);
#pragma unroll
                for (int kk = 0; kk < 4; kk++) {
                    const float* wr = sW + (c * KC + k4 + kk) * OUT + og * OPO;
                    ULL wv[NP];
#pragma unroll
                    for (int p = 0; p < NP; p++)
                        wv[p] = *(const ULL*)(wr + 2 * p);
#pragma unroll
                    for (int j = 0; j < EPT; j++) {
                        float xs = (kk == 0) ? xv[j].x : (kk == 1) ? xv[j].y
                                 : (kk == 2) ? xv[j].z : xv[j].w;
                        ULL xd = pack2(xs);
#pragma unroll
                        for (int p = 0; p < NP; p++)
                            acc[j][p] = fma2(xd, wv[p], acc[j][p]);
                    }
                }
            }
            b ^= 1;
        }

#pragma unroll
        for (int j = 0; j < EPT; j++) {
            long e = t * 64 + eg + EGN * j;
            float r[OPO];
#pragma unroll
            for (int p = 0; p < NP; p++) {
                union { ULL u; float2 f; } cv; cv.u = acc[j][p];
                r[2 * p] = cv.f.x; r[2 * p + 1] = cv.f.y;
            }
            op.epi(e, og, r);
        }
    }
}

// ---------------------------------------------------------------------------
// Epilogue / source policies.
// ---------------------------------------------------------------------------
struct OpG4T {  // lat -> w_all: cols 0-63 wedge, 64-127 env scatter
    const int* ctr;
    __device__ const float* src(long e, int k) const { return g_lat + e * 128 + k; }
    __device__ void epi2(long e, int col, float v0, float v1) const {
        if (col < 64) {
            *(float2*)(g_wedge + e * 64 + col) =
                make_float2(v0 * F_RS128, v1 * F_RS128);
        } else {
            long c = ctr[e];
            float4 Y = *(const float4*)(g_Y + e * 4);
            int m = (col - 64) >> 1;
            float w0 = v0 * F_RS128, w1 = v1 * F_RS128;
            red4(g_env + c * 128 + 4 * m, w0, w1 * Y.y, w1 * Y.z, w1 * Y.w);
        }
    }
};
struct OpG7T {  // [lat|scal0](192) -> silu -> H
    __device__ const float* src(long e, int k) const {
        return (k < 128) ? (g_lat + e * 128 + k) : (g_scal0 + e * 64 + (k - 128));
    }
    __device__ void epi2(long e, int col, float v0, float v1) const {
        *(float2*)(g_H + e * 128 + col) =
            make_float2(silu_f(v0 * F_RS192), silu_f(v1 * F_RS192));
    }
};
struct OpG8T {  // H -> *fcut, residual -> lat
    __device__ const float* src(long e, int k) const { return g_H + e * 128 + k; }
    __device__ void epi2(long e, int col, float v0, float v1) const {
        float s = F_C_NEW * F_RS128 * g_fcut[e];
        float2 l = *(float2*)(g_lat + e * 128 + col);
        *(float2*)(g_lat + e * 128 + col) =
            make_float2(F_C_OLD * l.x + s * v0, F_C_OLD * l.y + s * v1);
    }
};
struct OpG10T { // [lat|q](192) -> silu -> H
    __device__ const float* src(long e, int k) const {
        return (k < 128) ? (g_lat + e * 128 + k) : (g_q + e * 64 + (k - 128));
    }
    __device__ void epi2(long e, int col, float v0, float v1) const {
        *(float2*)(g_H + e * 128 + col) =
            make_float2(silu_f(v0 * F_RS192), silu_f(v1 * F_RS192));
    }
};
struct OpG11T { // H -> *fcut, residual, *isn -> node scatter
    const int* ctr;
    float* out;
    __device__ const float* src(long e, int k) const { return g_H + e * 128 + k; }
    __device__ void epi2(long e, int col, float v0, float v1) const {
        long c = ctr[e];
        float s = F_C_NEW * F_RS128 * g_fcut[e];
        float2 l = *(const float2*)(g_lat + e * 128 + col);
        red2(out + c * 128 + col,
             (F_C_OLD * l.x + s * v0) * F_ISN,
             (F_C_OLD * l.y + s * v1) * F_ISN);
    }
};
struct OpG5 {
    __device__ const float* src(long e, int k) const { return g_scal0 + e * 64 + k; }
    __device__ void epi(long e, int og, const float* r) const {
        *(float4*)(g_smix + e * 32 + og * 4) =
            make_float4(r[0] * F_RS64, r[1] * F_RS64, r[2] * F_RS64, r[3] * F_RS64);
    }
};
struct OpG6 {
    __device__ const float* src(long e, int k) const { return g_P + e * 96 + k; }
    __device__ void epi(long e, int og, const float* r) const {
        *(float4*)(g_vmx + e * 32 + og * 4) =
            make_float4(r[0] * F_RS96, r[1] * F_RS96, r[2] * F_RS96, r[3] * F_RS96);
    }
};
struct OpG9 {
    const int* ctr;
    __device__ const float* src(long e, int k) const { return g_lat + e * 128 + k; }
    __device__ void epi(long e, int og, const float* r) const {
        long c = ctr[e];
        float4 Y = *(const float4*)(g_Y + e * 4);
        int m0 = og * 2;
        float w0 = r[0] * F_RS128, w1 = r[1] * F_RS128;
        red4(g_env1 + c * 128 + 4 * m0, w0, w1 * Y.y, w1 * Y.z, w1 * Y.w);
        float w2 = r[2] * F_RS128, w3 = r[3] * F_RS128;
        red4(g_env1 + c * 128 + 4 * (m0 + 1), w2, w3 * Y.y, w3 * Y.z, w3 * Y.w);
    }
};

// ---------------------------------------------------------------------------
// k123: fused X0(40) -> silu(64) -> silu(128) -> *fcut*rs128 -> g_lat
// ---------------------------------------------------------------------------
__global__ void __launch_bounds__(512, 1) k123(
    const float* __restrict__ W0g, const float* __restrict__ W1g,
    const float* __restrict__ W2g, int ntiles)
{
    extern __shared__ __align__(16) float sh[];
    float* sW0 = sh;
    float* sW1 = sh + 2560;
    float* sW2 = sh + 10752;
    float* sX  = sh + 27136;
    float* sHU = sh + 38400;

    int tid = threadIdx.x;
    for (int i = tid; i < 2560 / 4;  i += 512) ((float4*)sW0)[i] = ((const float4*)W0g)[i];
    for (int i = tid; i < 8192 / 4;  i += 512) ((float4*)sW1)[i] = ((const float4*)W1g)[i];
    for (int i = tid; i < 16384 / 4; i += 512) ((float4*)sW2)[i] = ((const float4*)W2g)[i];

    int lane = tid & 31, w = tid >> 5;
    int og = (w & 3) * 4 + (lane & 3);
    int eg = (w >> 2) * 8 + (lane >> 2);

    auto stage = [&](long t, int b) {
        float* dst = sX + b * 5632;
        for (int i = tid; i < 1280; i += 512) {
            int e_l = i / 10, ks = (i % 10) * 4;
            cpa16(dst + e_l * 44 + ks, g_X0 + (t * 128 + e_l) * 40 + ks);
        }
        cp_commit();
    };

    long t0 = blockIdx.x;
    if (t0 < ntiles) stage(t0, 0);
    int b = 0;

    for (long t = t0; t < ntiles; t += gridDim.x) {
        long nt = t + gridDim.x;
        bool hn = nt < ntiles;
        __syncthreads();
        if (hn) stage(nt, b ^ 1);
        if (hn) cp_wait1(); else cp_wait0();
        __syncthreads();

        {
            const float* Xb = sX + b * 5632;
            ULL acc[4][2];
#pragma unroll
            for (int j = 0; j < 4; j++) { acc[j][0] = 0ULL; acc[j][1] = 0ULL; }
            const float* xr[4];
#pragma unroll
            for (int j = 0; j < 4; j++) xr[j] = Xb + (eg + 32 * j) * 44;
#pragma unroll 2
            for (int k4 = 0; k4 < 40; k4 += 4) {
                float4 xv[4];
#pragma unroll
                for (int j = 0; j < 4; j++) xv[j] = *(const float4*)(xr[j] + k4);
#pragma unroll
                for (int kk = 0; kk < 4; kk++) {
                    const float* wr = sW0 + (k4 + kk) * 64 + og * 4;
                    ULL w0 = *(const ULL*)wr, w1 = *(const ULL*)(wr + 2);
#pragma unroll
                    for (int j = 0; j < 4; j++) {
                        float xs = (kk == 0) ? xv[j].x : (kk == 1) ? xv[j].y
                                 : (kk == 2) ? xv[j].z : xv[j].w;
                        ULL xd = pack2(xs);
                        acc[j][0] = fma2(xd, w0, acc[j][0]);
                        acc[j][1] = fma2(xd, w1, acc[j][1]);
                    }
                }
            }
#pragma unroll
            for (int j = 0; j < 4; j++) {
                union { ULL u; float2 f; } c0, c1;
                c0.u = acc[j][0]; c1.u = acc[j][1];
                *(float4*)(sHU + (eg + 32 * j) * 68 + og * 4) =
                    make_float4(silu_f(c0.f.x * F_RS40), silu_f(c0.f.y * F_RS40),
                                silu_f(c1.f.x * F_RS40), silu_f(c1.f.y * F_RS40));
            }
        }
        __syncthreads();

        {
            ULL acc[4][4];
#pragma unroll
            for (int j = 0; j < 4; j++)
#pragma unroll
                for (int p = 0; p < 4; p++) acc[j][p] = 0ULL;
            const float* xr[4];
#pragma unroll
            for (int j = 0; j < 4; j++) xr[j] = sHU + (eg + 32 * j) * 68;
#pragma unroll 2
            for (int k4 = 0; k4 < 64; k4 += 4) {
                float4 xv[4];
#pragma unroll
                for (int j = 0; j < 4; j++) xv[j] = *(const float4*)(xr[j] + k4);
#pragma unroll
                for (int kk = 0; kk < 4; kk++) {
                    const float* wr = sW1 + (k4 + kk) * 128 + og * 8;
                    ulonglong2 wa = *(const ulonglong2*)wr;
                    ulonglong2 wb = *(const ulonglong2*)(wr + 4);
#pragma unroll
                    for (int j = 0; j < 4; j++) {
                        float xs = (kk == 0) ? xv[j].x : (kk == 1) ? xv[j].y
                                 : (kk == 2) ? xv[j].z : xv[j].w;
                        ULL xd = pack2(xs);
                        acc[j][0] = fma2(xd, wa.x, acc[j][0]);
                        acc[j][1] = fma2(xd, wa.y, acc[j][1]);
                        acc[j][2] = fma2(xd, wb.x, acc[j][2]);
                        acc[j][3] = fma2(xd, wb.y, acc[j][3]);
                    }
                }
            }
            __syncthreads();
#pragma unroll
            for (int j = 0; j < 4; j++) {
                float* hr = sHU + (eg + 32 * j) * 132 + og * 8;
                union { ULL u; float2 f; } c0, c1, c2, c3;
                c0.u = acc[j][0]; c1.u = acc[j][1]; c2.u = acc[j][2]; c3.u = acc[j][3];
                *(float4*)hr =
                    make_float4(silu_f(c0.f.x * F_RS64), silu_f(c0.f.y * F_RS64),
                                silu_f(c1.f.x * F_RS64), silu_f(c1.f.y * F_RS64));
                *(float4*)(hr + 4) =
                    make_float4(silu_f(c2.f.x * F_RS64), silu_f(c2.f.y * F_RS64),
                                silu_f(c3.f.x * F_RS64), silu_f(c3.f.y * F_RS64));
            }
        }
        __syncthreads();

        {
            ULL acc[4][4];
#pragma unroll
            for (int j = 0; j < 4; j++)
#pragma unroll
                for (int p = 0; p < 4; p++) acc[j][p] = 0ULL;
            const float* xr[4];
#pragma unroll
            for (int j = 0; j < 4; j++) xr[j] = sHU + (eg + 32 * j) * 132;
#pragma unroll 2
            for (int k4 = 0; k4 < 128; k4 += 4) {
                float4 xv[4];
#pragma unroll
                for (int j = 0; j < 4; j++) xv[j] = *(const float4*)(xr[j] + k4);
#pragma unroll
                for (int kk = 0; kk < 4; kk++) {
                    const float* wr = sW2 + (k4 + kk) * 128 + og * 8;
                    ulonglong2 wa = *(const ulonglong2*)wr;
                    ulonglong2 wb = *(const ulonglong2*)(wr + 4);
#pragma unroll
                    for (int j = 0; j < 4; j++) {
                        float xs = (kk == 0) ? xv[j].x : (kk == 1) ? xv[j].y
                                 : (kk == 2) ? xv[j].z : xv[j].w;
                        ULL xd = pack2(xs);
                        acc[j][0] = fma2(xd, wa.x, acc[j][0]);
                        acc[j][1] = fma2(xd, wa.y, acc[j][1]);
                        acc[j][2] = fma2(xd, wb.x, acc[j][2]);
                        acc[j][3] = fma2(xd, wb.y, acc[j][3]);
                    }
                }
            }
#pragma unroll
            for (int j = 0; j < 4; j++) {
                long e = t * 128 + eg + 32 * j;
                float s = F_RS128 * g_fcut[e];
                union { ULL u; float2 f; } c0, c1, c2, c3;
                c0.u = acc[j][0]; c1.u = acc[j][1]; c2.u = acc[j][2]; c3.u = acc[j][3];
                *(float4*)(g_lat + e * 128 + og * 8) =
                    make_float4(c0.f.x * s, c0.f.y * s, c1.f.x * s, c1.f.y * s);
                *(float4*)(g_lat + e * 128 + og * 8 + 4) =
                    make_float4(c2.f.x * s, c2.f.y * s, c3.f.x * s, c3.f.y * s);
            }
        }
        b ^= 1;
    }
}

// ---------------------------------------------------------------------------
__global__ void k_zero(float* __restrict__ out)
{
    int i = blockIdx.x * blockDim.x + threadIdx.x;
    int stride = gridDim.x * blockDim.x;
    for (; i < NN * 128; i += stride) {
        g_env[i]  = 0.0f;
        g_env1[i] = 0.0f;
        out[i]    = 0.0f;
    }
}

__global__ void __launch_bounds__(512) kgeo(
    const float* __restrict__ coords, const float* __restrict__ attrs,
    const int* __restrict__ eidx)
{
    int e = blockIdx.x * 512 + threadIdx.x;
    if (e >= NE) return;
    int snd = eidx[e];
    int c   = eidx[NE + e];
    float dx = coords[c * 3 + 0] - coords[snd * 3 + 0];
    float dy = coords[c * 3 + 1] - coords[snd * 3 + 1];
    float dz = coords[c * 3 + 2] - coords[snd * 3 + 2];
    float r2 = dx * dx + dy * dy + dz * dz + 1e-12f;
    float r  = sqrtf(r2);
    float inv_r = 1.0f / r;
    float u  = r * F_INV_RMAX;
    float u2 = u * u, u3 = u2 * u, u6 = u3 * u3, u7 = u6 * u, u8 = u7 * u;
    float f  = 1.0f - 28.0f * u6 + 48.0f * u7 - 21.0f * u8;
    if (u >= 1.0f) f = 0.0f;
    g_fcut[e] = f;
    *(float4*)(g_Y + e * 4) = make_float4(1.0f, F_SQRT3 * dx * inv_r,
                                          F_SQRT3 * dy * inv_r, F_SQRT3 * dz * inv_r);
    float* X = g_X0 + (long)e * 40;
    const float4* ac = (const float4*)(attrs + c * 16);
    const float4* as = (const float4*)(attrs + snd * 16);
#pragma unroll
    for (int i = 0; i < 4; i++) ((float4*)X)[i] = ac[i];
#pragma unroll
    for (int i = 0; i < 4; i++) ((float4*)(X + 16))[i] = as[i];
    float bi = inv_r * f * F_BESSEL;
#pragma unroll
    for (int n = 0; n < 8; n++)
        X[32 + n] = bi * sinf((n + 1) * F_PI * u);
}

__global__ void __launch_bounds__(256) kp1(const int* __restrict__ eidx)
{
    int warp = (blockIdx.x * 256 + threadIdx.x) >> 5;
    int lane = threadIdx.x & 31;
    int nw = gridDim.x * 8;
    for (long e = warp; e < NE; e += nw) {
        long c = eidx[NE + e];
        float2 we = *(const float2*)(g_wedge + e * 64 + 2 * lane);
        float4 en = *(const float4*)(g_env + c * 128 + 4 * lane);
        float4 Y  = *(const float4*)(g_Y + e * 4);
        float fs  = we.x;
        float fv0 = we.y * Y.y, fv1 = we.y * Y.z, fv2 = we.y * Y.w;
        float es  = en.x * F_ISN;
        float ev0 = en.y * F_ISN, ev1 = en.z * F_ISN, ev2 = en.w * F_ISN;
        g_scal0[e * 64 + lane]      = fs * es;
        g_scal0[e * 64 + 32 + lane] = (fv0 * ev0 + fv1 * ev1 + fv2 * ev2) * F_INV_SQRT3;
        float* P0 = g_P + (3 * e + 0) * 96;
        float* P1 = g_P + (3 * e + 1) * 96;
        float* P2 = g_P + (3 * e + 2) * 96;
        P0[lane] = fs * ev0;  P1[lane] = fs * ev1;  P2[lane] = fs * ev2;
        P0[32 + lane] = fv0 * es; P1[32 + lane] = fv1 * es; P2[32 + lane] = fv2 * es;
        P0[64 + lane] = (fv1 * ev2 - fv2 * ev1) * F_INV_SQRT2;
        P1[64 + lane] = (fv2 * ev0 - fv0 * ev2) * F_INV_SQRT2;
        P2[64 + lane] = (fv0 * ev1 - fv1 * ev0) * F_INV_SQRT2;
    }
}

__global__ void __launch_bounds__(256) kp2(const int* __restrict__ eidx)
{
    int warp = (blockIdx.x * 256 + threadIdx.x) >> 5;
    int lane = threadIdx.x & 31;
    int nw = gridDim.x * 8;
    for (long e = warp; e < NE; e += nw) {
        long c = eidx[NE + e];
        float4 e1 = *(const float4*)(g_env1 + c * 128 + 4 * lane);
        float sm = g_smix[e * 32 + lane];
        float v0 = g_vmx[(3 * e + 0) * 32 + lane];
        float v1 = g_vmx[(3 * e + 1) * 32 + lane];
        float v2 = g_vmx[(3 * e + 2) * 32 + lane];
        g_q[e * 64 + lane] = sm * e1.x * F_ISN;
        g_q[e * 64 + 32 + lane] =
            (v0 * e1.y + v1 * e1.z + v2 * e1.w) * F_ISN * F_INV_SQRT3;
    }
}

// ---------------------------------------------------------------------------
extern "C" void kernel_launch(void* const* d_in, const int* in_sizes, int n_in,
                              void* d_out, int out_size)
{
    const float* coords = (const float*)d_in[0];
    const float* attrs  = (const float*)d_in[1];
    const int*   eidx   = (const int*)  d_in[2];
    const float* W2b0   = (const float*)d_in[3];
    const float* W2b1   = (const float*)d_in[4];
    const float* W2b2   = (const float*)d_in[5];
    const float* Wenv0  = (const float*)d_in[6];
    const float* Wlat0  = (const float*)d_in[7];
    const float* Wlat1  = (const float*)d_in[8];
    const float* Ws0    = (const float*)d_in[9];
    const float* Wv0    = (const float*)d_in[10];
    const float* Wenv1  = (const float*)d_in[11];
    const float* Wfin0  = (const float*)d_in[12];
    const float* Wfin1  = (const float*)d_in[13];
    float* out = (float*)d_out;
    const int* ctr = eidx + NE;

    const size_t sm_k123   = (2560 + 8192 + 16384 + 11264 + 16896) * 4;
    const size_t sm2_64    = (8192  + 2 * 64 * 68) * 4;
    const size_t sm64_32   = (2048 + 2 * 128 * 68) * 4;
    const size_t sm96_32   = (3072 + 2 * 128 * 100) * 4;
    const size_t sm_t2     = (size_t)(2 * 64 * 64 + 2 * 128 * 64) * 4;  // 98304
    const size_t sm_t192   = (size_t)4 * 128 * 96 * 4;                  // 196608

    cudaFuncSetAttribute(k123, cudaFuncAttributeMaxDynamicSharedMemorySize, (int)sm_k123);
    cudaFuncSetAttribute(tkm2<128, OpG4T>,  cudaFuncAttributeMaxDynamicSharedMemorySize, (int)sm_t2);
    cudaFuncSetAttribute(tkm<192, OpG7T>,   cudaFuncAttributeMaxDynamicSharedMemorySize, (int)sm_t192);
    cudaFuncSetAttribute(tkm2<128, OpG8T>,  cudaFuncAttributeMaxDynamicSharedMemorySize, (int)sm_t2);
    cudaFuncSetAttribute(tkm<192, OpG10T>,  cudaFuncAttributeMaxDynamicSharedMemorySize, (int)sm_t192);
    cudaFuncSetAttribute(tkm2<128, OpG11T>, cudaFuncAttributeMaxDynamicSharedMemorySize, (int)sm_t2);
    cudaFuncSetAttribute(gk<64, 64, 32, 4, OpG5>, cudaFuncAttributeMaxDynamicSharedMemorySize, (int)sm64_32);
    cudaFuncSetAttribute(gk<96, 96, 32, 4, OpG6>, cudaFuncAttributeMaxDynamicSharedMemorySize, (int)sm96_32);
    cudaFuncSetAttribute(gk2<128, 64, 64, 4, OpG9>, cudaFuncAttributeMaxDynamicSharedMemorySize, (int)sm2_64);

    const int NT   = NE / 128;   // 2500
    const int NT64 = NE / 64;    // 5000
    const int NT3  = NE3 / 128;  // 7500

    k_zero<<<512, 256>>>(out);
    kgeo<<<(NE + 511) / 512, 512>>>(coords, attrs, eidx);

    k123<<<148, 512, sm_k123>>>(W2b0, W2b1, W2b2, NT);
    tkm2<128, OpG4T><<<296, 256, sm_t2>>>(OpG4T{ctr}, Wenv0, NT64);
    kp1<<<2560, 256>>>(eidx);
    gk<64, 64, 32, 4, OpG5><<<148, 512, sm64_32>>>(OpG5{}, Ws0, NT);
    gk<96, 96, 32, 4, OpG6><<<148, 512, sm96_32>>>(OpG6{}, Wv0, NT3);
    tkm<192, OpG7T><<<148, 512, sm_t192>>>(OpG7T{}, Wlat0, NT);
    tkm2<128, OpG8T><<<296, 256, sm_t2>>>(OpG8T{}, Wlat1, NT64);
    gk2<128, 64, 64, 4, OpG9><<<296, 256, sm2_64>>>(OpG9{ctr}, Wenv1, NT64);
    kp2<<<2560, 256>>>(eidx);
    tkm<192, OpG10T><<<148, 512, sm_t192>>>(OpG10T{}, Wfin0, NT);
    tkm2<128, OpG11T><<<296, 256, sm_t2>>>(OpG11T{ctr, out}, Wfin1, NT64);
}

// round 16
// speedup vs baseline: 1.6764x; 1.0627x over previous
#include <cuda_runtime.h>
#include <cuda_bf16.h>

// ---------------------------------------------------------------------------
// Allegro GNN layer.
//   tkm  : warp mma.sync bf16-split GEMM, K=192, 512 thr (G7/G10)
//   tkm2 : same, BM=64, 256 thr, 2 CTAs/SM, K=128 (G4/G8/G11)
//   kpv  : FUSED products+vmix — P[384x96] built as bf16 hi/lo in smem
//          (shfl pair packing), contracted @Wv0 by mma. P never hits HBM.
//   gk/gk2 FFMA2 (G5, G9), k123, kgeo, kp2 as in R15.
// ---------------------------------------------------------------------------

#define NN 10000
#define NE 320000
#define NE3 960000
typedef unsigned long long ULL;
typedef unsigned int U32;

__device__ float g_X0  [NE * 40];
__device__ float g_H   [NE * 128];
__device__ float g_lat [NE * 128];
__device__ float g_wedge[NE * 64];
__device__ float g_scal0[NE * 64];
__device__ float g_smix[NE * 32];
__device__ float g_vmx [NE3 * 32];
__device__ float g_q   [NE * 64];
__device__ float g_Y   [NE * 4];
__device__ float g_fcut[NE];
__device__ float g_env [NN * 128];
__device__ float g_env1[NN * 128];

#define F_RS40      0.15811388300841897f
#define F_RS64      0.125f
#define F_RS96      0.10206207261596575f
#define F_RS128     0.08838834764831845f
#define F_RS192     0.07216878364870323f
#define F_ISN       0.17677669529663689f
#define F_SQRT3     1.7320508075688772f
#define F_INV_SQRT3 0.5773502691896258f
#define F_INV_SQRT2 0.7071067811865476f
#define F_C_OLD     0.8944271909999159f
#define F_C_NEW     0.4472135954999579f
#define F_BESSEL    0.6324555320336759f
#define F_PI        3.14159265358979323846f
#define F_INV_RMAX  0.2f

__device__ __forceinline__ ULL fma2(ULL a, ULL b, ULL c) {
    ULL d;
    asm("fma.rn.f32x2 %0, %1, %2, %3;" : "=l"(d) : "l"(a), "l"(b), "l"(c));
    return d;
}
__device__ __forceinline__ ULL pack2(float x) {
    ULL d; unsigned u = __float_as_uint(x);
    asm("mov.b64 %0, {%1,%1};" : "=l"(d) : "r"(u));
    return d;
}
__device__ __forceinline__ void red4(float* p, float a, float b, float c, float d) {
    asm volatile("red.global.add.v4.f32 [%0], {%1,%2,%3,%4};"
                 :: "l"(p), "f"(a), "f"(b), "f"(c), "f"(d) : "memory");
}
__device__ __forceinline__ void red2(float* p, float a, float b) {
    asm volatile("red.global.add.v2.f32 [%0], {%1,%2};"
                 :: "l"(p), "f"(a), "f"(b) : "memory");
}
__device__ __forceinline__ float silu_f(float v) {
    return v * __frcp_rn(1.0f + __expf(-v));
}
__device__ __forceinline__ void cpa16(const void* s, const void* g) {
    unsigned sa = (unsigned)__cvta_generic_to_shared(s);
    asm volatile("cp.async.cg.shared.global [%0], [%1], 16;" :: "r"(sa), "l"(g));
}
__device__ __forceinline__ void cp_commit() { asm volatile("cp.async.commit_group;"); }
__device__ __forceinline__ void cp_wait1()  { asm volatile("cp.async.wait_group 1;"); }
__device__ __forceinline__ void cp_wait0()  { asm volatile("cp.async.wait_group 0;"); }

__device__ __forceinline__ void mma16816(float* d, const U32* a, const U32* b) {
    asm volatile(
        "mma.sync.aligned.m16n8k16.row.col.f32.bf16.bf16.f32 "
        "{%0,%1,%2,%3}, {%4,%5,%6,%7}, {%8,%9}, {%0,%1,%2,%3};"
        : "+f"(d[0]), "+f"(d[1]), "+f"(d[2]), "+f"(d[3])
        : "r"(a[0]), "r"(a[1]), "r"(a[2]), "r"(a[3]), "r"(b[0]), "r"(b[1]));
}
__device__ __forceinline__ void bsplit8(const float* xs, uint4& hi, uint4& lo) {
    unsigned h[4], l[4];
#pragma unroll
    for (int p = 0; p < 4; p++) {
        __nv_bfloat16 h0 = __float2bfloat16(xs[2 * p]);
        __nv_bfloat16 h1 = __float2bfloat16(xs[2 * p + 1]);
        __nv_bfloat16 l0 = __float2bfloat16(xs[2 * p] - __bfloat162float(h0));
        __nv_bfloat16 l1 = __float2bfloat16(xs[2 * p + 1] - __bfloat162float(h1));
        h[p] = (unsigned)__bfloat16_as_ushort(h0) |
               ((unsigned)__bfloat16_as_ushort(h1) << 16);
        l[p] = (unsigned)__bfloat16_as_ushort(l0) |
               ((unsigned)__bfloat16_as_ushort(l1) << 16);
    }
    hi = make_uint4(h[0], h[1], h[2], h[3]);
    lo = make_uint4(l[0], l[1], l[2], l[3]);
}
__device__ __forceinline__ int pidx(int row, int p, int KH) {
    return row * KH + (p ^ ((row & 7) << 2));
}

// ---------------------------------------------------------------------------
// tkm: warp mma bf16-split GEMM.  BM=128, OUT=128, 512 thr (K=192).
// ---------------------------------------------------------------------------
template <int K, class Op>
__global__ void __launch_bounds__(512, 1) tkm(Op op, const float* __restrict__ Wg,
                                              int ntiles)
{
    constexpr int KH = K / 2;
    constexpr int KB = K / 8;
    extern __shared__ __align__(16) U32 su[];
    U32* AH = su;
    U32* AL = AH + 128 * KH;
    U32* BH = AL + 128 * KH;
    U32* BL = BH + 128 * KH;

    int tid = threadIdx.x, lane = tid & 31, w = tid >> 5;
    int g = lane >> 2, tg = lane & 3;
    int wm = w & 3, wn = w >> 2;

    for (int i = tid; i < 128 * KB; i += 512) {
        int n = i / KB, kb = (i % KB) * 8;
        float xs[8];
#pragma unroll
        for (int j = 0; j < 8; j++) xs[j] = Wg[(kb + j) * 128 + n];
        uint4 hi, lo; bsplit8(xs, hi, lo);
        int p4 = ((kb >> 1) ^ ((n & 7) << 2));
        *(uint4*)&BH[n * KH + p4] = hi;
        *(uint4*)&BL[n * KH + p4] = lo;
    }
    __syncthreads();

    for (long t = blockIdx.x; t < ntiles; t += gridDim.x) {
        for (int i = tid; i < 128 * KB; i += 512) {
            int m = i / KB, kb = (i % KB) * 8;
            const float* s = op.src(t * 128 + m, kb);
            float4 x0 = *(const float4*)s, x1 = *(const float4*)(s + 4);
            float xs[8] = {x0.x, x0.y, x0.z, x0.w, x1.x, x1.y, x1.z, x1.w};
            uint4 hi, lo; bsplit8(xs, hi, lo);
            int p4 = ((kb >> 1) ^ ((m & 7) << 2));
            *(uint4*)&AH[m * KH + p4] = hi;
            *(uint4*)&AL[m * KH + p4] = lo;
        }
        __syncthreads();

        float acc[2][4][4];
#pragma unroll
        for (int mt = 0; mt < 2; mt++)
#pragma unroll
            for (int nt = 0; nt < 4; nt++)
#pragma unroll
                for (int q = 0; q < 4; q++) acc[mt][nt][q] = 0.0f;

#pragma unroll 2
        for (int ks = 0; ks < K / 16; ks++) {
            int pb = ks * 8;
            U32 ah[2][4], al[2][4];
#pragma unroll
            for (int mt = 0; mt < 2; mt++) {
                int r0 = wm * 32 + mt * 16 + g;
                ah[mt][0] = AH[pidx(r0,     pb + tg,     KH)];
                ah[mt][1] = AH[pidx(r0 + 8, pb + tg,     KH)];
                ah[mt][2] = AH[pidx(r0,     pb + tg + 4, KH)];
                ah[mt][3] = AH[pidx(r0 + 8, pb + tg + 4, KH)];
                al[mt][0] = AL[pidx(r0,     pb + tg,     KH)];
                al[mt][1] = AL[pidx(r0 + 8, pb + tg,     KH)];
                al[mt][2] = AL[pidx(r0,     pb + tg + 4, KH)];
                al[mt][3] = AL[pidx(r0 + 8, pb + tg + 4, KH)];
            }
            U32 bh[4][2], bl[4][2];
#pragma unroll
            for (int nt = 0; nt < 4; nt++) {
                int n = wn * 32 + nt * 8 + g;
                bh[nt][0] = BH[pidx(n, pb + tg,     KH)];
                bh[nt][1] = BH[pidx(n, pb + tg + 4, KH)];
                bl[nt][0] = BL[pidx(n, pb + tg,     KH)];
                bl[nt][1] = BL[pidx(n, pb + tg + 4, KH)];
            }
#pragma unroll
            for (int mt = 0; mt < 2; mt++)
#pragma unroll
                for (int nt = 0; nt < 4; nt++) {
                    mma16816(acc[mt][nt], ah[mt], bh[nt]);
                    mma16816(acc[mt][nt], ah[mt], bl[nt]);
                    mma16816(acc[mt][nt], al[mt], bh[nt]);
                }
        }

#pragma unroll
        for (int mt = 0; mt < 2; mt++) {
            int r0 = wm * 32 + mt * 16 + g;
#pragma unroll
            for (int nt = 0; nt < 4; nt++) {
                int col = wn * 32 + nt * 8 + tg * 2;
                op.epi2(t * 128 + r0,     col, acc[mt][nt][0], acc[mt][nt][1]);
                op.epi2(t * 128 + r0 + 8, col, acc[mt][nt][2], acc[mt][nt][3]);
            }
        }
        __syncthreads();
    }
}

// ---------------------------------------------------------------------------
// tkm2: BM=64, 256 thr, 2 CTAs/SM (K=128: G4/G8/G11)
// ---------------------------------------------------------------------------
template <int K, class Op>
__global__ void __launch_bounds__(256, 2) tkm2(Op op, const float* __restrict__ Wg,
                                               int ntiles)
{
    constexpr int KH = K / 2;
    constexpr int KB = K / 8;
    extern __shared__ __align__(16) U32 su[];
    U32* AH = su;
    U32* AL = AH + 64 * KH;
    U32* BH = AL + 64 * KH;
    U32* BL = BH + 128 * KH;

    int tid = threadIdx.x, lane = tid & 31, w = tid >> 5;
    int g = lane >> 2, tg = lane & 3;
    int wm = w & 1, wn = w >> 1;

    for (int i = tid; i < 128 * KB; i += 256) {
        int n = i / KB, kb = (i % KB) * 8;
        float xs[8];
#pragma unroll
        for (int j = 0; j < 8; j++) xs[j] = Wg[(kb + j) * 128 + n];
        uint4 hi, lo; bsplit8(xs, hi, lo);
        int p4 = ((kb >> 1) ^ ((n & 7) << 2));
        *(uint4*)&BH[n * KH + p4] = hi;
        *(uint4*)&BL[n * KH + p4] = lo;
    }
    __syncthreads();

    for (long t = blockIdx.x; t < ntiles; t += gridDim.x) {
        for (int i = tid; i < 64 * KB; i += 256) {
            int m = i / KB, kb = (i % KB) * 8;
            const float* s = op.src(t * 64 + m, kb);
            float4 x0 = *(const float4*)s, x1 = *(const float4*)(s + 4);
            float xs[8] = {x0.x, x0.y, x0.z, x0.w, x1.x, x1.y, x1.z, x1.w};
            uint4 hi, lo; bsplit8(xs, hi, lo);
            int p4 = ((kb >> 1) ^ ((m & 7) << 2));
            *(uint4*)&AH[m * KH + p4] = hi;
            *(uint4*)&AL[m * KH + p4] = lo;
        }
        __syncthreads();

        float acc[2][4][4];
#pragma unroll
        for (int mt = 0; mt < 2; mt++)
#pragma unroll
            for (int nt = 0; nt < 4; nt++)
#pragma unroll
                for (int q = 0; q < 4; q++) acc[mt][nt][q] = 0.0f;

#pragma unroll 2
        for (int ks = 0; ks < K / 16; ks++) {
            int pb = ks * 8;
            U32 ah[2][4], al[2][4];
#pragma unroll
            for (int mt = 0; mt < 2; mt++) {
                int r0 = wm * 32 + mt * 16 + g;
                ah[mt][0] = AH[pidx(r0,     pb + tg,     KH)];
                ah[mt][1] = AH[pidx(r0 + 8, pb + tg,     KH)];
                ah[mt][2] = AH[pidx(r0,     pb + tg + 4, KH)];
                ah[mt][3] = AH[pidx(r0 + 8, pb + tg + 4, KH)];
                al[mt][0] = AL[pidx(r0,     pb + tg,     KH)];
                al[mt][1] = AL[pidx(r0 + 8, pb + tg,     KH)];
                al[mt][2] = AL[pidx(r0,     pb + tg + 4, KH)];
                al[mt][3] = AL[pidx(r0 + 8, pb + tg + 4, KH)];
            }
            U32 bh[4][2], bl[4][2];
#pragma unroll
            for (int nt = 0; nt < 4; nt++) {
                int n = wn * 32 + nt * 8 + g;
                bh[nt][0] = BH[pidx(n, pb + tg,     KH)];
                bh[nt][1] = BH[pidx(n, pb + tg + 4, KH)];
                bl[nt][0] = BL[pidx(n, pb + tg,     KH)];
                bl[nt][1] = BL[pidx(n, pb + tg + 4, KH)];
            }
#pragma unroll
            for (int mt = 0; mt < 2; mt++)
#pragma unroll
                for (int nt = 0; nt < 4; nt++) {
                    mma16816(acc[mt][nt], ah[mt], bh[nt]);
                    mma16816(acc[mt][nt], ah[mt], bl[nt]);
                    mma16816(acc[mt][nt], al[mt], bh[nt]);
                }
        }

#pragma unroll
        for (int mt = 0; mt < 2; mt++) {
            int r0 = wm * 32 + mt * 16 + g;
#pragma unroll
            for (int nt = 0; nt < 4; nt++) {
                int col = wn * 32 + nt * 8 + tg * 2;
                op.epi2(t * 64 + r0,     col, acc[mt][nt][0], acc[mt][nt][1]);
                op.epi2(t * 64 + r0 + 8, col, acc[mt][nt][2], acc[mt][nt][3]);
            }
        }
        __syncthreads();
    }
}

// ---------------------------------------------------------------------------
// kpv: fused products + vmix.  512 thr, per tile: 128 edges -> P[384][96]
// bf16 hi/lo in smem (pitch-49 pair layout) -> @Wv0 via mma -> g_vmx.
// Also writes g_scal0.  P never touches global memory.
// ---------------------------------------------------------------------------
#define KPV_PITCH 49
__device__ __forceinline__ void kpv_pack(U32* AH, U32* AL, int r, int blk,
                                         float v, int lane)
{
    __nv_bfloat16 hb = __float2bfloat16(v);
    float lof = v - __bfloat162float(hb);
    __nv_bfloat16 lb = __float2bfloat16(lof);
    U32 h = (U32)__bfloat16_as_ushort(hb);
    U32 l = (U32)__bfloat16_as_ushort(lb);
    U32 hn = __shfl_down_sync(0xffffffffu, h, 1);
    U32 ln = __shfl_down_sync(0xffffffffu, l, 1);
    if (!(lane & 1)) {
        int p = blk * 16 + (lane >> 1);
        AH[r * KPV_PITCH + p] = h | (hn << 16);
        AL[r * KPV_PITCH + p] = l | (ln << 16);
    }
}

__global__ void __launch_bounds__(512, 1) kpv(
    const int* __restrict__ ctr, const float* __restrict__ Wv, int ntiles)
{
    extern __shared__ __align__(16) U32 su[];
    U32* AH = su;                        // 384*49
    U32* AL = AH + 384 * KPV_PITCH;
    U32* BH = AL + 384 * KPV_PITCH;      // 32*49
    U32* BL = BH + 32 * KPV_PITCH;

    int tid = threadIdx.x, lane = tid & 31, w = tid >> 5;
    int g = lane >> 2, tg = lane & 3;

    // B = Wv^T (Wv is [96][32]) -> bf16 hi/lo, pitch-49 pairs
    for (int i = tid; i < 32 * 12; i += 512) {
        int n = i / 12, kb = (i % 12) * 8;
        float xs[8];
#pragma unroll
        for (int j = 0; j < 8; j++) xs[j] = Wv[(kb + j) * 32 + n];
        uint4 hi, lo; bsplit8(xs, hi, lo);
        U32* hp = &BH[n * KPV_PITCH + (kb >> 1)];
        U32* lp = &BL[n * KPV_PITCH + (kb >> 1)];
        hp[0] = hi.x; hp[1] = hi.y; hp[2] = hi.z; hp[3] = hi.w;
        lp[0] = lo.x; lp[1] = lo.y; lp[2] = lo.z; lp[3] = lo.w;
    }
    __syncthreads();

    for (long t = blockIdx.x; t < ntiles; t += gridDim.x) {
        long e0 = t * 128;
        // build phase: warp w handles edges e0 + 8w .. +7; lane = channel m
#pragma unroll 2
        for (int j = 0; j < 8; j++) {
            int  el = w * 8 + j;
            long e  = e0 + el;
            long c  = ctr[e];
            float2 we = *(const float2*)(g_wedge + e * 64 + 2 * lane);
            float4 en = *(const float4*)(g_env + c * 128 + 4 * lane);
            float4 Y  = *(const float4*)(g_Y + e * 4);
            float fs  = we.x;
            float fv0 = we.y * Y.y, fv1 = we.y * Y.z, fv2 = we.y * Y.w;
            float es  = en.x * F_ISN;
            float ev0 = en.y * F_ISN, ev1 = en.z * F_ISN, ev2 = en.w * F_ISN;
            g_scal0[e * 64 + lane]      = fs * es;
            g_scal0[e * 64 + 32 + lane] =
                (fv0 * ev0 + fv1 * ev1 + fv2 * ev2) * F_INV_SQRT3;
            int r = 3 * el;
            kpv_pack(AH, AL, r + 0, 0, fs * ev0, lane);
            kpv_pack(AH, AL, r + 1, 0, fs * ev1, lane);
            kpv_pack(AH, AL, r + 2, 0, fs * ev2, lane);
            kpv_pack(AH, AL, r + 0, 1, fv0 * es, lane);
            kpv_pack(AH, AL, r + 1, 1, fv1 * es, lane);
            kpv_pack(AH, AL, r + 2, 1, fv2 * es, lane);
            kpv_pack(AH, AL, r + 0, 2, (fv1 * ev2 - fv2 * ev1) * F_INV_SQRT2, lane);
            kpv_pack(AH, AL, r + 1, 2, (fv2 * ev0 - fv0 * ev2) * F_INV_SQRT2, lane);
            kpv_pack(AH, AL, r + 2, 2, (fv0 * ev1 - fv1 * ev0) * F_INV_SQRT2, lane);
        }
        __syncthreads();

        // mma phase: [384][96] @ [96][32]; warp w -> m-tiles {w, w+16}
#pragma unroll
        for (int mt = 0; mt < 2; mt++) {
            if (mt == 1 && w >= 8) break;
            int r0 = mt * 256 + w * 16 + g;
            float acc[4][4];
#pragma unroll
            for (int nt = 0; nt < 4; nt++)
#pragma unroll
                for (int q = 0; q < 4; q++) acc[nt][q] = 0.0f;

#pragma unroll
            for (int ks = 0; ks < 6; ks++) {
                int pb = ks * 8;
                U32 ah[4], al[4];
                ah[0] = AH[(r0)     * KPV_PITCH + pb + tg];
                ah[1] = AH[(r0 + 8) * KPV_PITCH + pb + tg];
                ah[2] = AH[(r0)     * KPV_PITCH + pb + tg + 4];
                ah[3] = AH[(r0 + 8) * KPV_PITCH + pb + tg + 4];
                al[0] = AL[(r0)     * KPV_PITCH + pb + tg];
                al[1] = AL[(r0 + 8) * KPV_PITCH + pb + tg];
                al[2] = AL[(r0)     * KPV_PITCH + pb + tg + 4];
                al[3] = AL[(r0 + 8) * KPV_PITCH + pb + tg + 4];
#pragma unroll
                for (int nt = 0; nt < 4; nt++) {
                    int n = nt * 8 + g;
                    U32 bh[2] = { BH[n * KPV_PITCH + pb + tg],
                                  BH[n * KPV_PITCH + pb + tg + 4] };
                    U32 bl[2] = { BL[n * KPV_PITCH + pb + tg],
                                  BL[n * KPV_PITCH + pb + tg + 4] };
                    mma16816(acc[nt], ah, bh);
                    mma16816(acc[nt], ah, bl);
                    mma16816(acc[nt], al, bh);
                }
            }

            long rg = t * 384 + r0;
#pragma unroll
            for (int nt = 0; nt < 4; nt++) {
                int col = nt * 8 + tg * 2;
                *(float2*)(g_vmx + rg * 32 + col) =
                    make_float2(acc[nt][0] * F_RS96, acc[nt][1] * F_RS96);
                *(float2*)(g_vmx + (rg + 8) * 32 + col) =
                    make_float2(acc[nt][2] * F_RS96, acc[nt][3] * F_RS96);
            }
        }
        __syncthreads();
    }
}

// ---------------------------------------------------------------------------
// Streaming FFMA2 GEMM, 512 threads (G5)
// ---------------------------------------------------------------------------
template <int KTOT, int KC, int OUT, int OPO, class Op>
__global__ void __launch_bounds__(512, 1) gk(Op op, const float* __restrict__ Wg,
                                             int ntiles)
{
    constexpr int PC  = KC + 4;
    constexpr int NCH = KTOT / KC;
    constexpr int OG  = OUT / OPO;
    constexpr int OGW = OG / 4;
    constexpr int EGN = 512 / OG;
    constexpr int EPT = 128 / EGN;
    constexpr int NP  = OPO / 2;

    extern __shared__ __align__(16) float sh[];
    float* sW = sh;
    float* sX = sh + KTOT * OUT;

    int tid = threadIdx.x;
    for (int i = tid; i < KTOT * OUT / 4; i += 512)
        ((float4*)sW)[i] = ((const float4*)Wg)[i];

    int lane = tid & 31, w = tid >> 5;
    int og = (w & (OGW - 1)) * 4 + (lane & 3);
    int eg = (w / OGW) * 8 + (lane >> 2);

    auto stage = [&](long t, int c, int b) {
        float* dst = sX + b * (128 * PC);
        constexpr int UN = 128 * (KC / 4);
        for (int i = tid; i < UN; i += 512) {
            int e_l = i / (KC / 4);
            int ks  = (i % (KC / 4)) * 4;
            cpa16(dst + e_l * PC + ks, op.src(t * 128 + e_l, c * KC + ks));
        }
        cp_commit();
    };

    long t0 = blockIdx.x;
    if (t0 < ntiles) stage(t0, 0, 0);
    int b = 0;

    for (long t = t0; t < ntiles; t += gridDim.x) {
        ULL acc[EPT][NP];
#pragma unroll
        for (int j = 0; j < EPT; j++)
#pragma unroll
            for (int p = 0; p < NP; p++) acc[j][p] = 0ULL;

        for (int c = 0; c < NCH; c++) {
            long nt = t; int nc = c + 1;
            if (nc == NCH) { nt = t + gridDim.x; nc = 0; }
            bool hn = nt < ntiles;
            __syncthreads();
            if (hn) stage(nt, nc, b ^ 1);
            if (hn) cp_wait1(); else cp_wait0();
            __syncthreads();

            const float* Xb = sX + b * (128 * PC);
            const float* xr[EPT];
#pragma unroll
            for (int j = 0; j < EPT; j++) xr[j] = Xb + (eg + EGN * j) * PC;

#pragma unroll 2
            for (int k4 = 0; k4 < KC; k4 += 4) {
                float4 xv[EPT];
#pragma unroll
                for (int j = 0; j < EPT; j++)
                    xv[j] = *(const float4*)(xr[j] + k4);
#pragma unroll
                for (int kk = 0; kk < 4; kk++) {
                    const float* wr = sW + (c * KC + k4 + kk) * OUT + og * OPO;
                    ULL wv[NP];
#pragma unroll
                    for (int p = 0; p < NP; p++)
                        wv[p] = *(const ULL*)(wr + 2 * p);
#pragma unroll
                    for (int j = 0; j < EPT; j++) {
                        float xs = (kk == 0) ? xv[j].x : (kk == 1) ? xv[j].y
                                 : (kk == 2) ? xv[j].z : xv[j].w;
                        ULL xd = pack2(xs);
#pragma unroll
                        for (int p = 0; p < NP; p++)
                            acc[j][p] = fma2(xd, wv[p], acc[j][p]);
                    }
                }
            }
            b ^= 1;
        }

#pragma unroll
        for (int j = 0; j < EPT; j++) {
            long e = t * 128 + eg + EGN * j;
            float r[OPO];
#pragma unroll
            for (int p = 0; p < NP; p++) {
                union { ULL u; float2 f; } cv; cv.u = acc[j][p];
                r[2 * p] = cv.f.x; r[2 * p + 1] = cv.f.y;
            }
            op.epi(e, og, r);
        }
    }
}

// ---------------------------------------------------------------------------
// Streaming FFMA2 GEMM, 256 threads, 2 CTAs/SM (G9)
// ---------------------------------------------------------------------------
template <int KTOT, int KC, int OUT, int OPO, class Op>
__global__ void __launch_bounds__(256, 2) gk2(Op op, const float* __restrict__ Wg,
                                              int ntiles)
{
    constexpr int PC  = KC + 4;
    constexpr int NCH = KTOT / KC;
    constexpr int OG  = OUT / OPO;
    constexpr int OGW = OG / 4;
    constexpr int EGN = 256 / OG;
    constexpr int EPT = 64 / EGN;
    constexpr int NP  = OPO / 2;

    extern __shared__ __align__(16) float sh[];
    float* sW = sh;
    float* sX = sh + KTOT * OUT;

    int tid = threadIdx.x;
    for (int i = tid; i < KTOT * OUT / 4; i += 256)
        ((float4*)sW)[i] = ((const float4*)Wg)[i];

    int lane = tid & 31, w = tid >> 5;
    int og = (w & (OGW - 1)) * 4 + (lane & 3);
    int eg = (w / OGW) * 8 + (lane >> 2);

    auto stage = [&](long t, int c, int b) {
        float* dst = sX + b * (64 * PC);
        constexpr int UN = 64 * (KC / 4);
        for (int i = tid; i < UN; i += 256) {
            int e_l = i / (KC / 4);
            int ks  = (i % (KC / 4)) * 4;
            cpa16(dst + e_l * PC + ks, op.src(t * 64 + e_l, c * KC + ks));
        }
        cp_commit();
    };

    long t0 = blockIdx.x;
    if (t0 < ntiles) stage(t0, 0, 0);
    int b = 0;

    for (long t = t0; t < ntiles; t += gridDim.x) {
        ULL acc[EPT][NP];
#pragma unroll
        for (int j = 0; j < EPT; j++)
#pragma unroll
            for (int p = 0; p < NP; p++) acc[j][p] = 0ULL;

        for (int c = 0; c < NCH; c++) {
            long nt = t; int nc = c + 1;
            if (nc == NCH) { nt = t + gridDim.x; nc = 0; }
            bool hn = nt < ntiles;
            __syncthreads();
            if (hn) stage(nt, nc, b ^ 1);
            if (hn) cp_wait1(); else cp_wait0();
            __syncthreads();

            const float* Xb = sX + b * (64 * PC);
            const float* xr[EPT];
#pragma unroll
            for (int j = 0; j < EPT; j++) xr[j] = Xb + (eg + EGN * j) * PC;

#pragma unroll 2
            for (int k4 = 0; k4 < KC; k4 += 4) {
                float4 xv[EPT];
#pragma unroll
                for (int j = 0; j < EPT; j++)
                    xv[j] = *(const float4*)(xr[j] + k4);
#pragma unroll
                for (int kk = 0; kk < 4; kk++) {
                    const float* wr = sW + (c * KC + k4 + kk) * OUT + og * OPO;
                    ULL wv[NP];
#pragma unroll
                    for (int p = 0; p < NP; p++)
                        wv[p] = *(const ULL*)(wr + 2 * p);
#pragma unroll
                    for (int j = 0; j < EPT; j++) {
                        float xs = (kk == 0) ? xv[j].x : (kk == 1) ? xv[j].y
                                 : (kk == 2) ? xv[j].z : xv[j].w;
                        ULL xd = pack2(xs);
#pragma unroll
                        for (int p = 0; p < NP; p++)
                            acc[j][p] = fma2(xd, wv[p], acc[j][p]);
                    }
                }
            }
            b ^= 1;
        }

#pragma unroll
        for (int j = 0; j < EPT; j++) {
            long e = t * 64 + eg + EGN * j;
            float r[OPO];
#pragma unroll
            for (int p = 0; p < NP; p++) {
                union { ULL u; float2 f; } cv; cv.u = acc[j][p];
                r[2 * p] = cv.f.x; r[2 * p + 1] = cv.f.y;
            }
            op.epi(e, og, r);
        }
    }
}

// ---------------------------------------------------------------------------
// Epilogue / source policies.
// ---------------------------------------------------------------------------
struct OpG4T {
    const int* ctr;
    __device__ const float* src(long e, int k) const { return g_lat + e * 128 + k; }
    __device__ void epi2(long e, int col, float v0, float v1) const {
        if (col < 64) {
            *(float2*)(g_wedge + e * 64 + col) =
                make_float2(v0 * F_RS128, v1 * F_RS128);
        } else {
            long c = ctr[e];
            float4 Y = *(const float4*)(g_Y + e * 4);
            int m = (col - 64) >> 1;
            float w0 = v0 * F_RS128, w1 = v1 * F_RS128;
            red4(g_env + c * 128 + 4 * m, w0, w1 * Y.y, w1 * Y.z, w1 * Y.w);
        }
    }
};
struct OpG7T {
    __device__ const float* src(long e, int k) const {
        return (k < 128) ? (g_lat + e * 128 + k) : (g_scal0 + e * 64 + (k - 128));
    }
    __device__ void epi2(long e, int col, float v0, float v1) const {
        *(float2*)(g_H + e * 128 + col) =
            make_float2(silu_f(v0 * F_RS192), silu_f(v1 * F_RS192));
    }
};
struct OpG8T {
    __device__ const float* src(long e, int k) const { return g_H + e * 128 + k; }
    __device__ void epi2(long e, int col, float v0, float v1) const {
        float s = F_C_NEW * F_RS128 * g_fcut[e];
        float2 l = *(float2*)(g_lat + e * 128 + col);
        *(float2*)(g_lat + e * 128 + col) =
            make_float2(F_C_OLD * l.x + s * v0, F_C_OLD * l.y + s * v1);
    }
};
struct OpG10T {
    __device__ const float* src(long e, int k) const {
        return (k < 128) ? (g_lat + e * 128 + k) : (g_q + e * 64 + (k - 128));
    }
    __device__ void epi2(long e, int col, float v0, float v1) const {
        *(float2*)(g_H + e * 128 + col) =
            make_float2(silu_f(v0 * F_RS192), silu_f(v1 * F_RS192));
    }
};
struct OpG11T {
    const int* ctr;
    float* out;
    __device__ const float* src(long e, int k) const { return g_H + e * 128 + k; }
    __device__ void epi2(long e, int col, float v0, float v1) const {
        long c = ctr[e];
        float s = F_C_NEW * F_RS128 * g_fcut[e];
        float2 l = *(const float2*)(g_lat + e * 128 + col);
        red2(out + c * 128 + col,
             (F_C_OLD * l.x + s * v0) * F_ISN,
             (F_C_OLD * l.y + s * v1) * F_ISN);
    }
};
struct OpG5 {
    __device__ const float* src(long e, int k) const { return g_scal0 + e * 64 + k; }
    __device__ void epi(long e, int og, const float* r) const {
        *(float4*)(g_smix + e * 32 + og * 4) =
            make_float4(r[0] * F_RS64, r[1] * F_RS64, r[2] * F_RS64, r[3] * F_RS64);
    }
};
struct OpG9 {
    const int* ctr;
    __device__ const float* src(long e, int k) const { return g_lat + e * 128 + k; }
    __device__ void epi(long e, int og, const float* r) const {
        long c = ctr[e];
        float4 Y = *(const float4*)(g_Y + e * 4);
        int m0 = og * 2;
        float w0 = r[0] * F_RS128, w1 = r[1] * F_RS128;
        red4(g_env1 + c * 128 + 4 * m0, w0, w1 * Y.y, w1 * Y.z, w1 * Y.w);
        float w2 = r[2] * F_RS128, w3 = r[3] * F_RS128;
        red4(g_env1 + c * 128 + 4 * (m0 + 1), w2, w3 * Y.y, w3 * Y.z, w3 * Y.w);
    }
};

// ---------------------------------------------------------------------------
// k123: fused X0(40) -> silu(64) -> silu(128) -> *fcut*rs128 -> g_lat
// ---------------------------------------------------------------------------
__global__ void __launch_bounds__(512, 1) k123(
    const float* __restrict__ W0g, const float* __restrict__ W1g,
    const float* __restrict__ W2g, int ntiles)
{
    extern __shared__ __align__(16) float sh[];
    float* sW0 = sh;
    float* sW1 = sh + 2560;
    float* sW2 = sh + 10752;
    float* sX  = sh + 27136;
    float* sHU = sh + 38400;

    int tid = threadIdx.x;
    for (int i = tid; i < 2560 / 4;  i += 512) ((float4*)sW0)[i] = ((const float4*)W0g)[i];
    for (int i = tid; i < 8192 / 4;  i += 512) ((float4*)sW1)[i] = ((const float4*)W1g)[i];
    for (int i = tid; i < 16384 / 4; i += 512) ((float4*)sW2)[i] = ((const float4*)W2g)[i];

    int lane = tid & 31, w = tid >> 5;
    int og = (w & 3) * 4 + (lane & 3);
    int eg = (w >> 2) * 8 + (lane >> 2);

    auto stage = [&](long t, int b) {
        float* dst = sX + b * 5632;
        for (int i = tid; i < 1280; i += 512) {
            int e_l = i / 10, ks = (i % 10) * 4;
            cpa16(dst + e_l * 44 + ks, g_X0 + (t * 128 + e_l) * 40 + ks);
        }
        cp_commit();
    };

    long t0 = blockIdx.x;
    if (t0 < ntiles) stage(t0, 0);
    int b = 0;

    for (long t = t0; t < ntiles; t += gridDim.x) {
        long nt = t + gridDim.x;
        bool hn = nt < ntiles;
        __syncthreads();
        if (hn) stage(nt, b ^ 1);
        if (hn) cp_wait1(); else cp_wait0();
        __syncthreads();

        {
            const float* Xb = sX + b * 5632;
            ULL acc[4][2];
#pragma unroll
            for (int j = 0; j < 4; j++) { acc[j][0] = 0ULL; acc[j][1] = 0ULL; }
            const float* xr[4];
#pragma unroll
            for (int j = 0; j < 4; j++) xr[j] = Xb + (eg + 32 * j) * 44;
#pragma unroll 2
            for (int k4 = 0; k4 < 40; k4 += 4) {
                float4 xv[4];
#pragma unroll
                for (int j = 0; j < 4; j++) xv[j] = *(const float4*)(xr[j] + k4);
#pragma unroll
                for (int kk = 0; kk < 4; kk++) {
                    const float* wr = sW0 + (k4 + kk) * 64 + og * 4;
                    ULL w0 = *(const ULL*)wr, w1 = *(const ULL*)(wr + 2);
#pragma unroll
                    for (int j = 0; j < 4; j++) {
                        float xs = (kk == 0) ? xv[j].x : (kk == 1) ? xv[j].y
                                 : (kk == 2) ? xv[j].z : xv[j].w;
                        ULL xd = pack2(xs);
                        acc[j][0] = fma2(xd, w0, acc[j][0]);
                        acc[j][1] = fma2(xd, w1, acc[j][1]);
                    }
                }
            }
#pragma unroll
            for (int j = 0; j < 4; j++) {
                union { ULL u; float2 f; } c0, c1;
                c0.u = acc[j][0]; c1.u = acc[j][1];
                *(float4*)(sHU + (eg + 32 * j) * 68 + og * 4) =
                    make_float4(silu_f(c0.f.x * F_RS40), silu_f(c0.f.y * F_RS40),
                                silu_f(c1.f.x * F_RS40), silu_f(c1.f.y * F_RS40));
            }
        }
        __syncthreads();

        {
            ULL acc[4][4];
#pragma unroll
            for (int j = 0; j < 4; j++)
#pragma unroll
                for (int p = 0; p < 4; p++) acc[j][p] = 0ULL;
            const float* xr[4];
#pragma unroll
            for (int j = 0; j < 4; j++) xr[j] = sHU + (eg + 32 * j) * 68;
#pragma unroll 2
            for (int k4 = 0; k4 < 64; k4 += 4) {
                float4 xv[4];
#pragma unroll
                for (int j = 0; j < 4; j++) xv[j] = *(const float4*)(xr[j] + k4);
#pragma unroll
                for (int kk = 0; kk < 4; kk++) {
                    const float* wr = sW1 + (k4 + kk) * 128 + og * 8;
                    ulonglong2 wa = *(const ulonglong2*)wr;
                    ulonglong2 wb = *(const ulonglong2*)(wr + 4);
#pragma unroll
                    for (int j = 0; j < 4; j++) {
                        float xs = (kk == 0) ? xv[j].x : (kk == 1) ? xv[j].y
                                 : (kk == 2) ? xv[j].z : xv[j].w;
                        ULL xd = pack2(xs);
                        acc[j][0] = fma2(xd, wa.x, acc[j][0]);
                        acc[j][1] = fma2(xd, wa.y, acc[j][1]);
                        acc[j][2] = fma2(xd, wb.x, acc[j][2]);
                        acc[j][3] = fma2(xd, wb.y, acc[j][3]);
                    }
                }
            }
            __syncthreads();
#pragma unroll
            for (int j = 0; j < 4; j++) {
                float* hr = sHU + (eg + 32 * j) * 132 + og * 8;
                union { ULL u; float2 f; } c0, c1, c2, c3;
                c0.u = acc[j][0]; c1.u = acc[j][1]; c2.u = acc[j][2]; c3.u = acc[j][3];
                *(float4*)hr =
                    make_float4(silu_f(c0.f.x * F_RS64), silu_f(c0.f.y * F_RS64),
                                silu_f(c1.f.x * F_RS64), silu_f(c1.f.y * F_RS64));
                *(float4*)(hr + 4) =
                    make_float4(silu_f(c2.f.x * F_RS64), silu_f(c2.f.y * F_RS64),
                                silu_f(c3.f.x * F_RS64), silu_f(c3.f.y * F_RS64));
            }
        }
        __syncthreads();

        {
            ULL acc[4][4];
#pragma unroll
            for (int j = 0; j < 4; j++)
#pragma unroll
                for (int p = 0; p < 4; p++) acc[j][p] = 0ULL;
            const float* xr[4];
#pragma unroll
            for (int j = 0; j < 4; j++) xr[j] = sHU + (eg + 32 * j) * 132;
#pragma unroll 2
            for (int k4 = 0; k4 < 128; k4 += 4) {
                float4 xv[4];
#pragma unroll
                for (int j = 0; j < 4; j++) xv[j] = *(const float4*)(xr[j] + k4);
#pragma unroll
                for (int kk = 0; kk < 4; kk++) {
                    const float* wr = sW2 + (k4 + kk) * 128 + og * 8;
                    ulonglong2 wa = *(const ulonglong2*)wr;
                    ulonglong2 wb = *(const ulonglong2*)(wr + 4);
#pragma unroll
                    for (int j = 0; j < 4; j++) {
                        float xs = (kk == 0) ? xv[j].x : (kk == 1) ? xv[j].y
                                 : (kk == 2) ? xv[j].z : xv[j].w;
                        ULL xd = pack2(xs);
                        acc[j][0] = fma2(xd, wa.x, acc[j][0]);
                        acc[j][1] = fma2(xd, wa.y, acc[j][1]);
                        acc[j][2] = fma2(xd, wb.x, acc[j][2]);
                        acc[j][3] = fma2(xd, wb.y, acc[j][3]);
                    }
                }
            }
#pragma unroll
            for (int j = 0; j < 4; j++) {
                long e = t * 128 + eg + 32 * j;
                float s = F_RS128 * g_fcut[e];
                union { ULL u; float2 f; } c0, c1, c2, c3;
                c0.u = acc[j][0]; c1.u = acc[j][1]; c2.u = acc[j][2]; c3.u = acc[j][3];
                *(float4*)(g_lat + e * 128 + og * 8) =
                    make_float4(c0.f.x * s, c0.f.y * s, c1.f.x * s, c1.f.y * s);
                *(float4*)(g_lat + e * 128 + og * 8 + 4) =
                    make_float4(c2.f.x * s, c2.f.y * s, c3.f.x * s, c3.f.y * s);
            }
        }
        b ^= 1;
    }
}

// ---------------------------------------------------------------------------
__global__ void k_zero(float* __restrict__ out)
{
    int i = blockIdx.x * blockDim.x + threadIdx.x;
    int stride = gridDim.x * blockDim.x;
    for (; i < NN * 128; i += stride) {
        g_env[i]  = 0.0f;
        g_env1[i] = 0.0f;
        out[i]    = 0.0f;
    }
}

__global__ void __launch_bounds__(512) kgeo(
    const float* __restrict__ coords, const float* __restrict__ attrs,
    const int* __restrict__ eidx)
{
    int e = blockIdx.x * 512 + threadIdx.x;
    if (e >= NE) return;
    int snd = eidx[e];
    int c   = eidx[NE + e];
    float dx = coords[c * 3 + 0] - coords[snd * 3 + 0];
    float dy = coords[c * 3 + 1] - coords[snd * 3 + 1];
    float dz = coords[c * 3 + 2] - coords[snd * 3 + 2];
    float r2 = dx * dx + dy * dy + dz * dz + 1e-12f;
    float r  = sqrtf(r2);
    float inv_r = 1.0f / r;
    float u  = r * F_INV_RMAX;
    float u2 = u * u, u3 = u2 * u, u6 = u3 * u3, u7 = u6 * u, u8 = u7 * u;
    float f  = 1.0f - 28.0f * u6 + 48.0f * u7 - 21.0f * u8;
    if (u >= 1.0f) f = 0.0f;
    g_fcut[e] = f;
    *(float4*)(g_Y + e * 4) = make_float4(1.0f, F_SQRT3 * dx * inv_r,
                                          F_SQRT3 * dy * inv_r, F_SQRT3 * dz * inv_r);
    float* X = g_X0 + (long)e * 40;
    const float4* ac = (const float4*)(attrs + c * 16);
    const float4* as = (const float4*)(attrs + snd * 16);
#pragma unroll
    for (int i = 0; i < 4; i++) ((float4*)X)[i] = ac[i];
#pragma unroll
    for (int i = 0; i < 4; i++) ((float4*)(X + 16))[i] = as[i];
    float bi = inv_r * f * F_BESSEL;
#pragma unroll
    for (int n = 0; n < 8; n++)
        X[32 + n] = bi * sinf((n + 1) * F_PI * u);
}

// kp2: q0/q1 (warp per edge, lane = m)
__global__ void __launch_bounds__(256) kp2(const int* __restrict__ eidx)
{
    int warp = (blockIdx.x * 256 + threadIdx.x) >> 5;
    int lane = threadIdx.x & 31;
    int nw = gridDim.x * 8;
    for (long e = warp; e < NE; e += nw) {
        long c = eidx[NE + e];
        float4 e1 = *(const float4*)(g_env1 + c * 128 + 4 * lane);
        float sm = g_smix[e * 32 + lane];
        float v0 = g_vmx[(3 * e + 0) * 32 + lane];
        float v1 = g_vmx[(3 * e + 1) * 32 + lane];
        float v2 = g_vmx[(3 * e + 2) * 32 + lane];
        g_q[e * 64 + lane] = sm * e1.x * F_ISN;
        g_q[e * 64 + 32 + lane] =
            (v0 * e1.y + v1 * e1.z + v2 * e1.w) * F_ISN * F_INV_SQRT3;
    }
}

// ---------------------------------------------------------------------------
extern "C" void kernel_launch(void* const* d_in, const int* in_sizes, int n_in,
                              void* d_out, int out_size)
{
    const float* coords = (const float*)d_in[0];
    const float* attrs  = (const float*)d_in[1];
    const int*   eidx   = (const int*)  d_in[2];
    const float* W2b0   = (const float*)d_in[3];
    const float* W2b1   = (const float*)d_in[4];
    const float* W2b2   = (const float*)d_in[5];
    const float* Wenv0  = (const float*)d_in[6];
    const float* Wlat0  = (const float*)d_in[7];
    const float* Wlat1  = (const float*)d_in[8];
    const float* Ws0    = (const float*)d_in[9];
    const float* Wv0    = (const float*)d_in[10];
    const float* Wenv1  = (const float*)d_in[11];
    const float* Wfin0  = (const float*)d_in[12];
    const float* Wfin1  = (const float*)d_in[13];
    float* out = (float*)d_out;
    const int* ctr = eidx + NE;

    const size_t sm_k123 = (2560 + 8192 + 16384 + 11264 + 16896) * 4;
    const size_t sm2_64  = (8192  + 2 * 64 * 68) * 4;
    const size_t sm64_32 = (2048 + 2 * 128 * 68) * 4;
    const size_t sm_t2   = (size_t)(2 * 64 * 64 + 2 * 128 * 64) * 4;    //  98304
    const size_t sm_t192 = (size_t)4 * 128 * 96 * 4;                    // 196608
    const size_t sm_kpv  = (size_t)(2 * 384 * KPV_PITCH + 2 * 32 * KPV_PITCH) * 4; // 163072

    cudaFuncSetAttribute(k123, cudaFuncAttributeMaxDynamicSharedMemorySize, (int)sm_k123);
    cudaFuncSetAttribute(tkm2<128, OpG4T>,  cudaFuncAttributeMaxDynamicSharedMemorySize, (int)sm_t2);
    cudaFuncSetAttribute(kpv,               cudaFuncAttributeMaxDynamicSharedMemorySize, (int)sm_kpv);
    cudaFuncSetAttribute(tkm<192, OpG7T>,   cudaFuncAttributeMaxDynamicSharedMemorySize, (int)sm_t192);
    cudaFuncSetAttribute(tkm2<128, OpG8T>,  cudaFuncAttributeMaxDynamicSharedMemorySize, (int)sm_t2);
    cudaFuncSetAttribute(tkm<192, OpG10T>,  cudaFuncAttributeMaxDynamicSharedMemorySize, (int)sm_t192);
    cudaFuncSetAttribute(tkm2<128, OpG11T>, cudaFuncAttributeMaxDynamicSharedMemorySize, (int)sm_t2);
    cudaFuncSetAttribute(gk<64, 64, 32, 4, OpG5>, cudaFuncAttributeMaxDynamicSharedMemorySize, (int)sm64_32);
    cudaFuncSetAttribute(gk2<128, 64, 64, 4, OpG9>, cudaFuncAttributeMaxDynamicSharedMemorySize, (int)sm2_64);

    const int NT   = NE / 128;   // 2500
    const int NT64 = NE / 64;    // 5000

    k_zero<<<512, 256>>>(out);
    kgeo<<<(NE + 511) / 512, 512>>>(coords, attrs, eidx);

    k123<<<148, 512, sm_k123>>>(W2b0, W2b1, W2b2, NT);
    tkm2<128, OpG4T><<<296, 256, sm_t2>>>(OpG4T{ctr}, Wenv0, NT64);
    kpv<<<148, 512, sm_kpv>>>(ctr, Wv0, NT);
    gk<64, 64, 32, 4, OpG5><<<148, 512, sm64_32>>>(OpG5{}, Ws0, NT);
    tkm<192, OpG7T><<<148, 512, sm_t192>>>(OpG7T{}, Wlat0, NT);
    tkm2<128, OpG8T><<<296, 256, sm_t2>>>(OpG8T{}, Wlat1, NT64);
    gk2<128, 64, 64, 4, OpG9><<<296, 256, sm2_64>>>(OpG9{ctr}, Wenv1, NT64);
    kp2<<<2560, 256>>>(eidx);
    tkm<192, OpG10T><<<148, 512, sm_t192>>>(OpG10T{}, Wfin0, NT);
    tkm2<128, OpG11T><<<296, 256, sm_t2>>>(OpG11T{ctr, out}, Wfin1, NT64);
}

// round 17
// speedup vs baseline: 1.9070x; 1.1376x over previous
#include <cuda_runtime.h>
#include <cuda_bf16.h>

// ---------------------------------------------------------------------------
// Allegro GNN layer — tensor-core (mma.sync bf16-split hi/lo 3-pass) pipeline.
//   kt123 : X0 -> FFMA2(40->64) -> mma(64->128) -> mma(128->128)*fcut -> lat
//           (H1/H2 live only in smem as bf16 pairs; X0/H2 share a union)
//   tkm2  : BM-tiled mma GEMM, 256 thr, 2 CTAs/SM (G4/G8/G11 OUT=128; G9 OUT=64)
//   tkm   : 512-thr mma GEMM, K=192 (G7/G10)
//   kpv   : fused products+vmix (P only in smem)
//   gk    : FFMA2 (G5);  kgeo, kp2, k_zero
// ---------------------------------------------------------------------------

#define NN 10000
#define NE 320000
#define NE3 960000
typedef unsigned long long ULL;
typedef unsigned int U32;

__device__ float g_X0  [NE * 40];
__device__ float g_H   [NE * 128];
__device__ float g_lat [NE * 128];
__device__ float g_wedge[NE * 64];
__device__ float g_scal0[NE * 64];
__device__ float g_smix[NE * 32];
__device__ float g_vmx [NE3 * 32];
__device__ float g_q   [NE * 64];
__device__ float g_Y   [NE * 4];
__device__ float g_fcut[NE];
__device__ float g_env [NN * 128];
__device__ float g_env1[NN * 128];

#define F_RS40      0.15811388300841897f
#define F_RS64      0.125f
#define F_RS96      0.10206207261596575f
#define F_RS128     0.08838834764831845f
#define F_RS192     0.07216878364870323f
#define F_ISN       0.17677669529663689f
#define F_SQRT3     1.7320508075688772f
#define F_INV_SQRT3 0.5773502691896258f
#define F_INV_SQRT2 0.7071067811865476f
#define F_C_OLD     0.8944271909999159f
#define F_C_NEW     0.4472135954999579f
#define F_BESSEL    0.6324555320336759f
#define F_PI        3.14159265358979323846f
#define F_INV_RMAX  0.2f

__device__ __forceinline__ ULL fma2(ULL a, ULL b, ULL c) {
    ULL d;
    asm("fma.rn.f32x2 %0, %1, %2, %3;" : "=l"(d) : "l"(a), "l"(b), "l"(c));
    return d;
}
__device__ __forceinline__ ULL pack2(float x) {
    ULL d; unsigned u = __float_as_uint(x);
    asm("mov.b64 %0, {%1,%1};" : "=l"(d) : "r"(u));
    return d;
}
__device__ __forceinline__ void red4(float* p, float a, float b, float c, float d) {
    asm volatile("red.global.add.v4.f32 [%0], {%1,%2,%3,%4};"
                 :: "l"(p), "f"(a), "f"(b), "f"(c), "f"(d) : "memory");
}
__device__ __forceinline__ void red2(float* p, float a, float b) {
    asm volatile("red.global.add.v2.f32 [%0], {%1,%2};"
                 :: "l"(p), "f"(a), "f"(b) : "memory");
}
__device__ __forceinline__ float silu_f(float v) {
    return v * __frcp_rn(1.0f + __expf(-v));
}
__device__ __forceinline__ void cpa16(const void* s, const void* g) {
    unsigned sa = (unsigned)__cvta_generic_to_shared(s);
    asm volatile("cp.async.cg.shared.global [%0], [%1], 16;" :: "r"(sa), "l"(g));
}
__device__ __forceinline__ void cp_commit() { asm volatile("cp.async.commit_group;"); }
__device__ __forceinline__ void cp_wait0()  { asm volatile("cp.async.wait_group 0;"); }

__device__ __forceinline__ void mma16816(float* d, const U32* a, const U32* b) {
    asm volatile(
        "mma.sync.aligned.m16n8k16.row.col.f32.bf16.bf16.f32 "
        "{%0,%1,%2,%3}, {%4,%5,%6,%7}, {%8,%9}, {%0,%1,%2,%3};"
        : "+f"(d[0]), "+f"(d[1]), "+f"(d[2]), "+f"(d[3])
        : "r"(a[0]), "r"(a[1]), "r"(a[2]), "r"(a[3]), "r"(b[0]), "r"(b[1]));
}
__device__ __forceinline__ void bsplit8(const float* xs, uint4& hi, uint4& lo) {
    unsigned h[4], l[4];
#pragma unroll
    for (int p = 0; p < 4; p++) {
        __nv_bfloat16 h0 = __float2bfloat16(xs[2 * p]);
        __nv_bfloat16 h1 = __float2bfloat16(xs[2 * p + 1]);
        __nv_bfloat16 l0 = __float2bfloat16(xs[2 * p] - __bfloat162float(h0));
        __nv_bfloat16 l1 = __float2bfloat16(xs[2 * p + 1] - __bfloat162float(h1));
        h[p] = (unsigned)__bfloat16_as_ushort(h0) |
               ((unsigned)__bfloat16_as_ushort(h1) << 16);
        l[p] = (unsigned)__bfloat16_as_ushort(l0) |
               ((unsigned)__bfloat16_as_ushort(l1) << 16);
    }
    hi = make_uint4(h[0], h[1], h[2], h[3]);
    lo = make_uint4(l[0], l[1], l[2], l[3]);
}
__device__ __forceinline__ void packpair(float v0, float v1, U32& h, U32& l) {
    __nv_bfloat16 h0 = __float2bfloat16(v0), h1 = __float2bfloat16(v1);
    __nv_bfloat16 l0 = __float2bfloat16(v0 - __bfloat162float(h0));
    __nv_bfloat16 l1 = __float2bfloat16(v1 - __bfloat162float(h1));
    h = (U32)__bfloat16_as_ushort(h0) | ((U32)__bfloat16_as_ushort(h1) << 16);
    l = (U32)__bfloat16_as_ushort(l0) | ((U32)__bfloat16_as_ushort(l1) << 16);
}
__device__ __forceinline__ int pidx(int row, int p, int KH) {
    return row * KH + (p ^ ((row & 7) << 2));
}

// ---------------------------------------------------------------------------
// tkm: warp mma bf16-split GEMM.  BM=128, OUT=128, 512 thr (K=192).
// ---------------------------------------------------------------------------
template <int K, class Op>
__global__ void __launch_bounds__(512, 1) tkm(Op op, const float* __restrict__ Wg,
                                              int ntiles)
{
    constexpr int KH = K / 2;
    constexpr int KB = K / 8;
    extern __shared__ __align__(16) U32 su[];
    U32* AH = su;
    U32* AL = AH + 128 * KH;
    U32* BH = AL + 128 * KH;
    U32* BL = BH + 128 * KH;

    int tid = threadIdx.x, lane = tid & 31, w = tid >> 5;
    int g = lane >> 2, tg = lane & 3;
    int wm = w & 3, wn = w >> 2;

    for (int i = tid; i < 128 * KB; i += 512) {
        int n = i / KB, kb = (i % KB) * 8;
        float xs[8];
#pragma unroll
        for (int j = 0; j < 8; j++) xs[j] = Wg[(kb + j) * 128 + n];
        uint4 hi, lo; bsplit8(xs, hi, lo);
        int p4 = ((kb >> 1) ^ ((n & 7) << 2));
        *(uint4*)&BH[n * KH + p4] = hi;
        *(uint4*)&BL[n * KH + p4] = lo;
    }
    __syncthreads();

    for (long t = blockIdx.x; t < ntiles; t += gridDim.x) {
        for (int i = tid; i < 128 * KB; i += 512) {
            int m = i / KB, kb = (i % KB) * 8;
            const float* s = op.src(t * 128 + m, kb);
            float4 x0 = *(const float4*)s, x1 = *(const float4*)(s + 4);
            float xs[8] = {x0.x, x0.y, x0.z, x0.w, x1.x, x1.y, x1.z, x1.w};
            uint4 hi, lo; bsplit8(xs, hi, lo);
            int p4 = ((kb >> 1) ^ ((m & 7) << 2));
            *(uint4*)&AH[m * KH + p4] = hi;
            *(uint4*)&AL[m * KH + p4] = lo;
        }
        __syncthreads();

        float acc[2][4][4];
#pragma unroll
        for (int mt = 0; mt < 2; mt++)
#pragma unroll
            for (int nt = 0; nt < 4; nt++)
#pragma unroll
                for (int q = 0; q < 4; q++) acc[mt][nt][q] = 0.0f;

#pragma unroll 2
        for (int ks = 0; ks < K / 16; ks++) {
            int pb = ks * 8;
            U32 ah[2][4], al[2][4];
#pragma unroll
            for (int mt = 0; mt < 2; mt++) {
                int r0 = wm * 32 + mt * 16 + g;
                ah[mt][0] = AH[pidx(r0,     pb + tg,     KH)];
                ah[mt][1] = AH[pidx(r0 + 8, pb + tg,     KH)];
                ah[mt][2] = AH[pidx(r0,     pb + tg + 4, KH)];
                ah[mt][3] = AH[pidx(r0 + 8, pb + tg + 4, KH)];
                al[mt][0] = AL[pidx(r0,     pb + tg,     KH)];
                al[mt][1] = AL[pidx(r0 + 8, pb + tg,     KH)];
                al[mt][2] = AL[pidx(r0,     pb + tg + 4, KH)];
                al[mt][3] = AL[pidx(r0 + 8, pb + tg + 4, KH)];
            }
            U32 bh[4][2], bl[4][2];
#pragma unroll
            for (int nt = 0; nt < 4; nt++) {
                int n = wn * 32 + nt * 8 + g;
                bh[nt][0] = BH[pidx(n, pb + tg,     KH)];
                bh[nt][1] = BH[pidx(n, pb + tg + 4, KH)];
                bl[nt][0] = BL[pidx(n, pb + tg,     KH)];
                bl[nt][1] = BL[pidx(n, pb + tg + 4, KH)];
            }
#pragma unroll
            for (int mt = 0; mt < 2; mt++)
#pragma unroll
                for (int nt = 0; nt < 4; nt++) {
                    mma16816(acc[mt][nt], ah[mt], bh[nt]);
                    mma16816(acc[mt][nt], ah[mt], bl[nt]);
                    mma16816(acc[mt][nt], al[mt], bh[nt]);
                }
        }

#pragma unroll
        for (int mt = 0; mt < 2; mt++) {
            int r0 = wm * 32 + mt * 16 + g;
#pragma unroll
            for (int nt = 0; nt < 4; nt++) {
                int col = wn * 32 + nt * 8 + tg * 2;
                op.epi2(t * 128 + r0,     col, acc[mt][nt][0], acc[mt][nt][1]);
                op.epi2(t * 128 + r0 + 8, col, acc[mt][nt][2], acc[mt][nt][3]);
            }
        }
        __syncthreads();
    }
}

// ---------------------------------------------------------------------------
// tkm2: 256 thr, 2 CTAs/SM.  BM = WM*32, OUT = (8/WM)*32.
//   G4/G8/G11: K=128, OUT=128, WM=2 (BM=64)
//   G9       : K=128, OUT=64,  WM=4 (BM=128)
// ---------------------------------------------------------------------------
template <int K, int OUT, int WM, class Op>
__global__ void __launch_bounds__(256, 2) tkm2(Op op, const float* __restrict__ Wg,
                                               int ntiles)
{
    constexpr int KH = K / 2;
    constexpr int KB = K / 8;
    constexpr int BM = WM * 32;
    extern __shared__ __align__(16) U32 su[];
    U32* AH = su;
    U32* AL = AH + BM * KH;
    U32* BH = AL + BM * KH;
    U32* BL = BH + OUT * KH;

    int tid = threadIdx.x, lane = tid & 31, w = tid >> 5;
    int g = lane >> 2, tg = lane & 3;
    int wm = w % WM, wn = w / WM;

    for (int i = tid; i < OUT * KB; i += 256) {
        int n = i / KB, kb = (i % KB) * 8;
        float xs[8];
#pragma unroll
        for (int j = 0; j < 8; j++) xs[j] = Wg[(kb + j) * OUT + n];
        uint4 hi, lo; bsplit8(xs, hi, lo);
        int p4 = ((kb >> 1) ^ ((n & 7) << 2));
        *(uint4*)&BH[n * KH + p4] = hi;
        *(uint4*)&BL[n * KH + p4] = lo;
    }
    __syncthreads();

    for (long t = blockIdx.x; t < ntiles; t += gridDim.x) {
        for (int i = tid; i < BM * KB; i += 256) {
            int m = i / KB, kb = (i % KB) * 8;
            const float* s = op.src(t * BM + m, kb);
            float4 x0 = *(const float4*)s, x1 = *(const float4*)(s + 4);
            float xs[8] = {x0.x, x0.y, x0.z, x0.w, x1.x, x1.y, x1.z, x1.w};
            uint4 hi, lo; bsplit8(xs, hi, lo);
            int p4 = ((kb >> 1) ^ ((m & 7) << 2));
            *(uint4*)&AH[m * KH + p4] = hi;
            *(uint4*)&AL[m * KH + p4] = lo;
        }
        __syncthreads();

        float acc[2][4][4];
#pragma unroll
        for (int mt = 0; mt < 2; mt++)
#pragma unroll
            for (int nt = 0; nt < 4; nt++)
#pragma unroll
                for (int q = 0; q < 4; q++) acc[mt][nt][q] = 0.0f;

#pragma unroll 2
        for (int ks = 0; ks < K / 16; ks++) {
            int pb = ks * 8;
            U32 ah[2][4], al[2][4];
#pragma unroll
            for (int mt = 0; mt < 2; mt++) {
                int r0 = wm * 32 + mt * 16 + g;
                ah[mt][0] = AH[pidx(r0,     pb + tg,     KH)];
                ah[mt][1] = AH[pidx(r0 + 8, pb + tg,     KH)];
                ah[mt][2] = AH[pidx(r0,     pb + tg + 4, KH)];
                ah[mt][3] = AH[pidx(r0 + 8, pb + tg + 4, KH)];
                al[mt][0] = AL[pidx(r0,     pb + tg,     KH)];
                al[mt][1] = AL[pidx(r0 + 8, pb + tg,     KH)];
                al[mt][2] = AL[pidx(r0,     pb + tg + 4, KH)];
                al[mt][3] = AL[pidx(r0 + 8, pb + tg + 4, KH)];
            }
            U32 bh[4][2], bl[4][2];
#pragma unroll
            for (int nt = 0; nt < 4; nt++) {
                int n = wn * 32 + nt * 8 + g;
                bh[nt][0] = BH[pidx(n, pb + tg,     KH)];
                bh[nt][1] = BH[pidx(n, pb + tg + 4, KH)];
                bl[nt][0] = BL[pidx(n, pb + tg,     KH)];
                bl[nt][1] = BL[pidx(n, pb + tg + 4, KH)];
            }
#pragma unroll
            for (int mt = 0; mt < 2; mt++)
#pragma unroll
                for (int nt = 0; nt < 4; nt++) {
                    mma16816(acc[mt][nt], ah[mt], bh[nt]);
                    mma16816(acc[mt][nt], ah[mt], bl[nt]);
                    mma16816(acc[mt][nt], al[mt], bh[nt]);
                }
        }

#pragma unroll
        for (int mt = 0; mt < 2; mt++) {
            int r0 = wm * 32 + mt * 16 + g;
#pragma unroll
            for (int nt = 0; nt < 4; nt++) {
                int col = wn * 32 + nt * 8 + tg * 2;
                op.epi2(t * BM + r0,     col, acc[mt][nt][0], acc[mt][nt][1]);
                op.epi2(t * BM + r0 + 8, col, acc[mt][nt][2], acc[mt][nt][3]);
            }
        }
        __syncthreads();
    }
}

// ---------------------------------------------------------------------------
// kpv: fused products + vmix (as R16)
// ---------------------------------------------------------------------------
#define KPV_PITCH 49
__device__ __forceinline__ void kpv_pack(U32* AH, U32* AL, int r, int blk,
                                         float v, int lane)
{
    __nv_bfloat16 hb = __float2bfloat16(v);
    float lof = v - __bfloat162float(hb);
    __nv_bfloat16 lb = __float2bfloat16(lof);
    U32 h = (U32)__bfloat16_as_ushort(hb);
    U32 l = (U32)__bfloat16_as_ushort(lb);
    U32 hn = __shfl_down_sync(0xffffffffu, h, 1);
    U32 ln = __shfl_down_sync(0xffffffffu, l, 1);
    if (!(lane & 1)) {
        int p = blk * 16 + (lane >> 1);
        AH[r * KPV_PITCH + p] = h | (hn << 16);
        AL[r * KPV_PITCH + p] = l | (ln << 16);
    }
}

__global__ void __launch_bounds__(512, 1) kpv(
    const int* __restrict__ ctr, const float* __restrict__ Wv, int ntiles)
{
    extern __shared__ __align__(16) U32 su[];
    U32* AH = su;
    U32* AL = AH + 384 * KPV_PITCH;
    U32* BH = AL + 384 * KPV_PITCH;
    U32* BL = BH + 32 * KPV_PITCH;

    int tid = threadIdx.x, lane = tid & 31, w = tid >> 5;
    int g = lane >> 2, tg = lane & 3;

    for (int i = tid; i < 32 * 12; i += 512) {
        int n = i / 12, kb = (i % 12) * 8;
        float xs[8];
#pragma unroll
        for (int j = 0; j < 8; j++) xs[j] = Wv[(kb + j) * 32 + n];
        uint4 hi, lo; bsplit8(xs, hi, lo);
        U32* hp = &BH[n * KPV_PITCH + (kb >> 1)];
        U32* lp = &BL[n * KPV_PITCH + (kb >> 1)];
        hp[0] = hi.x; hp[1] = hi.y; hp[2] = hi.z; hp[3] = hi.w;
        lp[0] = lo.x; lp[1] = lo.y; lp[2] = lo.z; lp[3] = lo.w;
    }
    __syncthreads();

    for (long t = blockIdx.x; t < ntiles; t += gridDim.x) {
        long e0 = t * 128;
#pragma unroll 2
        for (int j = 0; j < 8; j++) {
            int  el = w * 8 + j;
            long e  = e0 + el;
            long c  = ctr[e];
            float2 we = *(const float2*)(g_wedge + e * 64 + 2 * lane);
            float4 en = *(const float4*)(g_env + c * 128 + 4 * lane);
            float4 Y  = *(const float4*)(g_Y + e * 4);
            float fs  = we.x;
            float fv0 = we.y * Y.y, fv1 = we.y * Y.z, fv2 = we.y * Y.w;
            float es  = en.x * F_ISN;
            float ev0 = en.y * F_ISN, ev1 = en.z * F_ISN, ev2 = en.w * F_ISN;
            g_scal0[e * 64 + lane]      = fs * es;
            g_scal0[e * 64 + 32 + lane] =
                (fv0 * ev0 + fv1 * ev1 + fv2 * ev2) * F_INV_SQRT3;
            int r = 3 * el;
            kpv_pack(AH, AL, r + 0, 0, fs * ev0, lane);
            kpv_pack(AH, AL, r + 1, 0, fs * ev1, lane);
            kpv_pack(AH, AL, r + 2, 0, fs * ev2, lane);
            kpv_pack(AH, AL, r + 0, 1, fv0 * es, lane);
            kpv_pack(AH, AL, r + 1, 1, fv1 * es, lane);
            kpv_pack(AH, AL, r + 2, 1, fv2 * es, lane);
            kpv_pack(AH, AL, r + 0, 2, (fv1 * ev2 - fv2 * ev1) * F_INV_SQRT2, lane);
            kpv_pack(AH, AL, r + 1, 2, (fv2 * ev0 - fv0 * ev2) * F_INV_SQRT2, lane);
            kpv_pack(AH, AL, r + 2, 2, (fv0 * ev1 - fv1 * ev0) * F_INV_SQRT2, lane);
        }
        __syncthreads();

#pragma unroll
        for (int mt = 0; mt < 2; mt++) {
            if (mt == 1 && w >= 8) break;
            int r0 = mt * 256 + w * 16 + g;
            float acc[4][4];
#pragma unroll
            for (int nt = 0; nt < 4; nt++)
#pragma unroll
                for (int q = 0; q < 4; q++) acc[nt][q] = 0.0f;

#pragma unroll
            for (int ks = 0; ks < 6; ks++) {
                int pb = ks * 8;
                U32 ah[4], al[4];
                ah[0] = AH[(r0)     * KPV_PITCH + pb + tg];
                ah[1] = AH[(r0 + 8) * KPV_PITCH + pb + tg];
                ah[2] = AH[(r0)     * KPV_PITCH + pb + tg + 4];
                ah[3] = AH[(r0 + 8) * KPV_PITCH + pb + tg + 4];
                al[0] = AL[(r0)     * KPV_PITCH + pb + tg];
                al[1] = AL[(r0 + 8) * KPV_PITCH + pb + tg];
                al[2] = AL[(r0)     * KPV_PITCH + pb + tg + 4];
                al[3] = AL[(r0 + 8) * KPV_PITCH + pb + tg + 4];
#pragma unroll
                for (int nt = 0; nt < 4; nt++) {
                    int n = nt * 8 + g;
                    U32 bh[2] = { BH[n * KPV_PITCH + pb + tg],
                                  BH[n * KPV_PITCH + pb + tg + 4] };
                    U32 bl[2] = { BL[n * KPV_PITCH + pb + tg],
                                  BL[n * KPV_PITCH + pb + tg + 4] };
                    mma16816(acc[nt], ah, bh);
                    mma16816(acc[nt], ah, bl);
                    mma16816(acc[nt], al, bh);
                }
            }

            long rg = t * 384 + r0;
#pragma unroll
            for (int nt = 0; nt < 4; nt++) {
                int col = nt * 8 + tg * 2;
                *(float2*)(g_vmx + rg * 32 + col) =
                    make_float2(acc[nt][0] * F_RS96, acc[nt][1] * F_RS96);
                *(float2*)(g_vmx + (rg + 8) * 32 + col) =
                    make_float2(acc[nt][2] * F_RS96, acc[nt][3] * F_RS96);
            }
        }
        __syncthreads();
    }
}

// ---------------------------------------------------------------------------
// kt123: fused input MLP, tensor path.
// smem bytes: W0 fp32 [0,10240) | BH1/BL1 [10240,43008) | AH1/AL1 [43008,75776)
//   | BH2/BL2 [75776,141312) | UNION(X0 fp32 | AH2+AL2) [141312,206848)
// ---------------------------------------------------------------------------
__global__ void __launch_bounds__(512, 1) kt123(
    const float* __restrict__ W0g, const float* __restrict__ W1g,
    const float* __restrict__ W2g, int ntiles)
{
    extern __shared__ __align__(16) char sb[];
    float* sW0 = (float*)sb;
    U32* BH1 = (U32*)(sb + 10240);
    U32* BL1 = BH1 + 4096;
    U32* AH1 = BL1 + 4096;
    U32* AL1 = AH1 + 4096;
    U32* BH2 = AL1 + 4096;
    U32* BL2 = BH2 + 8192;
    char* UNI = sb + 141312;
    float* X0 = (float*)UNI;
    U32* AH2 = (U32*)UNI;
    U32* AL2 = AH2 + 8192;

    int tid = threadIdx.x, lane = tid & 31, w = tid >> 5;
    int g = lane >> 2, tg = lane & 3;
    int og1 = (w & 3) * 4 + (lane & 3);
    int eg1 = (w >> 2) * 8 + (lane >> 2);
    int wm = w & 3, wn = w >> 2;

    for (int i = tid; i < 640; i += 512)
        ((float4*)sW0)[i] = ((const float4*)W0g)[i];
    // B1 = W1^T (W1 [64][128]) bf16 pairs, KH=32
    for (int i = tid; i < 1024; i += 512) {
        int n = i >> 3, kb = (i & 7) * 8;
        float xs[8];
#pragma unroll
        for (int j = 0; j < 8; j++) xs[j] = W1g[(kb + j) * 128 + n];
        uint4 hi, lo; bsplit8(xs, hi, lo);
        int p4 = ((kb >> 1) ^ ((n & 7) << 2));
        *(uint4*)&BH1[n * 32 + p4] = hi;
        *(uint4*)&BL1[n * 32 + p4] = lo;
    }
    // B2 = W2^T (W2 [128][128]) bf16 pairs, KH=64
    for (int i = tid; i < 2048; i += 512) {
        int n = i >> 4, kb = (i & 15) * 8;
        float xs[8];
#pragma unroll
        for (int j = 0; j < 8; j++) xs[j] = W2g[(kb + j) * 128 + n];
        uint4 hi, lo; bsplit8(xs, hi, lo);
        int p4 = ((kb >> 1) ^ ((n & 7) << 2));
        *(uint4*)&BH2[n * 64 + p4] = hi;
        *(uint4*)&BL2[n * 64 + p4] = lo;
    }
    __syncthreads();

    for (long t = blockIdx.x; t < ntiles; t += gridDim.x) {
        // stage X0 (single buffer, union region)
        for (int i = tid; i < 1280; i += 512) {
            int e_l = i / 10, ks = (i % 10) * 4;
            cpa16(X0 + e_l * 44 + ks, g_X0 + (t * 128 + e_l) * 40 + ks);
        }
        cp_commit(); cp_wait0();
        __syncthreads();

        // GEMM1: FFMA2, K=40 -> 64, silu -> H1 bf16 pairs (KH=32)
        {
            ULL acc[4][2];
#pragma unroll
            for (int j = 0; j < 4; j++) { acc[j][0] = 0ULL; acc[j][1] = 0ULL; }
            const float* xr[4];
#pragma unroll
            for (int j = 0; j < 4; j++) xr[j] = X0 + (eg1 + 32 * j) * 44;
#pragma unroll 2
            for (int k4 = 0; k4 < 40; k4 += 4) {
                float4 xv[4];
#pragma unroll
                for (int j = 0; j < 4; j++) xv[j] = *(const float4*)(xr[j] + k4);
#pragma unroll
                for (int kk = 0; kk < 4; kk++) {
                    const float* wr = sW0 + (k4 + kk) * 64 + og1 * 4;
                    ULL w0 = *(const ULL*)wr, w1 = *(const ULL*)(wr + 2);
#pragma unroll
                    for (int j = 0; j < 4; j++) {
                        float xs = (kk == 0) ? xv[j].x : (kk == 1) ? xv[j].y
                                 : (kk == 2) ? xv[j].z : xv[j].w;
                        ULL xd = pack2(xs);
                        acc[j][0] = fma2(xd, w0, acc[j][0]);
                        acc[j][1] = fma2(xd, w1, acc[j][1]);
                    }
                }
            }
            __syncthreads();   // all X0 reads done (GEMM2 epi will overwrite union)
#pragma unroll
            for (int j = 0; j < 4; j++) {
                int row = eg1 + 32 * j;
                union { ULL u; float2 f; } c0, c1;
                c0.u = acc[j][0]; c1.u = acc[j][1];
                float v0 = silu_f(c0.f.x * F_RS40), v1 = silu_f(c0.f.y * F_RS40);
                float v2 = silu_f(c1.f.x * F_RS40), v3 = silu_f(c1.f.y * F_RS40);
                U32 h0, l0, h1, l1;
                packpair(v0, v1, h0, l0);
                packpair(v2, v3, h1, l1);
                int p0 = (og1 * 2) ^ ((row & 7) << 2);
                AH1[row * 32 + p0] = h0;   AL1[row * 32 + p0] = l0;
                AH1[row * 32 + p0 + 1] = h1; AL1[row * 32 + p0 + 1] = l1;
            }
        }
        __syncthreads();

        // GEMM2: mma, K=64 (KH=32) -> 128, silu -> H2 bf16 pairs (KH=64, union)
        {
            float acc[2][4][4];
#pragma unroll
            for (int mt = 0; mt < 2; mt++)
#pragma unroll
                for (int nt = 0; nt < 4; nt++)
#pragma unroll
                    for (int q = 0; q < 4; q++) acc[mt][nt][q] = 0.0f;

#pragma unroll
            for (int ks = 0; ks < 4; ks++) {
                int pb = ks * 8;
                U32 ah[2][4], al[2][4];
#pragma unroll
                for (int mt = 0; mt < 2; mt++) {
                    int r0 = wm * 32 + mt * 16 + g;
                    ah[mt][0] = AH1[pidx(r0,     pb + tg,     32)];
                    ah[mt][1] = AH1[pidx(r0 + 8, pb + tg,     32)];
                    ah[mt][2] = AH1[pidx(r0,     pb + tg + 4, 32)];
                    ah[mt][3] = AH1[pidx(r0 + 8, pb + tg + 4, 32)];
                    al[mt][0] = AL1[pidx(r0,     pb + tg,     32)];
                    al[mt][1] = AL1[pidx(r0 + 8, pb + tg,     32)];
                    al[mt][2] = AL1[pidx(r0,     pb + tg + 4, 32)];
                    al[mt][3] = AL1[pidx(r0 + 8, pb + tg + 4, 32)];
                }
                U32 bh[4][2], bl[4][2];
#pragma unroll
                for (int nt = 0; nt < 4; nt++) {
                    int n = wn * 32 + nt * 8 + g;
                    bh[nt][0] = BH1[pidx(n, pb + tg,     32)];
                    bh[nt][1] = BH1[pidx(n, pb + tg + 4, 32)];
                    bl[nt][0] = BL1[pidx(n, pb + tg,     32)];
                    bl[nt][1] = BL1[pidx(n, pb + tg + 4, 32)];
                }
#pragma unroll
                for (int mt = 0; mt < 2; mt++)
#pragma unroll
                    for (int nt = 0; nt < 4; nt++) {
                        mma16816(acc[mt][nt], ah[mt], bh[nt]);
                        mma16816(acc[mt][nt], ah[mt], bl[nt]);
                        mma16816(acc[mt][nt], al[mt], bh[nt]);
                    }
            }

            // epilogue: silu + pack pairs into H2 (overwrites X0 region; safe)
#pragma unroll
            for (int mt = 0; mt < 2; mt++) {
                int r0 = wm * 32 + mt * 16 + g;
                int r8 = r0 + 8;
#pragma unroll
                for (int nt = 0; nt < 4; nt++) {
                    int pc = wn * 16 + nt * 4 + tg;
                    float s0 = silu_f(acc[mt][nt][0] * F_RS64);
                    float s1 = silu_f(acc[mt][nt][1] * F_RS64);
                    float s2 = silu_f(acc[mt][nt][2] * F_RS64);
                    float s3 = silu_f(acc[mt][nt][3] * F_RS64);
                    U32 h, l;
                    packpair(s0, s1, h, l);
                    AH2[r0 * 64 + (pc ^ ((r0 & 7) << 2))] = h;
                    AL2[r0 * 64 + (pc ^ ((r0 & 7) << 2))] = l;
                    packpair(s2, s3, h, l);
                    AH2[r8 * 64 + (pc ^ ((r8 & 7) << 2))] = h;
                    AL2[r8 * 64 + (pc ^ ((r8 & 7) << 2))] = l;
                }
            }
        }
        __syncthreads();

        // GEMM3: mma, K=128 (KH=64) -> 128, *fcut*rs128 -> g_lat
        {
            float acc[2][4][4];
#pragma unroll
            for (int mt = 0; mt < 2; mt++)
#pragma unroll
                for (int nt = 0; nt < 4; nt++)
#pragma unroll
                    for (int q = 0; q < 4; q++) acc[mt][nt][q] = 0.0f;

#pragma unroll 2
            for (int ks = 0; ks < 8; ks++) {
                int pb = ks * 8;
                U32 ah[2][4], al[2][4];
#pragma unroll
                for (int mt = 0; mt < 2; mt++) {
                    int r0 = wm * 32 + mt * 16 + g;
                    ah[mt][0] = AH2[pidx(r0,     pb + tg,     64)];
                    ah[mt][1] = AH2[pidx(r0 + 8, pb + tg,     64)];
                    ah[mt][2] = AH2[pidx(r0,     pb + tg + 4, 64)];
                    ah[mt][3] = AH2[pidx(r0 + 8, pb + tg + 4, 64)];
                    al[mt][0] = AL2[pidx(r0,     pb + tg,     64)];
                    al[mt][1] = AL2[pidx(r0 + 8, pb + tg,     64)];
                    al[mt][2] = AL2[pidx(r0,     pb + tg + 4, 64)];
                    al[mt][3] = AL2[pidx(r0 + 8, pb + tg + 4, 64)];
                }
                U32 bh[4][2], bl[4][2];
#pragma unroll
                for (int nt = 0; nt < 4; nt++) {
                    int n = wn * 32 + nt * 8 + g;
                    bh[nt][0] = BH2[pidx(n, pb + tg,     64)];
                    bh[nt][1] = BH2[pidx(n, pb + tg + 4, 64)];
                    bl[nt][0] = BL2[pidx(n, pb + tg,     64)];
                    bl[nt][1] = BL2[pidx(n, pb + tg + 4, 64)];
                }
#pragma unroll
                for (int mt = 0; mt < 2; mt++)
#pragma unroll
                    for (int nt = 0; nt < 4; nt++) {
                        mma16816(acc[mt][nt], ah[mt], bh[nt]);
                        mma16816(acc[mt][nt], ah[mt], bl[nt]);
                        mma16816(acc[mt][nt], al[mt], bh[nt]);
                    }
            }

#pragma unroll
            for (int mt = 0; mt < 2; mt++) {
                int r0 = wm * 32 + mt * 16 + g;
                long ea = t * 128 + r0, eb = ea + 8;
                float sa = F_RS128 * g_fcut[ea];
                float sb2 = F_RS128 * g_fcut[eb];
#pragma unroll
                for (int nt = 0; nt < 4; nt++) {
                    int col = wn * 32 + nt * 8 + tg * 2;
                    *(float2*)(g_lat + ea * 128 + col) =
                        make_float2(acc[mt][nt][0] * sa, acc[mt][nt][1] * sa);
                    *(float2*)(g_lat + eb * 128 + col) =
                        make_float2(acc[mt][nt][2] * sb2, acc[mt][nt][3] * sb2);
                }
            }
        }
        __syncthreads();
    }
}

// ---------------------------------------------------------------------------
// Streaming FFMA2 GEMM, 512 threads (G5)
// ---------------------------------------------------------------------------
template <int KTOT, int KC, int OUT, int OPO, class Op>
__global__ void __launch_bounds__(512, 1) gk(Op op, const float* __restrict__ Wg,
                                             int ntiles)
{
    constexpr int PC  = KC + 4;
    constexpr int NCH = KTOT / KC;
    constexpr int OG  = OUT / OPO;
    constexpr int OGW = OG / 4;
    constexpr int EGN = 512 / OG;
    constexpr int EPT = 128 / EGN;
    constexpr int NP  = OPO / 2;

    extern __shared__ __align__(16) float sh[];
    float* sW = sh;
    float* sX = sh + KTOT * OUT;

    int tid = threadIdx.x;
    for (int i = tid; i < KTOT * OUT / 4; i += 512)
        ((float4*)sW)[i] = ((const float4*)Wg)[i];

    int lane = tid & 31, w = tid >> 5;
    int og = (w & (OGW - 1)) * 4 + (lane & 3);
    int eg = (w / OGW) * 8 + (lane >> 2);

    auto stage = [&](long t, int c, int b) {
        float* dst = sX + b * (128 * PC);
        constexpr int UN = 128 * (KC / 4);
        for (int i = tid; i < UN; i += 512) {
            int e_l = i / (KC / 4);
            int ks  = (i % (KC / 4)) * 4;
            cpa16(dst + e_l * PC + ks, op.src(t * 128 + e_l, c * KC + ks));
        }
        cp_commit();
    };

    long t0 = blockIdx.x;
    if (t0 < ntiles) stage(t0, 0, 0);
    int b = 0;

    for (long t = t0; t < ntiles; t += gridDim.x) {
        ULL acc[EPT][NP];
#pragma unroll
        for (int j = 0; j < EPT; j++)
#pragma unroll
            for (int p = 0; p < NP; p++) acc[j][p] = 0ULL;

        for (int c = 0; c < NCH; c++) {
            long nt = t; int nc = c + 1;
            if (nc == NCH) { nt = t + gridDim.x; nc = 0; }
            bool hn = nt < ntiles;
            __syncthreads();
            if (hn) stage(nt, nc, b ^ 1);
            if (hn) { asm volatile("cp.async.wait_group 1;"); } else cp_wait0();
            __syncthreads();

            const float* Xb = sX + b * (128 * PC);
            const float* xr[EPT];
#pragma unroll
            for (int j = 0; j < EPT; j++) xr[j] = Xb + (eg + EGN * j) * PC;

#pragma unroll 2
            for (int k4 = 0; k4 < KC; k4 += 4) {
                float4 xv[EPT];
#pragma unroll
                for (int j = 0; j < EPT; j++)
                    xv[j] = *(const float4*)(xr[j] + k4);
#pragma unroll
                for (int kk = 0; kk < 4; kk++) {
                    const float* wr = sW + (c * KC + k4 + kk) * OUT + og * OPO;
                    ULL wv[NP];
#pragma unroll
                    for (int p = 0; p < NP; p++)
                        wv[p] = *(const ULL*)(wr + 2 * p);
#pragma unroll
                    for (int j = 0; j < EPT; j++) {
                        float xs = (kk == 0) ? xv[j].x : (kk == 1) ? xv[j].y
                                 : (kk == 2) ? xv[j].z : xv[j].w;
                        ULL xd = pack2(xs);
#pragma unroll
                        for (int p = 0; p < NP; p++)
                            acc[j][p] = fma2(xd, wv[p], acc[j][p]);
                    }
                }
            }
            b ^= 1;
        }

#pragma unroll
        for (int j = 0; j < EPT; j++) {
            long e = t * 128 + eg + EGN * j;
            float r[OPO];
#pragma unroll
            for (int p = 0; p < NP; p++) {
                union { ULL u; float2 f; } cv; cv.u = acc[j][p];
                r[2 * p] = cv.f.x; r[2 * p + 1] = cv.f.y;
            }
            op.epi(e, og, r);
        }
    }
}

// ---------------------------------------------------------------------------
// Epilogue / source policies.
// ---------------------------------------------------------------------------
struct OpG4T {
    const int* ctr;
    __device__ const float* src(long e, int k) const { return g_lat + e * 128 + k; }
    __device__ void epi2(long e, int col, float v0, float v1) const {
        if (col < 64) {
            *(float2*)(g_wedge + e * 64 + col) =
                make_float2(v0 * F_RS128, v1 * F_RS128);
        } else {
            long c = ctr[e];
            float4 Y = *(const float4*)(g_Y + e * 4);
            int m = (col - 64) >> 1;
            float w0 = v0 * F_RS128, w1 = v1 * F_RS128;
            red4(g_env + c * 128 + 4 * m, w0, w1 * Y.y, w1 * Y.z, w1 * Y.w);
        }
    }
};
struct OpG7T {
    __device__ const float* src(long e, int k) const {
        return (k < 128) ? (g_lat + e * 128 + k) : (g_scal0 + e * 64 + (k - 128));
    }
    __device__ void epi2(long e, int col, float v0, float v1) const {
        *(float2*)(g_H + e * 128 + col) =
            make_float2(silu_f(v0 * F_RS192), silu_f(v1 * F_RS192));
    }
};
struct OpG8T {
    __device__ const float* src(long e, int k) const { return g_H + e * 128 + k; }
    __device__ void epi2(long e, int col, float v0, float v1) const {
        float s = F_C_NEW * F_RS128 * g_fcut[e];
        float2 l = *(float2*)(g_lat + e * 128 + col);
        *(float2*)(g_lat + e * 128 + col) =
            make_float2(F_C_OLD * l.x + s * v0, F_C_OLD * l.y + s * v1);
    }
};
struct OpG9T {  // lat -> w_env1(64) -> env1 scatter (pair epilogue)
    const int* ctr;
    __device__ const float* src(long e, int k) const { return g_lat + e * 128 + k; }
    __device__ void epi2(long e, int col, float v0, float v1) const {
        long c = ctr[e];
        float4 Y = *(const float4*)(g_Y + e * 4);
        int m = col >> 1;
        float w0 = v0 * F_RS128, w1 = v1 * F_RS128;
        red4(g_env1 + c * 128 + 4 * m, w0, w1 * Y.y, w1 * Y.z, w1 * Y.w);
    }
};
struct OpG10T {
    __device__ const float* src(long e, int k) const {
        return (k < 128) ? (g_lat + e * 128 + k) : (g_q + e * 64 + (k - 128));
    }
    __device__ void epi2(long e, int col, float v0, float v1) const {
        *(float2*)(g_H + e * 128 + col) =
            make_float2(silu_f(v0 * F_RS192), silu_f(v1 * F_RS192));
    }
};
struct OpG11T {
    const int* ctr;
    float* out;
    __device__ const float* src(long e, int k) const { return g_H + e * 128 + k; }
    __device__ void epi2(long e, int col, float v0, float v1) const {
        long c = ctr[e];
        float s = F_C_NEW * F_RS128 * g_fcut[e];
        float2 l = *(const float2*)(g_lat + e * 128 + col);
        red2(out + c * 128 + col,
             (F_C_OLD * l.x + s * v0) * F_ISN,
             (F_C_OLD * l.y + s * v1) * F_ISN);
    }
};
struct OpG5 {
    __device__ const float* src(long e, int k) const { return g_scal0 + e * 64 + k; }
    __device__ void epi(long e, int og, const float* r) const {
        *(float4*)(g_smix + e * 32 + og * 4) =
            make_float4(r[0] * F_RS64, r[1] * F_RS64, r[2] * F_RS64, r[3] * F_RS64);
    }
};

// ---------------------------------------------------------------------------
__global__ void k_zero(float* __restrict__ out)
{
    int i = blockIdx.x * blockDim.x + threadIdx.x;
    int stride = gridDim.x * blockDim.x;
    for (; i < NN * 128; i += stride) {
        g_env[i]  = 0.0f;
        g_env1[i] = 0.0f;
        out[i]    = 0.0f;
    }
}

__global__ void __launch_bounds__(512) kgeo(
    const float* __restrict__ coords, const float* __restrict__ attrs,
    const int* __restrict__ eidx)
{
    int e = blockIdx.x * 512 + threadIdx.x;
    if (e >= NE) return;
    int snd = eidx[e];
    int c   = eidx[NE + e];
    float dx = coords[c * 3 + 0] - coords[snd * 3 + 0];
    float dy = coords[c * 3 + 1] - coords[snd * 3 + 1];
    float dz = coords[c * 3 + 2] - coords[snd * 3 + 2];
    float r2 = dx * dx + dy * dy + dz * dz + 1e-12f;
    float r  = sqrtf(r2);
    float inv_r = 1.0f / r;
    float u  = r * F_INV_RMAX;
    float u2 = u * u, u3 = u2 * u, u6 = u3 * u3, u7 = u6 * u, u8 = u7 * u;
    float f  = 1.0f - 28.0f * u6 + 48.0f * u7 - 21.0f * u8;
    if (u >= 1.0f) f = 0.0f;
    g_fcut[e] = f;
    *(float4*)(g_Y + e * 4) = make_float4(1.0f, F_SQRT3 * dx * inv_r,
                                          F_SQRT3 * dy * inv_r, F_SQRT3 * dz * inv_r);
    float* X = g_X0 + (long)e * 40;
    const float4* ac = (const float4*)(attrs + c * 16);
    const float4* as = (const float4*)(attrs + snd * 16);
#pragma unroll
    for (int i = 0; i < 4; i++) ((float4*)X)[i] = ac[i];
#pragma unroll
    for (int i = 0; i < 4; i++) ((float4*)(X + 16))[i] = as[i];
    float bi = inv_r * f * F_BESSEL;
#pragma unroll
    for (int n = 0; n < 8; n++)
        X[32 + n] = bi * sinf((n + 1) * F_PI * u);
}

__global__ void __launch_bounds__(256) kp2(const int* __restrict__ eidx)
{
    int warp = (blockIdx.x * 256 + threadIdx.x) >> 5;
    int lane = threadIdx.x & 31;
    int nw = gridDim.x * 8;
    for (long e = warp; e < NE; e += nw) {
        long c = eidx[NE + e];
        float4 e1 = *(const float4*)(g_env1 + c * 128 + 4 * lane);
        float sm = g_smix[e * 32 + lane];
        float v0 = g_vmx[(3 * e + 0) * 32 + lane];
        float v1 = g_vmx[(3 * e + 1) * 32 + lane];
        float v2 = g_vmx[(3 * e + 2) * 32 + lane];
        g_q[e * 64 + lane] = sm * e1.x * F_ISN;
        g_q[e * 64 + 32 + lane] =
            (v0 * e1.y + v1 * e1.z + v2 * e1.w) * F_ISN * F_INV_SQRT3;
    }
}

// ---------------------------------------------------------------------------
extern "C" void kernel_launch(void* const* d_in, const int* in_sizes, int n_in,
                              void* d_out, int out_size)
{
    const float* coords = (const float*)d_in[0];
    const float* attrs  = (const float*)d_in[1];
    const int*   eidx   = (const int*)  d_in[2];
    const float* W2b0   = (const float*)d_in[3];
    const float* W2b1   = (const float*)d_in[4];
    const float* W2b2   = (const float*)d_in[5];
    const float* Wenv0  = (const float*)d_in[6];
    const float* Wlat0  = (const float*)d_in[7];
    const float* Wlat1  = (const float*)d_in[8];
    const float* Ws0    = (const float*)d_in[9];
    const float* Wv0    = (const float*)d_in[10];
    const float* Wenv1  = (const float*)d_in[11];
    const float* Wfin0  = (const float*)d_in[12];
    const float* Wfin1  = (const float*)d_in[13];
    float* out = (float*)d_out;
    const int* ctr = eidx + NE;

    const size_t sm_kt123 = 206848;
    const size_t sm64_32  = (2048 + 2 * 128 * 68) * 4;
    const size_t sm_t2    = (size_t)(2 * 64 * 64 + 2 * 128 * 64) * 4;   //  98304
    const size_t sm_t2g9  = (size_t)(2 * 128 * 64 + 2 * 64 * 64) * 4;   //  98304
    const size_t sm_t192  = (size_t)4 * 128 * 96 * 4;                   // 196608
    const size_t sm_kpv   = (size_t)(2 * 384 * KPV_PITCH + 2 * 32 * KPV_PITCH) * 4;

    cudaFuncSetAttribute(kt123, cudaFuncAttributeMaxDynamicSharedMemorySize, (int)sm_kt123);
    cudaFuncSetAttribute(tkm2<128, 128, 2, OpG4T>,  cudaFuncAttributeMaxDynamicSharedMemorySize, (int)sm_t2);
    cudaFuncSetAttribute(kpv,                       cudaFuncAttributeMaxDynamicSharedMemorySize, (int)sm_kpv);
    cudaFuncSetAttribute(tkm<192, OpG7T>,           cudaFuncAttributeMaxDynamicSharedMemorySize, (int)sm_t192);
    cudaFuncSetAttribute(tkm2<128, 128, 2, OpG8T>,  cudaFuncAttributeMaxDynamicSharedMemorySize, (int)sm_t2);
    cudaFuncSetAttribute(tkm2<128, 64, 4, OpG9T>,   cudaFuncAttributeMaxDynamicSharedMemorySize, (int)sm_t2g9);
    cudaFuncSetAttribute(tkm<192, OpG10T>,          cudaFuncAttributeMaxDynamicSharedMemorySize, (int)sm_t192);
    cudaFuncSetAttribute(tkm2<128, 128, 2, OpG11T>, cudaFuncAttributeMaxDynamicSharedMemorySize, (int)sm_t2);
    cudaFuncSetAttribute(gk<64, 64, 32, 4, OpG5>,   cudaFuncAttributeMaxDynamicSharedMemorySize, (int)sm64_32);

    const int NT    = NE / 128;   // 2500
    const int NT64  = NE / 64;    // 5000

    k_zero<<<512, 256>>>(out);
    kgeo<<<(NE + 511) / 512, 512>>>(coords, attrs, eidx);

    kt123<<<148, 512, sm_kt123>>>(W2b0, W2b1, W2b2, NT);
    tkm2<128, 128, 2, OpG4T><<<296, 256, sm_t2>>>(OpG4T{ctr}, Wenv0, NT64);
    kpv<<<148, 512, sm_kpv>>>(ctr, Wv0, NT);
    gk<64, 64, 32, 4, OpG5><<<148, 512, sm64_32>>>(OpG5{}, Ws0, NT);
    tkm<192, OpG7T><<<148, 512, sm_t192>>>(OpG7T{}, Wlat0, NT);
    tkm2<128, 128, 2, OpG8T><<<296, 256, sm_t2>>>(OpG8T{}, Wlat1, NT64);
    tkm2<128, 64, 4, OpG9T><<<296, 256, sm_t2g9>>>(OpG9T{ctr}, Wenv1, NT);
    kp2<<<2560, 256>>>(eidx);
    tkm<192, OpG10T><<<148, 512, sm_t192>>>(OpG10T{}, Wfin0, NT);
    tkm2<128, 128, 2, OpG11T><<<296, 256, sm_t2>>>(OpG11T{ctr, out}, Wfin1, NT64);
}